// round 1
// baseline (speedup 1.0000x reference)
#include <cuda_runtime.h>
#include <cuda_bf16.h>
#include <math.h>

#define BB 2
#define SS 2048
#define DD 1024
#define HH 16
#define HKV 4
#define HDIM 64
#define SDIM 16

// ---------------- scratch (device globals; no allocation) ----------------
__device__ float g_qlin[BB*SS*DD];
__device__ float g_klin[BB*SS*HKV*HDIM];
__device__ float g_vlin[BB*SS*HKV*HDIM];
__device__ float g_q   [BB*HH*SS*HDIM];
__device__ float g_qsp [BB*HH*SS*SDIM];
__device__ float g_k   [BB*HKV*SS*HDIM];
__device__ float g_ksp [BB*HKV*SS*SDIM];
__device__ float g_v   [BB*HKV*SS*HDIM];
__device__ float g_att [BB*SS*DD];
__device__ float g_cosT[SS*(HDIM/2)];
__device__ float g_sinT[SS*(HDIM/2)];

// ---------------- RoPE table (fp64 for accuracy, tiny cost) ----------------
__global__ void init_rope_kernel() {
    int idx = blockIdx.x*blockDim.x + threadIdx.x;
    if (idx >= SS*(HDIM/2)) return;
    int s = idx / (HDIM/2), i = idx % (HDIM/2);
    // theta_i = 10000^{-(2i)/HDIM}; compute fp32 theta like the reference, then
    // the angle s*theta in fp32, then accurate trig on that value.
    float thf = (float)pow(10000.0, -(double)i / (double)(HDIM/2));
    float ff  = (float)s * thf;
    g_cosT[idx] = (float)cos((double)ff);
    g_sinT[idx] = (float)sin((double)ff);
}

// ---------------- generic C[M,N] = A[M,K] @ W[N,K]^T (+bias) ----------------
#define GBM 64
#define GBN 64
#define GBK 16
__global__ void __launch_bounds__(256) gemm_nt_bias(
    const float* __restrict__ A, const float* __restrict__ W,
    const float* __restrict__ bias, float* __restrict__ C,
    int M, int N, int K)
{
    __shared__ float As[GBM][GBK+1];
    __shared__ float Bs[GBN][GBK+1];
    const int tx = threadIdx.x & 15, ty = threadIdx.x >> 4;
    const int row0 = blockIdx.y * GBM, col0 = blockIdx.x * GBN;
    float acc[4][4] = {};
    for (int k0 = 0; k0 < K; k0 += GBK) {
        #pragma unroll
        for (int t = 0; t < 4; t++) {
            int e = threadIdx.x + t*256;
            int r = e / GBK, c = e % GBK;
            As[r][c] = A[(size_t)(row0 + r)*K + k0 + c];
            Bs[r][c] = W[(size_t)(col0 + r)*K + k0 + c];
        }
        __syncthreads();
        #pragma unroll
        for (int kk = 0; kk < GBK; kk++) {
            float a[4], b[4];
            #pragma unroll
            for (int i = 0; i < 4; i++) a[i] = As[ty*4+i][kk];
            #pragma unroll
            for (int j = 0; j < 4; j++) b[j] = Bs[tx*4+j][kk];
            #pragma unroll
            for (int i = 0; i < 4; i++)
                #pragma unroll
                for (int j = 0; j < 4; j++)
                    acc[i][j] += a[i]*b[j];
        }
        __syncthreads();
    }
    #pragma unroll
    for (int i = 0; i < 4; i++) {
        int r = row0 + ty*4 + i;
        #pragma unroll
        for (int j = 0; j < 4; j++) {
            int c = col0 + tx*4 + j;
            float bv = bias ? bias[c] : 0.f;
            C[(size_t)r*N + c] = acc[i][j] + bv;
        }
    }
}

// ---------------- RoPE + low-rank sparsity projection + relayout ----------------
// lin: [B,S,NH*64] -> obuf [B,NH,S,64] (roped), spbuf [B,NH,S,16]
// optionally vlin -> vbuf [B,NH,S,64]
__global__ void rope_sp_kernel(const float* __restrict__ lin,
                               const float* __restrict__ vlin,
                               const float* __restrict__ Ws,
                               const float* __restrict__ bs,
                               float* __restrict__ obuf,
                               float* __restrict__ spbuf,
                               float* __restrict__ vbuf,
                               int NH)
{
    __shared__ float WsS[SDIM*HDIM];
    __shared__ float bsS[SDIM];
    for (int i = threadIdx.x; i < SDIM*HDIM; i += blockDim.x) WsS[i] = Ws[i];
    if (threadIdx.x < SDIM) bsS[threadIdx.x] = bs[threadIdx.x];
    __syncthreads();

    int idx = blockIdx.x*blockDim.x + threadIdx.x;
    int total = BB*SS*NH;
    if (idx >= total) return;
    int h = idx % NH;
    int s = (idx / NH) % SS;
    int b = idx / (NH*SS);

    const float* src = lin + ((size_t)(b*SS + s)*NH + h)*HDIM;
    float v[HDIM];
    #pragma unroll
    for (int d = 0; d < HDIM; d++) v[d] = src[d];

    #pragma unroll
    for (int i = 0; i < HDIM/2; i++) {
        float c  = g_cosT[s*(HDIM/2)+i];
        float sn = g_sinT[s*(HDIM/2)+i];
        float a  = v[i], bpart = v[i+HDIM/2];
        v[i]        = a*c - bpart*sn;
        v[i+HDIM/2] = bpart*c + a*sn;
    }

    float* dst = obuf + (((size_t)b*NH + h)*SS + s)*HDIM;
    #pragma unroll
    for (int d = 0; d < HDIM; d++) dst[d] = v[d];

    float* spd = spbuf + (((size_t)b*NH + h)*SS + s)*SDIM;
    for (int j = 0; j < SDIM; j++) {
        float acc = bsS[j];
        #pragma unroll
        for (int d = 0; d < HDIM; d++) acc += WsS[j*HDIM + d] * v[d];
        spd[j] = acc;
    }

    if (vlin) {
        const float* vsrc = vlin + ((size_t)(b*SS + s)*NH + h)*HDIM;
        float* vdst = vbuf + (((size_t)b*NH + h)*SS + s)*HDIM;
        #pragma unroll
        for (int d = 0; d < HDIM; d++) vdst[d] = vsrc[d];
    }
}

// ---------------- gated causal flash attention ----------------
// One warp per query row; 8 rows per block; K tiles of 64 keys.
__global__ void __launch_bounds__(256) attn_kernel()
{
    __shared__ float ks  [HDIM][64+1];   // transposed: [d][key]
    __shared__ float vs  [64][HDIM];     // natural:    [key][d]
    __shared__ float ksps[64][SDIM+1];   // [key][j]
    __shared__ float qs  [8][HDIM];
    __shared__ float qsps[8][SDIM];

    const int b  = blockIdx.z, h = blockIdx.y;
    const int hkv = h / (HH/HKV);
    const int q0 = blockIdx.x * 8;
    const int warp = threadIdx.x >> 5, lane = threadIdx.x & 31;
    const int qrow = q0 + warp;

    const float* qptr = g_q   + (((size_t)b*HH  + h  )*SS)*HDIM;
    const float* qspp = g_qsp + (((size_t)b*HH  + h  )*SS)*SDIM;
    const float* kptr = g_k   + (((size_t)b*HKV + hkv)*SS)*HDIM;
    const float* kspp = g_ksp + (((size_t)b*HKV + hkv)*SS)*SDIM;
    const float* vptr = g_v   + (((size_t)b*HKV + hkv)*SS)*HDIM;

    for (int i = threadIdx.x; i < 8*HDIM; i += 256) {
        int r = i >> 6, d = i & 63;
        qs[r][d] = qptr[(size_t)(q0+r)*HDIM + d];
    }
    for (int i = threadIdx.x; i < 8*SDIM; i += 256) {
        int r = i >> 4, j = i & 15;
        qsps[r][j] = qspp[(size_t)(q0+r)*SDIM + j];
    }
    __syncthreads();

    // hoist this warp's query into registers (halves LDS traffic in the dot)
    float qreg[HDIM];
    #pragma unroll
    for (int d = 0; d < HDIM; d++) qreg[d] = qs[warp][d];
    float qspr[SDIM];
    #pragma unroll
    for (int j = 0; j < SDIM; j++) qspr[j] = qsps[warp][j];

    float m = -INFINITY, l = 0.f, o0 = 0.f, o1 = 0.f;
    const int kend = q0 + 8;   // last key needed (exclusive) in this block

    for (int kb = 0; kb < kend; kb += 64) {
        __syncthreads();
        for (int i = threadIdx.x; i < 64*HDIM; i += 256) {
            int key = i >> 6, d = i & 63;
            ks[d][key] = kptr[(size_t)(kb+key)*HDIM + d];
            vs[key][d] = vptr[(size_t)(kb+key)*HDIM + d];
        }
        for (int i = threadIdx.x; i < 64*SDIM; i += 256) {
            int key = i >> 4, j = i & 15;
            ksps[key][j] = kspp[(size_t)(kb+key)*SDIM + j];
        }
        __syncthreads();
        if (kb > qrow) continue;   // whole tile masked for this warp

        #pragma unroll
        for (int sub = 0; sub < 2; sub++) {
            const int kcol = sub*32 + lane;
            const int key  = kb + kcol;

            float sdot = 0.f;
            #pragma unroll
            for (int d = 0; d < HDIM; d++) sdot += qreg[d] * ks[d][kcol];
            float spdot = 0.f;
            #pragma unroll
            for (int j = 0; j < SDIM; j++) spdot += qspr[j] * ksps[kcol][j];

            float gate  = 1.f / (1.f + expf(-spdot * 0.25f));   // sigmoid(sp/sqrt(SD))
            float logit = (key <= qrow) ? sdot * 0.125f * gate : -INFINITY;

            float mx = logit;
            #pragma unroll
            for (int off = 16; off; off >>= 1)
                mx = fmaxf(mx, __shfl_xor_sync(0xffffffffu, mx, off));
            if (mx == -INFINITY) continue;   // this 32-key chunk fully masked

            float m_new = fmaxf(m, mx);
            float scale = expf(m - m_new);          // 0 on first chunk (m=-inf)
            float p = expf(logit - m_new);          // 0 for masked lanes
            float ps = p;
            #pragma unroll
            for (int off = 16; off; off >>= 1)
                ps += __shfl_xor_sync(0xffffffffu, ps, off);

            l = l*scale + ps;
            o0 *= scale; o1 *= scale;
            m = m_new;

            #pragma unroll
            for (int kk = 0; kk < 32; kk++) {
                float pk = __shfl_sync(0xffffffffu, p, kk);
                int kr = sub*32 + kk;
                o0 += pk * vs[kr][lane];
                o1 += pk * vs[kr][lane+32];
            }
        }
    }

    float inv = 1.f / l;
    float* op = g_att + ((size_t)b*SS + qrow)*DD + h*HDIM;
    op[lane]      = o0*inv;
    op[lane+32]   = o1*inv;
}

// ---------------- launch ----------------
extern "C" void kernel_launch(void* const* d_in, const int* in_sizes, int n_in,
                              void* d_out, int out_size)
{
    (void)in_sizes; (void)n_in; (void)out_size;
    const float* x  = (const float*)d_in[0];
    const float* Wq = (const float*)d_in[1];
    const float* Wk = (const float*)d_in[2];
    const float* Wv = (const float*)d_in[3];
    const float* Wo = (const float*)d_in[4];
    const float* bo = (const float*)d_in[5];
    const float* Ws = (const float*)d_in[6];
    const float* bs = (const float*)d_in[7];
    float* out = (float*)d_out;

    float *qlin, *klin, *vlin, *q, *qsp, *k, *ksp, *v, *att;
    cudaGetSymbolAddress((void**)&qlin, g_qlin);
    cudaGetSymbolAddress((void**)&klin, g_klin);
    cudaGetSymbolAddress((void**)&vlin, g_vlin);
    cudaGetSymbolAddress((void**)&q,    g_q);
    cudaGetSymbolAddress((void**)&qsp,  g_qsp);
    cudaGetSymbolAddress((void**)&k,    g_k);
    cudaGetSymbolAddress((void**)&ksp,  g_ksp);
    cudaGetSymbolAddress((void**)&v,    g_v);
    cudaGetSymbolAddress((void**)&att,  g_att);

    const int M = BB*SS;   // 4096

    init_rope_kernel<<<(SS*(HDIM/2) + 255)/256, 256>>>();

    gemm_nt_bias<<<dim3(DD/GBN,        M/GBM), 256>>>(x, Wq, nullptr, qlin, M, DD,        DD);
    gemm_nt_bias<<<dim3((HKV*HDIM)/GBN, M/GBM), 256>>>(x, Wk, nullptr, klin, M, HKV*HDIM, DD);
    gemm_nt_bias<<<dim3((HKV*HDIM)/GBN, M/GBM), 256>>>(x, Wv, nullptr, vlin, M, HKV*HDIM, DD);

    rope_sp_kernel<<<(BB*SS*HH  + 255)/256, 256>>>(qlin, nullptr, Ws, bs, q, qsp, nullptr, HH);
    rope_sp_kernel<<<(BB*SS*HKV + 255)/256, 256>>>(klin, vlin,    Ws, bs, k, ksp, v,       HKV);

    attn_kernel<<<dim3(SS/8, HH, BB), 256>>>();

    gemm_nt_bias<<<dim3(DD/GBN, M/GBM), 256>>>(att, Wo, bo, out, M, DD, DD);
}

// round 2
// speedup vs baseline: 2.2924x; 2.2924x over previous
#include <cuda_runtime.h>
#include <cuda_bf16.h>
#include <math.h>

#define BB 2
#define SS 2048
#define DD 1024
#define HH 16
#define HKV 4
#define HDIM 64
#define SDIM 16

// ---------------- scratch (device globals; no allocation) ----------------
__device__ float g_qlin[BB*SS*DD];
__device__ float g_klin[BB*SS*HKV*HDIM];
__device__ float g_vlin[BB*SS*HKV*HDIM];
__device__ float g_q   [BB*HH*SS*HDIM];
__device__ float g_qsp [BB*HH*SS*SDIM];
__device__ float g_k   [BB*HKV*SS*HDIM];
__device__ float g_ksp [BB*HKV*SS*SDIM];
__device__ float g_v   [BB*HKV*SS*HDIM];
__device__ float g_att [BB*SS*DD];
__device__ float g_cosT[SS*(HDIM/2)];
__device__ float g_sinT[SS*(HDIM/2)];

// ---------------- RoPE table (fp64 for accuracy, tiny cost) ----------------
__global__ void init_rope_kernel() {
    int idx = blockIdx.x*blockDim.x + threadIdx.x;
    if (idx >= SS*(HDIM/2)) return;
    int s = idx / (HDIM/2), i = idx % (HDIM/2);
    float thf = (float)pow(10000.0, -(double)i / (double)(HDIM/2));
    float ff  = (float)s * thf;
    g_cosT[idx] = (float)cos((double)ff);
    g_sinT[idx] = (float)sin((double)ff);
}

// ---------------- generic C[M,N] = A[M,K] @ W[N,K]^T (+bias) ----------------
#define GBM 64
#define GBN 64
#define GBK 16
__global__ void __launch_bounds__(256) gemm_nt_bias(
    const float* __restrict__ A, const float* __restrict__ W,
    const float* __restrict__ bias, float* __restrict__ C,
    int M, int N, int K)
{
    __shared__ float As[GBM][GBK+1];
    __shared__ float Bs[GBN][GBK+1];
    const int tx = threadIdx.x & 15, ty = threadIdx.x >> 4;
    const int row0 = blockIdx.y * GBM, col0 = blockIdx.x * GBN;
    float acc[4][4] = {};
    for (int k0 = 0; k0 < K; k0 += GBK) {
        #pragma unroll
        for (int t = 0; t < 4; t++) {
            int e = threadIdx.x + t*256;
            int r = e / GBK, c = e % GBK;
            As[r][c] = A[(size_t)(row0 + r)*K + k0 + c];
            Bs[r][c] = W[(size_t)(col0 + r)*K + k0 + c];
        }
        __syncthreads();
        #pragma unroll
        for (int kk = 0; kk < GBK; kk++) {
            float a[4], b[4];
            #pragma unroll
            for (int i = 0; i < 4; i++) a[i] = As[ty*4+i][kk];
            #pragma unroll
            for (int j = 0; j < 4; j++) b[j] = Bs[tx*4+j][kk];
            #pragma unroll
            for (int i = 0; i < 4; i++)
                #pragma unroll
                for (int j = 0; j < 4; j++)
                    acc[i][j] += a[i]*b[j];
        }
        __syncthreads();
    }
    #pragma unroll
    for (int i = 0; i < 4; i++) {
        int r = row0 + ty*4 + i;
        #pragma unroll
        for (int j = 0; j < 4; j++) {
            int c = col0 + tx*4 + j;
            float bv = bias ? bias[c] : 0.f;
            C[(size_t)r*N + c] = acc[i][j] + bv;
        }
    }
}

// ---------------- RoPE + low-rank sparsity projection + relayout ----------------
__global__ void rope_sp_kernel(const float* __restrict__ lin,
                               const float* __restrict__ vlin,
                               const float* __restrict__ Ws,
                               const float* __restrict__ bs,
                               float* __restrict__ obuf,
                               float* __restrict__ spbuf,
                               float* __restrict__ vbuf,
                               int NH)
{
    __shared__ float WsS[SDIM*HDIM];
    __shared__ float bsS[SDIM];
    for (int i = threadIdx.x; i < SDIM*HDIM; i += blockDim.x) WsS[i] = Ws[i];
    if (threadIdx.x < SDIM) bsS[threadIdx.x] = bs[threadIdx.x];
    __syncthreads();

    int idx = blockIdx.x*blockDim.x + threadIdx.x;
    int total = BB*SS*NH;
    if (idx >= total) return;
    int h = idx % NH;
    int s = (idx / NH) % SS;
    int b = idx / (NH*SS);

    const float* src = lin + ((size_t)(b*SS + s)*NH + h)*HDIM;
    float v[HDIM];
    #pragma unroll
    for (int d = 0; d < HDIM; d++) v[d] = src[d];

    #pragma unroll
    for (int i = 0; i < HDIM/2; i++) {
        float c  = g_cosT[s*(HDIM/2)+i];
        float sn = g_sinT[s*(HDIM/2)+i];
        float a  = v[i], bpart = v[i+HDIM/2];
        v[i]        = a*c - bpart*sn;
        v[i+HDIM/2] = bpart*c + a*sn;
    }

    float* dst = obuf + (((size_t)b*NH + h)*SS + s)*HDIM;
    #pragma unroll
    for (int d = 0; d < HDIM; d++) dst[d] = v[d];

    float* spd = spbuf + (((size_t)b*NH + h)*SS + s)*SDIM;
    for (int j = 0; j < SDIM; j++) {
        float acc = bsS[j];
        #pragma unroll
        for (int d = 0; d < HDIM; d++) acc += WsS[j*HDIM + d] * v[d];
        spd[j] = acc;
    }

    if (vlin) {
        const float* vsrc = vlin + ((size_t)(b*SS + s)*NH + h)*HDIM;
        float* vdst = vbuf + (((size_t)b*NH + h)*SS + s)*HDIM;
        #pragma unroll
        for (int d = 0; d < HDIM; d++) vdst[d] = vsrc[d];
    }
}

// ---------------- gated causal flash attention, 64x64 register-tiled ----------------
#define QT 64
#define KT 64

struct AttnSMem {
    float Qs  [QT][HDIM+4];   // natural [query][dim]
    float Kt  [KT*HDIM];      // transposed [dim][key], XOR-swizzled in 4-float groups
    float Vs  [KT][HDIM+4];   // natural [key][dim]
    float Ps  [QT][KT+4];     // probabilities [query][key]
    float Qsps[QT][SDIM+4];   // natural [query][sdim]
    float Kspt[SDIM][KT+4];   // transposed [sdim][key]
};

__global__ void __launch_bounds__(256, 2) attn_kernel64()
{
    extern __shared__ char smraw[];
    AttnSMem& sm = *reinterpret_cast<AttnSMem*>(smraw);

    const int b = blockIdx.z, h = blockIdx.y;
    const int hkv = h >> 2;                 // H/HKV = 4
    const int q0 = blockIdx.x * QT;
    const int tid = threadIdx.x;
    const int tx = tid & 15, ty = tid >> 4;

    const float* qptr = g_q   + (((size_t)b*HH  + h  )*SS + q0)*HDIM;
    const float* qspp = g_qsp + (((size_t)b*HH  + h  )*SS + q0)*SDIM;
    const float* kptr = g_k   + (((size_t)b*HKV + hkv)*SS)*HDIM;
    const float* kspp = g_ksp + (((size_t)b*HKV + hkv)*SS)*SDIM;
    const float* vptr = g_v   + (((size_t)b*HKV + hkv)*SS)*HDIM;

    // load Q tile (natural, coalesced, conflict-free)
    #pragma unroll
    for (int t = 0; t < 16; t++) {
        int i = tid + t*256;
        sm.Qs[i >> 6][i & 63] = qptr[i];
    }
    #pragma unroll
    for (int t = 0; t < 4; t++) {
        int i = tid + t*256;
        sm.Qsps[i >> 4][i & 15] = qspp[i];
    }

    float m[4], l[4], o[4][4];
    #pragma unroll
    for (int i = 0; i < 4; i++) {
        m[i] = -1e30f; l[i] = 0.f;
        #pragma unroll
        for (int j = 0; j < 4; j++) o[i][j] = 0.f;
    }

    for (int kb = 0; kb <= q0; kb += KT) {
        __syncthreads();   // previous PV reads done
        // K transposed + swizzled; V natural; Ksp transposed
        #pragma unroll
        for (int t = 0; t < 16; t++) {
            int i = tid + t*256;
            int r = i >> 6, d = i & 63;    // r = key, d = dim
            float kv = kptr[(size_t)kb*HDIM + i];
            sm.Kt[d*64 + ((((r >> 2) ^ (d & 15)) << 2) | (r & 3))] = kv;
            sm.Vs[r][d] = vptr[(size_t)kb*HDIM + i];
        }
        #pragma unroll
        for (int t = 0; t < 4; t++) {
            int i = tid + t*256;
            int r = i >> 4, j = i & 15;
            sm.Kspt[j][r] = kspp[(size_t)kb*SDIM + i];
        }
        __syncthreads();

        // --- S = Q K^T (64-dim inner), SP = Qsp Ksp^T (16-dim inner) ---
        float s[4][4] = {}, sp[4][4] = {};
        #pragma unroll
        for (int kk = 0; kk < HDIM; kk += 4) {
            float4 b0 = *(const float4*)&sm.Kt[(kk+0)*64 + ((tx ^ ((kk+0) & 15)) << 2)];
            float4 b1 = *(const float4*)&sm.Kt[(kk+1)*64 + ((tx ^ ((kk+1) & 15)) << 2)];
            float4 b2 = *(const float4*)&sm.Kt[(kk+2)*64 + ((tx ^ ((kk+2) & 15)) << 2)];
            float4 b3 = *(const float4*)&sm.Kt[(kk+3)*64 + ((tx ^ ((kk+3) & 15)) << 2)];
            #pragma unroll
            for (int i = 0; i < 4; i++) {
                float4 a = *(const float4*)&sm.Qs[ty*4+i][kk];
                s[i][0] += a.x*b0.x + a.y*b1.x + a.z*b2.x + a.w*b3.x;
                s[i][1] += a.x*b0.y + a.y*b1.y + a.z*b2.y + a.w*b3.y;
                s[i][2] += a.x*b0.z + a.y*b1.z + a.z*b2.z + a.w*b3.z;
                s[i][3] += a.x*b0.w + a.y*b1.w + a.z*b2.w + a.w*b3.w;
            }
        }
        #pragma unroll
        for (int kk = 0; kk < SDIM; kk += 4) {
            float4 b0 = *(const float4*)&sm.Kspt[kk+0][tx*4];
            float4 b1 = *(const float4*)&sm.Kspt[kk+1][tx*4];
            float4 b2 = *(const float4*)&sm.Kspt[kk+2][tx*4];
            float4 b3 = *(const float4*)&sm.Kspt[kk+3][tx*4];
            #pragma unroll
            for (int i = 0; i < 4; i++) {
                float4 a = *(const float4*)&sm.Qsps[ty*4+i][kk];
                sp[i][0] += a.x*b0.x + a.y*b1.x + a.z*b2.x + a.w*b3.x;
                sp[i][1] += a.x*b0.y + a.y*b1.y + a.z*b2.y + a.w*b3.y;
                sp[i][2] += a.x*b0.z + a.y*b1.z + a.z*b2.z + a.w*b3.z;
                sp[i][3] += a.x*b0.w + a.y*b1.w + a.z*b2.w + a.w*b3.w;
            }
        }

        // --- gate, mask, online softmax ---
        const bool diag = (kb == q0);
        #pragma unroll
        for (int i = 0; i < 4; i++) {
            #pragma unroll
            for (int j = 0; j < 4; j++) {
                float g = 1.f / (1.f + expf(-sp[i][j] * 0.25f));  // sigmoid(sp/sqrt(SD))
                float logit = s[i][j] * 0.125f * g;               // s/sqrt(HD) * gate
                if (diag && (tx*4+j > ty*4+i)) logit = -1e30f;
                s[i][j] = logit;
            }
        }
        #pragma unroll
        for (int i = 0; i < 4; i++) {
            float mx = fmaxf(fmaxf(s[i][0], s[i][1]), fmaxf(s[i][2], s[i][3]));
            #pragma unroll
            for (int off = 1; off < 16; off <<= 1)
                mx = fmaxf(mx, __shfl_xor_sync(0xffffffffu, mx, off));
            float mn = fmaxf(m[i], mx);
            float scale = expf(m[i] - mn);
            float sum = 0.f;
            #pragma unroll
            for (int j = 0; j < 4; j++) {
                float p = expf(s[i][j] - mn);
                s[i][j] = p; sum += p;
            }
            #pragma unroll
            for (int off = 1; off < 16; off <<= 1)
                sum += __shfl_xor_sync(0xffffffffu, sum, off);
            l[i] = l[i]*scale + sum;
            m[i] = mn;
            #pragma unroll
            for (int j = 0; j < 4; j++) o[i][j] *= scale;
            *(float4*)&sm.Ps[ty*4+i][tx*4] = make_float4(s[i][0], s[i][1], s[i][2], s[i][3]);
        }
        __syncthreads();

        // --- O += P V ---
        #pragma unroll
        for (int kk = 0; kk < KT; kk += 4) {
            float4 b0 = *(const float4*)&sm.Vs[kk+0][tx*4];
            float4 b1 = *(const float4*)&sm.Vs[kk+1][tx*4];
            float4 b2 = *(const float4*)&sm.Vs[kk+2][tx*4];
            float4 b3 = *(const float4*)&sm.Vs[kk+3][tx*4];
            #pragma unroll
            for (int i = 0; i < 4; i++) {
                float4 a = *(const float4*)&sm.Ps[ty*4+i][kk];
                o[i][0] += a.x*b0.x + a.y*b1.x + a.z*b2.x + a.w*b3.x;
                o[i][1] += a.x*b0.y + a.y*b1.y + a.z*b2.y + a.w*b3.y;
                o[i][2] += a.x*b0.z + a.y*b1.z + a.z*b2.z + a.w*b3.z;
                o[i][3] += a.x*b0.w + a.y*b1.w + a.z*b2.w + a.w*b3.w;
            }
        }
    }

    // epilogue: normalize, write [b, q, h*64 + d]
    #pragma unroll
    for (int i = 0; i < 4; i++) {
        float inv = 1.f / l[i];
        float* op = g_att + ((size_t)b*SS + q0 + ty*4 + i)*DD + h*HDIM + tx*4;
        *(float4*)op = make_float4(o[i][0]*inv, o[i][1]*inv, o[i][2]*inv, o[i][3]*inv);
    }
}

// ---------------- launch ----------------
extern "C" void kernel_launch(void* const* d_in, const int* in_sizes, int n_in,
                              void* d_out, int out_size)
{
    (void)in_sizes; (void)n_in; (void)out_size;
    const float* x  = (const float*)d_in[0];
    const float* Wq = (const float*)d_in[1];
    const float* Wk = (const float*)d_in[2];
    const float* Wv = (const float*)d_in[3];
    const float* Wo = (const float*)d_in[4];
    const float* bo = (const float*)d_in[5];
    const float* Ws = (const float*)d_in[6];
    const float* bs = (const float*)d_in[7];
    float* out = (float*)d_out;

    float *qlin, *klin, *vlin, *q, *qsp, *k, *ksp, *v, *att;
    cudaGetSymbolAddress((void**)&qlin, g_qlin);
    cudaGetSymbolAddress((void**)&klin, g_klin);
    cudaGetSymbolAddress((void**)&vlin, g_vlin);
    cudaGetSymbolAddress((void**)&q,    g_q);
    cudaGetSymbolAddress((void**)&qsp,  g_qsp);
    cudaGetSymbolAddress((void**)&k,    g_k);
    cudaGetSymbolAddress((void**)&ksp,  g_ksp);
    cudaGetSymbolAddress((void**)&v,    g_v);
    cudaGetSymbolAddress((void**)&att,  g_att);

    const int M = BB*SS;   // 4096
    const int smem_bytes = (int)sizeof(AttnSMem);
    static bool attr_set = false;
    if (!attr_set) {
        cudaFuncSetAttribute(attn_kernel64,
                             cudaFuncAttributeMaxDynamicSharedMemorySize, smem_bytes);
        attr_set = true;
    }

    init_rope_kernel<<<(SS*(HDIM/2) + 255)/256, 256>>>();

    gemm_nt_bias<<<dim3(DD/GBN,         M/GBM), 256>>>(x, Wq, nullptr, qlin, M, DD,        DD);
    gemm_nt_bias<<<dim3((HKV*HDIM)/GBN, M/GBM), 256>>>(x, Wk, nullptr, klin, M, HKV*HDIM, DD);
    gemm_nt_bias<<<dim3((HKV*HDIM)/GBN, M/GBM), 256>>>(x, Wv, nullptr, vlin, M, HKV*HDIM, DD);

    rope_sp_kernel<<<(BB*SS*HH  + 255)/256, 256>>>(qlin, nullptr, Ws, bs, q, qsp, nullptr, HH);
    rope_sp_kernel<<<(BB*SS*HKV + 255)/256, 256>>>(klin, vlin,    Ws, bs, k, ksp, v,       HKV);

    attn_kernel64<<<dim3(SS/QT, HH, BB), 256, smem_bytes>>>();

    gemm_nt_bias<<<dim3(DD/GBN, M/GBM), 256>>>(att, Wo, bo, out, M, DD, DD);
}

// round 3
// speedup vs baseline: 3.0162x; 1.3158x over previous
#include <cuda_runtime.h>
#include <cuda_bf16.h>
#include <math.h>

#define BB 2
#define SS 2048
#define DD 1024
#define HH 16
#define HKV 4
#define HDIM 64
#define SDIM 16

// ---------------- scratch (device globals; no allocation) ----------------
__device__ float g_qlin[BB*SS*DD];
__device__ float g_klin[BB*SS*HKV*HDIM];
__device__ float g_vlin[BB*SS*HKV*HDIM];
__device__ float g_q   [BB*HH*SS*HDIM];
__device__ float g_qsp [BB*HH*SS*SDIM];
__device__ float g_k   [BB*HKV*SS*HDIM];
__device__ float g_ksp [BB*HKV*SS*SDIM];
__device__ float g_v   [BB*HKV*SS*HDIM];
__device__ float g_att [BB*SS*DD];
__device__ float g_cosT[SS*(HDIM/2)];
__device__ float g_sinT[SS*(HDIM/2)];

// ---------------- RoPE table ----------------
__global__ void init_rope_kernel() {
    int idx = blockIdx.x*blockDim.x + threadIdx.x;
    if (idx >= SS*(HDIM/2)) return;
    int s = idx / (HDIM/2), i = idx % (HDIM/2);
    float thf = (float)pow(10000.0, -(double)i / (double)(HDIM/2));
    float ff  = (float)s * thf;
    g_cosT[idx] = (float)cos((double)ff);
    g_sinT[idx] = (float)sin((double)ff);
}

// ---------------- generic C[M,N] = A[M,K] @ W[N,K]^T (+bias) ----------------
#define GBM 64
#define GBN 64
#define GBK 16
__global__ void __launch_bounds__(256) gemm_nt_bias(
    const float* __restrict__ A, const float* __restrict__ W,
    const float* __restrict__ bias, float* __restrict__ C,
    int M, int N, int K)
{
    __shared__ float As[GBM][GBK+1];
    __shared__ float Bs[GBN][GBK+1];
    const int tx = threadIdx.x & 15, ty = threadIdx.x >> 4;
    const int row0 = blockIdx.y * GBM, col0 = blockIdx.x * GBN;
    float acc[4][4] = {};
    for (int k0 = 0; k0 < K; k0 += GBK) {
        #pragma unroll
        for (int t = 0; t < 4; t++) {
            int e = threadIdx.x + t*256;
            int r = e / GBK, c = e % GBK;
            As[r][c] = A[(size_t)(row0 + r)*K + k0 + c];
            Bs[r][c] = W[(size_t)(col0 + r)*K + k0 + c];
        }
        __syncthreads();
        #pragma unroll
        for (int kk = 0; kk < GBK; kk++) {
            float a[4], b[4];
            #pragma unroll
            for (int i = 0; i < 4; i++) a[i] = As[ty*4+i][kk];
            #pragma unroll
            for (int j = 0; j < 4; j++) b[j] = Bs[tx*4+j][kk];
            #pragma unroll
            for (int i = 0; i < 4; i++)
                #pragma unroll
                for (int j = 0; j < 4; j++)
                    acc[i][j] += a[i]*b[j];
        }
        __syncthreads();
    }
    #pragma unroll
    for (int i = 0; i < 4; i++) {
        int r = row0 + ty*4 + i;
        #pragma unroll
        for (int j = 0; j < 4; j++) {
            int c = col0 + tx*4 + j;
            float bv = bias ? bias[c] : 0.f;
            C[(size_t)r*N + c] = acc[i][j] + bv;
        }
    }
}

// ---------------- RoPE + low-rank sparsity projection + relayout ----------------
__global__ void rope_sp_kernel(const float* __restrict__ lin,
                               const float* __restrict__ vlin,
                               const float* __restrict__ Ws,
                               const float* __restrict__ bs,
                               float* __restrict__ obuf,
                               float* __restrict__ spbuf,
                               float* __restrict__ vbuf,
                               int NH)
{
    __shared__ float WsS[SDIM*HDIM];
    __shared__ float bsS[SDIM];
    for (int i = threadIdx.x; i < SDIM*HDIM; i += blockDim.x) WsS[i] = Ws[i];
    if (threadIdx.x < SDIM) bsS[threadIdx.x] = bs[threadIdx.x];
    __syncthreads();

    int idx = blockIdx.x*blockDim.x + threadIdx.x;
    int total = BB*SS*NH;
    if (idx >= total) return;
    int h = idx % NH;
    int s = (idx / NH) % SS;
    int b = idx / (NH*SS);

    const float* src = lin + ((size_t)(b*SS + s)*NH + h)*HDIM;
    float v[HDIM];
    #pragma unroll
    for (int d = 0; d < HDIM; d++) v[d] = src[d];

    #pragma unroll
    for (int i = 0; i < HDIM/2; i++) {
        float c  = g_cosT[s*(HDIM/2)+i];
        float sn = g_sinT[s*(HDIM/2)+i];
        float a  = v[i], bpart = v[i+HDIM/2];
        v[i]        = a*c - bpart*sn;
        v[i+HDIM/2] = bpart*c + a*sn;
    }

    float* dst = obuf + (((size_t)b*NH + h)*SS + s)*HDIM;
    #pragma unroll
    for (int d = 0; d < HDIM; d++) dst[d] = v[d];

    float* spd = spbuf + (((size_t)b*NH + h)*SS + s)*SDIM;
    for (int j = 0; j < SDIM; j++) {
        float acc = bsS[j];
        #pragma unroll
        for (int d = 0; d < HDIM; d++) acc += WsS[j*HDIM + d] * v[d];
        spd[j] = acc;
    }

    if (vlin) {
        const float* vsrc = vlin + ((size_t)(b*SS + s)*NH + h)*HDIM;
        float* vdst = vbuf + (((size_t)b*NH + h)*SS + s)*HDIM;
        #pragma unroll
        for (int d = 0; d < HDIM; d++) vdst[d] = vsrc[d];
    }
}

// ================= TF32 tensor-core attention =================
#define AQT 128        // queries per block (8 warps x 16 rows)
#define AKT 64         // keys per tile
#define KSTR 68        // K smem row stride (floats)  -> B-frag conflict-free
#define VSTR 72        // V smem row stride (floats)  -> B-frag conflict-free
#define SSTR 20        // Ksp smem row stride

__device__ __forceinline__ unsigned f2tf32(float f) {
    unsigned r;
    asm("cvt.rna.tf32.f32 %0, %1;" : "=r"(r) : "f"(f));
    return r;
}

__device__ __forceinline__ void mma_tf32(float& d0, float& d1, float& d2, float& d3,
                                         unsigned a0, unsigned a1, unsigned a2, unsigned a3,
                                         unsigned b0, unsigned b1) {
    asm volatile(
        "mma.sync.aligned.m16n8k8.row.col.f32.tf32.tf32.f32 "
        "{%0,%1,%2,%3},{%4,%5,%6,%7},{%8,%9},{%0,%1,%2,%3};"
        : "+f"(d0), "+f"(d1), "+f"(d2), "+f"(d3)
        : "r"(a0), "r"(a1), "r"(a2), "r"(a3), "r"(b0), "r"(b1));
}

__global__ void __launch_bounds__(256, 1) attn_mma_kernel()
{
    __shared__ unsigned Ks  [AKT*KSTR];   // tf32 bits, [key][dim]
    __shared__ unsigned Vs  [AKT*VSTR];   // tf32 bits, [key][dim]
    __shared__ unsigned Ksps[AKT*SSTR];   // tf32 bits, [key][j]

    const int b = blockIdx.z, h = blockIdx.y;
    const int hkv = h >> 2;
    const int q0 = (gridDim.x - 1 - blockIdx.x) * AQT;  // heavy blocks first
    const int tid = threadIdx.x;
    const int w = tid >> 5, lane = tid & 31;
    const int gid = lane >> 2, t4 = lane & 3;

    const int q0w = q0 + w*16;
    const int qr0 = q0w + gid;
    const int qr1 = qr0 + 8;

    const float* qbase = g_q   + ((size_t)b*HH  + h  )*SS*HDIM;
    const float* qspb  = g_qsp + ((size_t)b*HH  + h  )*SS*SDIM;
    const float* kptr  = g_k   + ((size_t)b*HKV + hkv)*SS*HDIM;
    const float* kspp  = g_ksp + ((size_t)b*HKV + hkv)*SS*SDIM;
    const float* vptr  = g_v   + ((size_t)b*HKV + hkv)*SS*HDIM;

    // ---- Q fragments (registers, persistent) ----
    unsigned qa[8][4], qsa[2][4];
    #pragma unroll
    for (int kt = 0; kt < 8; kt++) {
        qa[kt][0] = f2tf32(qbase[(size_t)qr0*HDIM + kt*8 + t4]);
        qa[kt][1] = f2tf32(qbase[(size_t)qr1*HDIM + kt*8 + t4]);
        qa[kt][2] = f2tf32(qbase[(size_t)qr0*HDIM + kt*8 + t4 + 4]);
        qa[kt][3] = f2tf32(qbase[(size_t)qr1*HDIM + kt*8 + t4 + 4]);
    }
    #pragma unroll
    for (int kt = 0; kt < 2; kt++) {
        qsa[kt][0] = f2tf32(qspb[(size_t)qr0*SDIM + kt*8 + t4]);
        qsa[kt][1] = f2tf32(qspb[(size_t)qr1*SDIM + kt*8 + t4]);
        qsa[kt][2] = f2tf32(qspb[(size_t)qr0*SDIM + kt*8 + t4 + 4]);
        qsa[kt][3] = f2tf32(qspb[(size_t)qr1*SDIM + kt*8 + t4 + 4]);
    }

    float m0 = -1e30f, m1 = -1e30f, l0 = 0.f, l1 = 0.f;
    float O[8][4];
    #pragma unroll
    for (int dn = 0; dn < 8; dn++)
        #pragma unroll
        for (int j = 0; j < 4; j++) O[dn][j] = 0.f;

    const int srcA = (lane & ~3) | (t4 >> 1);
    const int srcB = srcA + 2;
    const bool odd = (t4 & 1);

    for (int kb = 0; kb < q0 + AQT; kb += AKT) {
        __syncthreads();
        #pragma unroll
        for (int t = 0; t < 16; t++) {
            int i = tid + t*256;
            int key = i >> 6, d = i & 63;
            Ks[key*KSTR + d] = f2tf32(kptr[(size_t)kb*HDIM + i]);
            Vs[key*VSTR + d] = f2tf32(vptr[(size_t)kb*HDIM + i]);
        }
        #pragma unroll
        for (int t = 0; t < 4; t++) {
            int i = tid + t*256;
            Ksps[(i >> 4)*SSTR + (i & 15)] = f2tf32(kspp[(size_t)kb*SDIM + i]);
        }
        __syncthreads();

        if (kb > q0w + 15) continue;   // tile fully masked for this warp

        // ---- S = Q K^T ----
        float S[8][4], SP[8][4];
        #pragma unroll
        for (int nt = 0; nt < 8; nt++)
            #pragma unroll
            for (int j = 0; j < 4; j++) { S[nt][j] = 0.f; SP[nt][j] = 0.f; }

        #pragma unroll
        for (int kt = 0; kt < 8; kt++) {
            #pragma unroll
            for (int nt = 0; nt < 8; nt++) {
                unsigned b0 = Ks[(nt*8 + gid)*KSTR + kt*8 + t4];
                unsigned b1 = Ks[(nt*8 + gid)*KSTR + kt*8 + t4 + 4];
                mma_tf32(S[nt][0], S[nt][1], S[nt][2], S[nt][3],
                         qa[kt][0], qa[kt][1], qa[kt][2], qa[kt][3], b0, b1);
            }
        }
        #pragma unroll
        for (int kt = 0; kt < 2; kt++) {
            #pragma unroll
            for (int nt = 0; nt < 8; nt++) {
                unsigned b0 = Ksps[(nt*8 + gid)*SSTR + kt*8 + t4];
                unsigned b1 = Ksps[(nt*8 + gid)*SSTR + kt*8 + t4 + 4];
                mma_tf32(SP[nt][0], SP[nt][1], SP[nt][2], SP[nt][3],
                         qsa[kt][0], qsa[kt][1], qsa[kt][2], qsa[kt][3], b0, b1);
            }
        }

        // ---- gate + causal mask ----
        #pragma unroll
        for (int nt = 0; nt < 8; nt++) {
            #pragma unroll
            for (int j = 0; j < 4; j++) {
                int key = kb + nt*8 + 2*t4 + (j & 1);
                int row = (j >= 2) ? qr1 : qr0;
                float g = 1.f / (1.f + __expf(-SP[nt][j] * 0.25f));
                float lg = S[nt][j] * 0.125f * g;
                S[nt][j] = (key > row) ? -1e30f : lg;
            }
        }

        // ---- online softmax (rows qr0: regs 0,1 ; qr1: regs 2,3) ----
        float mx0 = -1e30f, mx1 = -1e30f;
        #pragma unroll
        for (int nt = 0; nt < 8; nt++) {
            mx0 = fmaxf(mx0, fmaxf(S[nt][0], S[nt][1]));
            mx1 = fmaxf(mx1, fmaxf(S[nt][2], S[nt][3]));
        }
        #pragma unroll
        for (int off = 1; off < 4; off <<= 1) {
            mx0 = fmaxf(mx0, __shfl_xor_sync(0xffffffffu, mx0, off));
            mx1 = fmaxf(mx1, __shfl_xor_sync(0xffffffffu, mx1, off));
        }
        float mn0 = fmaxf(m0, mx0), mn1 = fmaxf(m1, mx1);
        float sc0 = __expf(m0 - mn0), sc1 = __expf(m1 - mn1);
        float sum0 = 0.f, sum1 = 0.f;
        #pragma unroll
        for (int nt = 0; nt < 8; nt++) {
            S[nt][0] = __expf(S[nt][0] - mn0); sum0 += S[nt][0];
            S[nt][1] = __expf(S[nt][1] - mn0); sum0 += S[nt][1];
            S[nt][2] = __expf(S[nt][2] - mn1); sum1 += S[nt][2];
            S[nt][3] = __expf(S[nt][3] - mn1); sum1 += S[nt][3];
        }
        #pragma unroll
        for (int off = 1; off < 4; off <<= 1) {
            sum0 += __shfl_xor_sync(0xffffffffu, sum0, off);
            sum1 += __shfl_xor_sync(0xffffffffu, sum1, off);
        }
        l0 = l0*sc0 + sum0; l1 = l1*sc1 + sum1;
        m0 = mn0; m1 = mn1;
        #pragma unroll
        for (int dn = 0; dn < 8; dn++) {
            O[dn][0] *= sc0; O[dn][1] *= sc0;
            O[dn][2] *= sc1; O[dn][3] *= sc1;
        }

        // ---- O += P V : convert P (C-layout) -> A-fragments via quad shuffles ----
        #pragma unroll
        for (int kt = 0; kt < 8; kt++) {
            float e, o;
            e = __shfl_sync(0xffffffffu, S[kt][0], srcA);
            o = __shfl_sync(0xffffffffu, S[kt][1], srcA);
            unsigned a0 = f2tf32(odd ? o : e);
            e = __shfl_sync(0xffffffffu, S[kt][2], srcA);
            o = __shfl_sync(0xffffffffu, S[kt][3], srcA);
            unsigned a1 = f2tf32(odd ? o : e);
            e = __shfl_sync(0xffffffffu, S[kt][0], srcB);
            o = __shfl_sync(0xffffffffu, S[kt][1], srcB);
            unsigned a2 = f2tf32(odd ? o : e);
            e = __shfl_sync(0xffffffffu, S[kt][2], srcB);
            o = __shfl_sync(0xffffffffu, S[kt][3], srcB);
            unsigned a3 = f2tf32(odd ? o : e);

            #pragma unroll
            for (int dn = 0; dn < 8; dn++) {
                unsigned b0 = Vs[(kt*8 + t4    )*VSTR + dn*8 + gid];
                unsigned b1 = Vs[(kt*8 + t4 + 4)*VSTR + dn*8 + gid];
                mma_tf32(O[dn][0], O[dn][1], O[dn][2], O[dn][3],
                         a0, a1, a2, a3, b0, b1);
            }
        }
    }

    // ---- epilogue ----
    float inv0 = 1.f / l0, inv1 = 1.f / l1;
    #pragma unroll
    for (int dn = 0; dn < 8; dn++) {
        int col = h*HDIM + dn*8 + 2*t4;
        float2 r0 = make_float2(O[dn][0]*inv0, O[dn][1]*inv0);
        float2 r1 = make_float2(O[dn][2]*inv1, O[dn][3]*inv1);
        *(float2*)&g_att[((size_t)b*SS + qr0)*DD + col] = r0;
        *(float2*)&g_att[((size_t)b*SS + qr1)*DD + col] = r1;
    }
}

// ---------------- launch ----------------
extern "C" void kernel_launch(void* const* d_in, const int* in_sizes, int n_in,
                              void* d_out, int out_size)
{
    (void)in_sizes; (void)n_in; (void)out_size;
    const float* x  = (const float*)d_in[0];
    const float* Wq = (const float*)d_in[1];
    const float* Wk = (const float*)d_in[2];
    const float* Wv = (const float*)d_in[3];
    const float* Wo = (const float*)d_in[4];
    const float* bo = (const float*)d_in[5];
    const float* Ws = (const float*)d_in[6];
    const float* bs = (const float*)d_in[7];
    float* out = (float*)d_out;

    float *qlin, *klin, *vlin, *q, *qsp, *k, *ksp, *v, *att;
    cudaGetSymbolAddress((void**)&qlin, g_qlin);
    cudaGetSymbolAddress((void**)&klin, g_klin);
    cudaGetSymbolAddress((void**)&vlin, g_vlin);
    cudaGetSymbolAddress((void**)&q,    g_q);
    cudaGetSymbolAddress((void**)&qsp,  g_qsp);
    cudaGetSymbolAddress((void**)&k,    g_k);
    cudaGetSymbolAddress((void**)&ksp,  g_ksp);
    cudaGetSymbolAddress((void**)&v,    g_v);
    cudaGetSymbolAddress((void**)&att,  g_att);

    const int M = BB*SS;   // 4096

    init_rope_kernel<<<(SS*(HDIM/2) + 255)/256, 256>>>();

    gemm_nt_bias<<<dim3(DD/GBN,         M/GBM), 256>>>(x, Wq, nullptr, qlin, M, DD,        DD);
    gemm_nt_bias<<<dim3((HKV*HDIM)/GBN, M/GBM), 256>>>(x, Wk, nullptr, klin, M, HKV*HDIM, DD);
    gemm_nt_bias<<<dim3((HKV*HDIM)/GBN, M/GBM), 256>>>(x, Wv, nullptr, vlin, M, HKV*HDIM, DD);

    rope_sp_kernel<<<(BB*SS*HH  + 255)/256, 256>>>(qlin, nullptr, Ws, bs, q, qsp, nullptr, HH);
    rope_sp_kernel<<<(BB*SS*HKV + 255)/256, 256>>>(klin, vlin,    Ws, bs, k, ksp, v,       HKV);

    attn_mma_kernel<<<dim3(SS/AQT, HH, BB), 256>>>();

    gemm_nt_bias<<<dim3(DD/GBN, M/GBM), 256>>>(att, Wo, bo, out, M, DD, DD);
}

// round 4
// speedup vs baseline: 5.7259x; 1.8984x over previous
#include <cuda_runtime.h>
#include <cuda_bf16.h>
#include <math.h>

#define BB 2
#define SS 2048
#define DD 1024
#define HH 16
#define HKV 4
#define HDIM 64
#define SDIM 16

// ---------------- scratch (device globals; no allocation) ----------------
__device__ float g_qlin[BB*SS*DD];
__device__ float g_klin[BB*SS*HKV*HDIM];
__device__ float g_vlin[BB*SS*HKV*HDIM];
__device__ float g_q   [BB*HH*SS*HDIM];
__device__ float g_qsp [BB*HH*SS*SDIM];
__device__ float g_k   [BB*HKV*SS*HDIM];
__device__ float g_ksp [BB*HKV*SS*SDIM];
__device__ float g_v   [BB*HKV*SS*HDIM];
__device__ float g_att [BB*SS*DD];
__device__ float g_cosT[SS*(HDIM/2)];
__device__ float g_sinT[SS*(HDIM/2)];

// ---------------- common mma helpers ----------------
__device__ __forceinline__ unsigned f2tf32(float f) {
    unsigned r;
    asm("cvt.rna.tf32.f32 %0, %1;" : "=r"(r) : "f"(f));
    return r;
}

__device__ __forceinline__ void mma_tf32(float& d0, float& d1, float& d2, float& d3,
                                         unsigned a0, unsigned a1, unsigned a2, unsigned a3,
                                         unsigned b0, unsigned b1) {
    asm volatile(
        "mma.sync.aligned.m16n8k8.row.col.f32.tf32.tf32.f32 "
        "{%0,%1,%2,%3},{%4,%5,%6,%7},{%8,%9},{%0,%1,%2,%3};"
        : "+f"(d0), "+f"(d1), "+f"(d2), "+f"(d3)
        : "r"(a0), "r"(a1), "r"(a2), "r"(a3), "r"(b0), "r"(b1));
}

// ---------------- RoPE table ----------------
__global__ void init_rope_kernel() {
    int idx = blockIdx.x*blockDim.x + threadIdx.x;
    if (idx >= SS*(HDIM/2)) return;
    int s = idx / (HDIM/2), i = idx % (HDIM/2);
    float thf = (float)pow(10000.0, -(double)i / (double)(HDIM/2));
    float ff  = (float)s * thf;
    g_cosT[idx] = (float)cos((double)ff);
    g_sinT[idx] = (float)sin((double)ff);
}

// ================= TF32 tensor-core GEMM: C[M,N] = A[M,K] @ W[N,K]^T (+bias) =================
// block tile 128x64, 8 warps (4m x 2n), warp tile 32x32, BK=16, double-buffered.
#define TBM 128
#define TBN 64
#define TBK 16
#define TST 20   // smem row stride (floats): conflict-free fragment LDS

__global__ void __launch_bounds__(256) gemm_tf32(
    const float* __restrict__ A, const float* __restrict__ W,
    const float* __restrict__ bias, float* __restrict__ C,
    int M, int N, int K)
{
    __shared__ unsigned As[2][TBM*TST];
    __shared__ unsigned Bs[2][TBN*TST];

    const int tid = threadIdx.x;
    const int w = tid >> 5, lane = tid & 31;
    const int gid = lane >> 2, t4 = lane & 3;
    const int wm = w & 3, wn = w >> 2;
    const int row0 = blockIdx.y*TBM, col0 = blockIdx.x*TBN;

    // global->smem mapping (float4 granularity)
    const int ar0 = tid >> 2,          ac0 = (tid & 3) << 2;        // A f4 #tid
    const int ar1 = (tid + 256) >> 2,  ac1 = (tid & 3) << 2;        // A f4 #tid+256
    const int br  = tid >> 2,          bc  = (tid & 3) << 2;        // B f4 #tid

    const float* Aptr = A + (size_t)row0*K;
    const float* Wptr = W + (size_t)col0*K;

    float4 la0, la1, lb;
    // prologue: k0 = 0
    la0 = *(const float4*)(Aptr + (size_t)ar0*K + ac0);
    la1 = *(const float4*)(Aptr + (size_t)ar1*K + ac1);
    lb  = *(const float4*)(Wptr + (size_t)br *K + bc);
    {
        uint4 u;
        u.x=f2tf32(la0.x); u.y=f2tf32(la0.y); u.z=f2tf32(la0.z); u.w=f2tf32(la0.w);
        *(uint4*)&As[0][ar0*TST + ac0] = u;
        u.x=f2tf32(la1.x); u.y=f2tf32(la1.y); u.z=f2tf32(la1.z); u.w=f2tf32(la1.w);
        *(uint4*)&As[0][ar1*TST + ac1] = u;
        u.x=f2tf32(lb.x);  u.y=f2tf32(lb.y);  u.z=f2tf32(lb.z);  u.w=f2tf32(lb.w);
        *(uint4*)&Bs[0][br*TST + bc] = u;
    }
    __syncthreads();

    float acc[2][4][4];
    #pragma unroll
    for (int mt = 0; mt < 2; mt++)
        #pragma unroll
        for (int nt = 0; nt < 4; nt++)
            #pragma unroll
            for (int j = 0; j < 4; j++) acc[mt][nt][j] = 0.f;

    int buf = 0;
    for (int k0 = 0; k0 < K; k0 += TBK) {
        const bool has_next = (k0 + TBK) < K;
        if (has_next) {
            la0 = *(const float4*)(Aptr + (size_t)ar0*K + k0 + TBK + ac0);
            la1 = *(const float4*)(Aptr + (size_t)ar1*K + k0 + TBK + ac1);
            lb  = *(const float4*)(Wptr + (size_t)br *K + k0 + TBK + bc);
        }

        #pragma unroll
        for (int kk = 0; kk < TBK; kk += 8) {
            unsigned a[2][4];
            #pragma unroll
            for (int mt = 0; mt < 2; mt++) {
                int r0 = wm*32 + mt*16 + gid;
                a[mt][0] = As[buf][(r0    )*TST + kk + t4];
                a[mt][1] = As[buf][(r0 + 8)*TST + kk + t4];
                a[mt][2] = As[buf][(r0    )*TST + kk + t4 + 4];
                a[mt][3] = As[buf][(r0 + 8)*TST + kk + t4 + 4];
            }
            #pragma unroll
            for (int nt = 0; nt < 4; nt++) {
                int n0 = wn*32 + nt*8 + gid;
                unsigned b0 = Bs[buf][n0*TST + kk + t4];
                unsigned b1 = Bs[buf][n0*TST + kk + t4 + 4];
                #pragma unroll
                for (int mt = 0; mt < 2; mt++)
                    mma_tf32(acc[mt][nt][0], acc[mt][nt][1], acc[mt][nt][2], acc[mt][nt][3],
                             a[mt][0], a[mt][1], a[mt][2], a[mt][3], b0, b1);
            }
        }

        if (has_next) {
            uint4 u;
            u.x=f2tf32(la0.x); u.y=f2tf32(la0.y); u.z=f2tf32(la0.z); u.w=f2tf32(la0.w);
            *(uint4*)&As[buf^1][ar0*TST + ac0] = u;
            u.x=f2tf32(la1.x); u.y=f2tf32(la1.y); u.z=f2tf32(la1.z); u.w=f2tf32(la1.w);
            *(uint4*)&As[buf^1][ar1*TST + ac1] = u;
            u.x=f2tf32(lb.x);  u.y=f2tf32(lb.y);  u.z=f2tf32(lb.z);  u.w=f2tf32(lb.w);
            *(uint4*)&Bs[buf^1][br*TST + bc] = u;
            __syncthreads();
            buf ^= 1;
        }
    }

    // epilogue
    #pragma unroll
    for (int mt = 0; mt < 2; mt++) {
        int r = row0 + wm*32 + mt*16 + gid;
        #pragma unroll
        for (int nt = 0; nt < 4; nt++) {
            int c = col0 + wn*32 + nt*8 + 2*t4;
            float bv0 = bias ? bias[c]   : 0.f;
            float bv1 = bias ? bias[c+1] : 0.f;
            *(float2*)&C[(size_t)r*N + c]     = make_float2(acc[mt][nt][0]+bv0, acc[mt][nt][1]+bv1);
            *(float2*)&C[(size_t)(r+8)*N + c] = make_float2(acc[mt][nt][2]+bv0, acc[mt][nt][3]+bv1);
        }
    }
}

// ---------------- RoPE + low-rank sparsity projection + relayout ----------------
__global__ void rope_sp_kernel(const float* __restrict__ lin,
                               const float* __restrict__ vlin,
                               const float* __restrict__ Ws,
                               const float* __restrict__ bs,
                               float* __restrict__ obuf,
                               float* __restrict__ spbuf,
                               float* __restrict__ vbuf,
                               int NH)
{
    __shared__ float WsS[SDIM*HDIM];
    __shared__ float bsS[SDIM];
    for (int i = threadIdx.x; i < SDIM*HDIM; i += blockDim.x) WsS[i] = Ws[i];
    if (threadIdx.x < SDIM) bsS[threadIdx.x] = bs[threadIdx.x];
    __syncthreads();

    int idx = blockIdx.x*blockDim.x + threadIdx.x;
    int total = BB*SS*NH;
    if (idx >= total) return;
    int h = idx % NH;
    int s = (idx / NH) % SS;
    int b = idx / (NH*SS);

    const float4* src = (const float4*)(lin + ((size_t)(b*SS + s)*NH + h)*HDIM);
    float v[HDIM];
    #pragma unroll
    for (int t = 0; t < HDIM/4; t++) ((float4*)v)[t] = src[t];

    #pragma unroll
    for (int i = 0; i < HDIM/2; i++) {
        float c  = g_cosT[s*(HDIM/2)+i];
        float sn = g_sinT[s*(HDIM/2)+i];
        float a  = v[i], bpart = v[i+HDIM/2];
        v[i]        = a*c - bpart*sn;
        v[i+HDIM/2] = bpart*c + a*sn;
    }

    float4* dst = (float4*)(obuf + (((size_t)b*NH + h)*SS + s)*HDIM);
    #pragma unroll
    for (int t = 0; t < HDIM/4; t++) dst[t] = ((float4*)v)[t];

    float* spd = spbuf + (((size_t)b*NH + h)*SS + s)*SDIM;
    #pragma unroll
    for (int j = 0; j < SDIM; j++) {
        float acc = bsS[j];
        #pragma unroll
        for (int d = 0; d < HDIM; d++) acc += WsS[j*HDIM + d] * v[d];
        spd[j] = acc;
    }

    if (vlin) {
        const float4* vsrc = (const float4*)(vlin + ((size_t)(b*SS + s)*NH + h)*HDIM);
        float4* vdst = (float4*)(vbuf + (((size_t)b*NH + h)*SS + s)*HDIM);
        #pragma unroll
        for (int t = 0; t < HDIM/4; t++) vdst[t] = vsrc[t];
    }
}

// ================= TF32 tensor-core attention =================
#define AQT 128        // queries per block (8 warps x 16 rows)
#define AKT 64         // keys per tile
#define KSTR 68
#define VSTR 72
#define SSTR 20

__global__ void __launch_bounds__(256, 1) attn_mma_kernel()
{
    __shared__ unsigned Ks  [AKT*KSTR];
    __shared__ unsigned Vs  [AKT*VSTR];
    __shared__ unsigned Ksps[AKT*SSTR];

    const int b = blockIdx.z, h = blockIdx.y;
    const int hkv = h >> 2;
    const int q0 = (gridDim.x - 1 - blockIdx.x) * AQT;
    const int tid = threadIdx.x;
    const int w = tid >> 5, lane = tid & 31;
    const int gid = lane >> 2, t4 = lane & 3;

    const int q0w = q0 + w*16;
    const int qr0 = q0w + gid;
    const int qr1 = qr0 + 8;

    const float* qbase = g_q   + ((size_t)b*HH  + h  )*SS*HDIM;
    const float* qspb  = g_qsp + ((size_t)b*HH  + h  )*SS*SDIM;
    const float* kptr  = g_k   + ((size_t)b*HKV + hkv)*SS*HDIM;
    const float* kspp  = g_ksp + ((size_t)b*HKV + hkv)*SS*SDIM;
    const float* vptr  = g_v   + ((size_t)b*HKV + hkv)*SS*HDIM;

    unsigned qa[8][4], qsa[2][4];
    #pragma unroll
    for (int kt = 0; kt < 8; kt++) {
        qa[kt][0] = f2tf32(qbase[(size_t)qr0*HDIM + kt*8 + t4]);
        qa[kt][1] = f2tf32(qbase[(size_t)qr1*HDIM + kt*8 + t4]);
        qa[kt][2] = f2tf32(qbase[(size_t)qr0*HDIM + kt*8 + t4 + 4]);
        qa[kt][3] = f2tf32(qbase[(size_t)qr1*HDIM + kt*8 + t4 + 4]);
    }
    #pragma unroll
    for (int kt = 0; kt < 2; kt++) {
        qsa[kt][0] = f2tf32(qspb[(size_t)qr0*SDIM + kt*8 + t4]);
        qsa[kt][1] = f2tf32(qspb[(size_t)qr1*SDIM + kt*8 + t4]);
        qsa[kt][2] = f2tf32(qspb[(size_t)qr0*SDIM + kt*8 + t4 + 4]);
        qsa[kt][3] = f2tf32(qspb[(size_t)qr1*SDIM + kt*8 + t4 + 4]);
    }

    float m0 = -1e30f, m1 = -1e30f, l0 = 0.f, l1 = 0.f;
    float O[8][4];
    #pragma unroll
    for (int dn = 0; dn < 8; dn++)
        #pragma unroll
        for (int j = 0; j < 4; j++) O[dn][j] = 0.f;

    const int srcA = (lane & ~3) | (t4 >> 1);
    const int srcB = srcA + 2;
    const bool odd = (t4 & 1);

    for (int kb = 0; kb < q0 + AQT; kb += AKT) {
        __syncthreads();
        #pragma unroll
        for (int t = 0; t < 16; t++) {
            int i = tid + t*256;
            int key = i >> 6, d = i & 63;
            Ks[key*KSTR + d] = f2tf32(kptr[(size_t)kb*HDIM + i]);
            Vs[key*VSTR + d] = f2tf32(vptr[(size_t)kb*HDIM + i]);
        }
        #pragma unroll
        for (int t = 0; t < 4; t++) {
            int i = tid + t*256;
            Ksps[(i >> 4)*SSTR + (i & 15)] = f2tf32(kspp[(size_t)kb*SDIM + i]);
        }
        __syncthreads();

        if (kb > q0w + 15) continue;

        float S[8][4], SP[8][4];
        #pragma unroll
        for (int nt = 0; nt < 8; nt++)
            #pragma unroll
            for (int j = 0; j < 4; j++) { S[nt][j] = 0.f; SP[nt][j] = 0.f; }

        #pragma unroll
        for (int kt = 0; kt < 8; kt++) {
            #pragma unroll
            for (int nt = 0; nt < 8; nt++) {
                unsigned b0 = Ks[(nt*8 + gid)*KSTR + kt*8 + t4];
                unsigned b1 = Ks[(nt*8 + gid)*KSTR + kt*8 + t4 + 4];
                mma_tf32(S[nt][0], S[nt][1], S[nt][2], S[nt][3],
                         qa[kt][0], qa[kt][1], qa[kt][2], qa[kt][3], b0, b1);
            }
        }
        #pragma unroll
        for (int kt = 0; kt < 2; kt++) {
            #pragma unroll
            for (int nt = 0; nt < 8; nt++) {
                unsigned b0 = Ksps[(nt*8 + gid)*SSTR + kt*8 + t4];
                unsigned b1 = Ksps[(nt*8 + gid)*SSTR + kt*8 + t4 + 4];
                mma_tf32(SP[nt][0], SP[nt][1], SP[nt][2], SP[nt][3],
                         qsa[kt][0], qsa[kt][1], qsa[kt][2], qsa[kt][3], b0, b1);
            }
        }

        #pragma unroll
        for (int nt = 0; nt < 8; nt++) {
            #pragma unroll
            for (int j = 0; j < 4; j++) {
                int key = kb + nt*8 + 2*t4 + (j & 1);
                int row = (j >= 2) ? qr1 : qr0;
                float g = 1.f / (1.f + __expf(-SP[nt][j] * 0.25f));
                float lg = S[nt][j] * 0.125f * g;
                S[nt][j] = (key > row) ? -1e30f : lg;
            }
        }

        float mx0 = -1e30f, mx1 = -1e30f;
        #pragma unroll
        for (int nt = 0; nt < 8; nt++) {
            mx0 = fmaxf(mx0, fmaxf(S[nt][0], S[nt][1]));
            mx1 = fmaxf(mx1, fmaxf(S[nt][2], S[nt][3]));
        }
        #pragma unroll
        for (int off = 1; off < 4; off <<= 1) {
            mx0 = fmaxf(mx0, __shfl_xor_sync(0xffffffffu, mx0, off));
            mx1 = fmaxf(mx1, __shfl_xor_sync(0xffffffffu, mx1, off));
        }
        float mn0 = fmaxf(m0, mx0), mn1 = fmaxf(m1, mx1);
        float sc0 = __expf(m0 - mn0), sc1 = __expf(m1 - mn1);
        float sum0 = 0.f, sum1 = 0.f;
        #pragma unroll
        for (int nt = 0; nt < 8; nt++) {
            S[nt][0] = __expf(S[nt][0] - mn0); sum0 += S[nt][0];
            S[nt][1] = __expf(S[nt][1] - mn0); sum0 += S[nt][1];
            S[nt][2] = __expf(S[nt][2] - mn1); sum1 += S[nt][2];
            S[nt][3] = __expf(S[nt][3] - mn1); sum1 += S[nt][3];
        }
        #pragma unroll
        for (int off = 1; off < 4; off <<= 1) {
            sum0 += __shfl_xor_sync(0xffffffffu, sum0, off);
            sum1 += __shfl_xor_sync(0xffffffffu, sum1, off);
        }
        l0 = l0*sc0 + sum0; l1 = l1*sc1 + sum1;
        m0 = mn0; m1 = mn1;
        #pragma unroll
        for (int dn = 0; dn < 8; dn++) {
            O[dn][0] *= sc0; O[dn][1] *= sc0;
            O[dn][2] *= sc1; O[dn][3] *= sc1;
        }

        #pragma unroll
        for (int kt = 0; kt < 8; kt++) {
            float e, o;
            e = __shfl_sync(0xffffffffu, S[kt][0], srcA);
            o = __shfl_sync(0xffffffffu, S[kt][1], srcA);
            unsigned a0 = f2tf32(odd ? o : e);
            e = __shfl_sync(0xffffffffu, S[kt][2], srcA);
            o = __shfl_sync(0xffffffffu, S[kt][3], srcA);
            unsigned a1 = f2tf32(odd ? o : e);
            e = __shfl_sync(0xffffffffu, S[kt][0], srcB);
            o = __shfl_sync(0xffffffffu, S[kt][1], srcB);
            unsigned a2 = f2tf32(odd ? o : e);
            e = __shfl_sync(0xffffffffu, S[kt][2], srcB);
            o = __shfl_sync(0xffffffffu, S[kt][3], srcB);
            unsigned a3 = f2tf32(odd ? o : e);

            #pragma unroll
            for (int dn = 0; dn < 8; dn++) {
                unsigned b0 = Vs[(kt*8 + t4    )*VSTR + dn*8 + gid];
                unsigned b1 = Vs[(kt*8 + t4 + 4)*VSTR + dn*8 + gid];
                mma_tf32(O[dn][0], O[dn][1], O[dn][2], O[dn][3],
                         a0, a1, a2, a3, b0, b1);
            }
        }
    }

    float inv0 = 1.f / l0, inv1 = 1.f / l1;
    #pragma unroll
    for (int dn = 0; dn < 8; dn++) {
        int col = h*HDIM + dn*8 + 2*t4;
        float2 r0 = make_float2(O[dn][0]*inv0, O[dn][1]*inv0);
        float2 r1 = make_float2(O[dn][2]*inv1, O[dn][3]*inv1);
        *(float2*)&g_att[((size_t)b*SS + qr0)*DD + col] = r0;
        *(float2*)&g_att[((size_t)b*SS + qr1)*DD + col] = r1;
    }
}

// ---------------- launch ----------------
extern "C" void kernel_launch(void* const* d_in, const int* in_sizes, int n_in,
                              void* d_out, int out_size)
{
    (void)in_sizes; (void)n_in; (void)out_size;
    const float* x  = (const float*)d_in[0];
    const float* Wq = (const float*)d_in[1];
    const float* Wk = (const float*)d_in[2];
    const float* Wv = (const float*)d_in[3];
    const float* Wo = (const float*)d_in[4];
    const float* bo = (const float*)d_in[5];
    const float* Ws = (const float*)d_in[6];
    const float* bs = (const float*)d_in[7];
    float* out = (float*)d_out;

    float *qlin, *klin, *vlin, *q, *qsp, *k, *ksp, *v, *att;
    cudaGetSymbolAddress((void**)&qlin, g_qlin);
    cudaGetSymbolAddress((void**)&klin, g_klin);
    cudaGetSymbolAddress((void**)&vlin, g_vlin);
    cudaGetSymbolAddress((void**)&q,    g_q);
    cudaGetSymbolAddress((void**)&qsp,  g_qsp);
    cudaGetSymbolAddress((void**)&k,    g_k);
    cudaGetSymbolAddress((void**)&ksp,  g_ksp);
    cudaGetSymbolAddress((void**)&v,    g_v);
    cudaGetSymbolAddress((void**)&att,  g_att);

    const int M = BB*SS;   // 4096

    init_rope_kernel<<<(SS*(HDIM/2) + 255)/256, 256>>>();

    gemm_tf32<<<dim3(DD/TBN,         M/TBM), 256>>>(x, Wq, nullptr, qlin, M, DD,        DD);
    gemm_tf32<<<dim3((HKV*HDIM)/TBN, M/TBM), 256>>>(x, Wk, nullptr, klin, M, HKV*HDIM, DD);
    gemm_tf32<<<dim3((HKV*HDIM)/TBN, M/TBM), 256>>>(x, Wv, nullptr, vlin, M, HKV*HDIM, DD);

    rope_sp_kernel<<<(BB*SS*HH  + 255)/256, 256>>>(qlin, nullptr, Ws, bs, q, qsp, nullptr, HH);
    rope_sp_kernel<<<(BB*SS*HKV + 255)/256, 256>>>(klin, vlin,    Ws, bs, k, ksp, v,       HKV);

    attn_mma_kernel<<<dim3(SS/AQT, HH, BB), 256>>>();

    gemm_tf32<<<dim3(DD/TBN, M/TBM), 256>>>(att, Wo, bo, out, M, DD, DD);
}

// round 5
// speedup vs baseline: 6.7240x; 1.1743x over previous
#include <cuda_runtime.h>
#include <cuda_bf16.h>
#include <math.h>

#define BB 2
#define SS 2048
#define DD 1024
#define HH 16
#define HKV 4
#define HDIM 64
#define SDIM 16

// ---------------- scratch (device globals; no allocation) ----------------
__device__ float    g_qlin[BB*SS*DD];
__device__ float    g_klin[BB*SS*HKV*HDIM];
__device__ float    g_vlin[BB*SS*HKV*HDIM];
__device__ float    g_q   [BB*HH*SS*HDIM];
__device__ float    g_qsp [BB*HH*SS*SDIM];
__device__ float    g_k   [BB*HKV*SS*HDIM];
__device__ float    g_ksp [BB*HKV*SS*SDIM];
__device__ float    g_v   [BB*HKV*SS*HDIM];
__device__ float    g_att [BB*SS*DD];          // holds tf32-rounded bit patterns
__device__ float    g_cosT[SS*(HDIM/2)];
__device__ float    g_sinT[SS*(HDIM/2)];
// tf32-preconverted operands
__device__ unsigned g_xc  [BB*SS*DD];
__device__ unsigned g_wqc [DD*DD];
__device__ unsigned g_wkc [HKV*HDIM*DD];
__device__ unsigned g_wvc [HKV*HDIM*DD];
__device__ unsigned g_woc [DD*DD];

// ---------------- common helpers ----------------
__device__ __forceinline__ unsigned f2tf32(float f) {
    unsigned r;
    asm("cvt.rna.tf32.f32 %0, %1;" : "=r"(r) : "f"(f));
    return r;
}

__device__ __forceinline__ void mma_tf32(float& d0, float& d1, float& d2, float& d3,
                                         unsigned a0, unsigned a1, unsigned a2, unsigned a3,
                                         unsigned b0, unsigned b1) {
    asm volatile(
        "mma.sync.aligned.m16n8k8.row.col.f32.tf32.tf32.f32 "
        "{%0,%1,%2,%3},{%4,%5,%6,%7},{%8,%9},{%0,%1,%2,%3};"
        : "+f"(d0), "+f"(d1), "+f"(d2), "+f"(d3)
        : "r"(a0), "r"(a1), "r"(a2), "r"(a3), "r"(b0), "r"(b1));
}

__device__ __forceinline__ unsigned smem_u32(const void* p) {
    return (unsigned)__cvta_generic_to_shared(p);
}
__device__ __forceinline__ void cp16(unsigned dst, const void* src) {
    asm volatile("cp.async.cg.shared.global [%0], [%1], 16;" :: "r"(dst), "l"(src));
}

// ---------------- tf32 pre-conversion ----------------
__global__ void cvt_tf32_kernel(const float* __restrict__ in,
                                unsigned* __restrict__ out, int n4) {
    int i = blockIdx.x*blockDim.x + threadIdx.x;
    if (i >= n4) return;
    float4 f = ((const float4*)in)[i];
    uint4 u;
    u.x = f2tf32(f.x); u.y = f2tf32(f.y); u.z = f2tf32(f.z); u.w = f2tf32(f.w);
    ((uint4*)out)[i] = u;
}

// ---------------- RoPE table ----------------
__global__ void init_rope_kernel() {
    int idx = blockIdx.x*blockDim.x + threadIdx.x;
    if (idx >= SS*(HDIM/2)) return;
    int s = idx / (HDIM/2), i = idx % (HDIM/2);
    float thf = (float)pow(10000.0, -(double)i / (double)(HDIM/2));
    float ff  = (float)s * thf;
    g_cosT[idx] = (float)cos((double)ff);
    g_sinT[idx] = (float)sin((double)ff);
}

// ================= cp.async-pipelined TF32 GEMM =================
// C[M,N] = A[M,K] @ W[N,K]^T (+bias). A/W pre-converted to tf32 bits.
// block tile 128x64, 8 warps (4m x 2n), BK=16, 3-stage cp.async pipeline.
// Up to 3 independent (W,C,N) segments selected by blockIdx.x.
#define TBM 128
#define TBN 64
#define TBK 16
#define PADK 20
#define STG 3

__global__ void __launch_bounds__(256) gemm3(
    const unsigned* __restrict__ A,
    const unsigned* __restrict__ W0, float* __restrict__ C0, int nx0, int N0,
    const unsigned* __restrict__ W1, float* __restrict__ C1, int nx1, int N1,
    const unsigned* __restrict__ W2, float* __restrict__ C2, int nx2, int N2,
    const float* __restrict__ bias, int K)
{
    __shared__ unsigned As[STG][TBM*PADK];
    __shared__ unsigned Bs[STG][TBN*PADK];

    const int tid = threadIdx.x;
    const int w = tid >> 5, lane = tid & 31;
    const int gid = lane >> 2, t4 = lane & 3;
    const int wm = w & 3, wn = w >> 2;
    const int row0 = blockIdx.y*TBM;

    const unsigned* Wp; float* Cp; int N, cb;
    int bx = blockIdx.x;
    if (bx < nx0)            { Wp = W0; Cp = C0; N = N0; cb = bx; }
    else if (bx < nx0 + nx1) { Wp = W1; Cp = C1; N = N1; cb = bx - nx0; }
    else                     { Wp = W2; Cp = C2; N = N2; cb = bx - nx0 - nx1; }
    const int col0 = cb*TBN;

    const unsigned* Aptr = A  + (size_t)row0*K;
    const unsigned* Wptr = Wp + (size_t)col0*K;

    // cp.async chunk mapping (16B = 4 elems)
    const int arow0 = tid >> 2, acol = (tid & 3) << 2;  // A chunk #tid
    const int arow1 = arow0 + 64;                       // A chunk #tid+256
    const int brow  = tid >> 2, bcol = acol;            // B chunk #tid

    const unsigned asA = smem_u32(&As[0][0]);
    const unsigned asB = smem_u32(&Bs[0][0]);

    // prologue: stages 0..STG-2
    #pragma unroll
    for (int s = 0; s < STG-1; s++) {
        int k0 = s*TBK;
        cp16(asA + (s*(TBM*PADK) + arow0*PADK + acol)*4, Aptr + (size_t)arow0*K + k0 + acol);
        cp16(asA + (s*(TBM*PADK) + arow1*PADK + acol)*4, Aptr + (size_t)arow1*K + k0 + acol);
        cp16(asB + (s*(TBN*PADK) + brow *PADK + bcol)*4, Wptr + (size_t)brow*K + k0 + bcol);
        asm volatile("cp.async.commit_group;");
    }

    float acc[2][4][4];
    #pragma unroll
    for (int mt = 0; mt < 2; mt++)
        #pragma unroll
        for (int nt = 0; nt < 4; nt++)
            #pragma unroll
            for (int j = 0; j < 4; j++) acc[mt][nt][j] = 0.f;

    const int T = K / TBK;
    int st = 0, si = STG - 1;
    for (int t = 0; t < T; t++) {
        asm volatile("cp.async.wait_group 1;" ::: "memory");
        __syncthreads();

        if (t + STG - 1 < T) {
            int k0 = (t + STG - 1)*TBK;
            cp16(asA + (si*(TBM*PADK) + arow0*PADK + acol)*4, Aptr + (size_t)arow0*K + k0 + acol);
            cp16(asA + (si*(TBM*PADK) + arow1*PADK + acol)*4, Aptr + (size_t)arow1*K + k0 + acol);
            cp16(asB + (si*(TBN*PADK) + brow *PADK + bcol)*4, Wptr + (size_t)brow*K + k0 + bcol);
        }
        asm volatile("cp.async.commit_group;");

        #pragma unroll
        for (int kk = 0; kk < TBK; kk += 8) {
            unsigned a[2][4];
            #pragma unroll
            for (int mt = 0; mt < 2; mt++) {
                int r0 = wm*32 + mt*16 + gid;
                a[mt][0] = As[st][(r0    )*PADK + kk + t4];
                a[mt][1] = As[st][(r0 + 8)*PADK + kk + t4];
                a[mt][2] = As[st][(r0    )*PADK + kk + t4 + 4];
                a[mt][3] = As[st][(r0 + 8)*PADK + kk + t4 + 4];
            }
            #pragma unroll
            for (int nt = 0; nt < 4; nt++) {
                int n0 = wn*32 + nt*8 + gid;
                unsigned b0 = Bs[st][n0*PADK + kk + t4];
                unsigned b1 = Bs[st][n0*PADK + kk + t4 + 4];
                #pragma unroll
                for (int mt = 0; mt < 2; mt++)
                    mma_tf32(acc[mt][nt][0], acc[mt][nt][1], acc[mt][nt][2], acc[mt][nt][3],
                             a[mt][0], a[mt][1], a[mt][2], a[mt][3], b0, b1);
            }
        }
        st = (st + 1 == STG) ? 0 : st + 1;
        si = (si + 1 == STG) ? 0 : si + 1;
    }

    // epilogue
    #pragma unroll
    for (int mt = 0; mt < 2; mt++) {
        int r = row0 + wm*32 + mt*16 + gid;
        #pragma unroll
        for (int nt = 0; nt < 4; nt++) {
            int c = col0 + wn*32 + nt*8 + 2*t4;
            float bv0 = bias ? bias[c]   : 0.f;
            float bv1 = bias ? bias[c+1] : 0.f;
            *(float2*)&Cp[(size_t)r*N + c]     = make_float2(acc[mt][nt][0]+bv0, acc[mt][nt][1]+bv1);
            *(float2*)&Cp[(size_t)(r+8)*N + c] = make_float2(acc[mt][nt][2]+bv0, acc[mt][nt][3]+bv1);
        }
    }
}

// ---------------- RoPE + low-rank sparsity projection + relayout ----------------
__global__ void rope_sp_kernel(const float* __restrict__ lin,
                               const float* __restrict__ vlin,
                               const float* __restrict__ Ws,
                               const float* __restrict__ bs,
                               float* __restrict__ obuf,
                               float* __restrict__ spbuf,
                               float* __restrict__ vbuf,
                               int NH)
{
    __shared__ float WsS[SDIM*HDIM];
    __shared__ float bsS[SDIM];
    for (int i = threadIdx.x; i < SDIM*HDIM; i += blockDim.x) WsS[i] = Ws[i];
    if (threadIdx.x < SDIM) bsS[threadIdx.x] = bs[threadIdx.x];
    __syncthreads();

    int idx = blockIdx.x*blockDim.x + threadIdx.x;
    int total = BB*SS*NH;
    if (idx >= total) return;
    int h = idx % NH;
    int s = (idx / NH) % SS;
    int b = idx / (NH*SS);

    const float4* src = (const float4*)(lin + ((size_t)(b*SS + s)*NH + h)*HDIM);
    float v[HDIM];
    #pragma unroll
    for (int t = 0; t < HDIM/4; t++) ((float4*)v)[t] = src[t];

    #pragma unroll
    for (int i = 0; i < HDIM/2; i++) {
        float c  = g_cosT[s*(HDIM/2)+i];
        float sn = g_sinT[s*(HDIM/2)+i];
        float a  = v[i], bpart = v[i+HDIM/2];
        v[i]        = a*c - bpart*sn;
        v[i+HDIM/2] = bpart*c + a*sn;
    }

    float4* dst = (float4*)(obuf + (((size_t)b*NH + h)*SS + s)*HDIM);
    #pragma unroll
    for (int t = 0; t < HDIM/4; t++) dst[t] = ((float4*)v)[t];

    float* spd = spbuf + (((size_t)b*NH + h)*SS + s)*SDIM;
    #pragma unroll
    for (int j = 0; j < SDIM; j++) {
        float acc = bsS[j];
        #pragma unroll
        for (int d = 0; d < HDIM; d++) acc += WsS[j*HDIM + d] * v[d];
        spd[j] = acc;
    }

    if (vlin) {
        const float4* vsrc = (const float4*)(vlin + ((size_t)(b*SS + s)*NH + h)*HDIM);
        float4* vdst = (float4*)(vbuf + (((size_t)b*NH + h)*SS + s)*HDIM);
        #pragma unroll
        for (int t = 0; t < HDIM/4; t++) vdst[t] = vsrc[t];
    }
}

// ================= TF32 tensor-core attention =================
#define AQT 128
#define AKT 64
#define KSTR 68
#define VSTR 72
#define SSTR 20

__global__ void __launch_bounds__(256, 1) attn_mma_kernel()
{
    __shared__ unsigned Ks  [AKT*KSTR];
    __shared__ unsigned Vs  [AKT*VSTR];
    __shared__ unsigned Ksps[AKT*SSTR];

    const int b = blockIdx.z, h = blockIdx.y;
    const int hkv = h >> 2;
    const int q0 = (gridDim.x - 1 - blockIdx.x) * AQT;
    const int tid = threadIdx.x;
    const int w = tid >> 5, lane = tid & 31;
    const int gid = lane >> 2, t4 = lane & 3;

    const int q0w = q0 + w*16;
    const int qr0 = q0w + gid;
    const int qr1 = qr0 + 8;

    const float* qbase = g_q   + ((size_t)b*HH  + h  )*SS*HDIM;
    const float* qspb  = g_qsp + ((size_t)b*HH  + h  )*SS*SDIM;
    const float* kptr  = g_k   + ((size_t)b*HKV + hkv)*SS*HDIM;
    const float* kspp  = g_ksp + ((size_t)b*HKV + hkv)*SS*SDIM;
    const float* vptr  = g_v   + ((size_t)b*HKV + hkv)*SS*HDIM;

    unsigned qa[8][4], qsa[2][4];
    #pragma unroll
    for (int kt = 0; kt < 8; kt++) {
        qa[kt][0] = f2tf32(qbase[(size_t)qr0*HDIM + kt*8 + t4]);
        qa[kt][1] = f2tf32(qbase[(size_t)qr1*HDIM + kt*8 + t4]);
        qa[kt][2] = f2tf32(qbase[(size_t)qr0*HDIM + kt*8 + t4 + 4]);
        qa[kt][3] = f2tf32(qbase[(size_t)qr1*HDIM + kt*8 + t4 + 4]);
    }
    #pragma unroll
    for (int kt = 0; kt < 2; kt++) {
        qsa[kt][0] = f2tf32(qspb[(size_t)qr0*SDIM + kt*8 + t4]);
        qsa[kt][1] = f2tf32(qspb[(size_t)qr1*SDIM + kt*8 + t4]);
        qsa[kt][2] = f2tf32(qspb[(size_t)qr0*SDIM + kt*8 + t4 + 4]);
        qsa[kt][3] = f2tf32(qspb[(size_t)qr1*SDIM + kt*8 + t4 + 4]);
    }

    float m0 = -1e30f, m1 = -1e30f, l0 = 0.f, l1 = 0.f;
    float O[8][4];
    #pragma unroll
    for (int dn = 0; dn < 8; dn++)
        #pragma unroll
        for (int j = 0; j < 4; j++) O[dn][j] = 0.f;

    const int srcA = (lane & ~3) | (t4 >> 1);
    const int srcB = srcA + 2;
    const bool odd = (t4 & 1);

    for (int kb = 0; kb < q0 + AQT; kb += AKT) {
        __syncthreads();
        #pragma unroll
        for (int t = 0; t < 16; t++) {
            int i = tid + t*256;
            int key = i >> 6, d = i & 63;
            Ks[key*KSTR + d] = f2tf32(kptr[(size_t)kb*HDIM + i]);
            Vs[key*VSTR + d] = f2tf32(vptr[(size_t)kb*HDIM + i]);
        }
        #pragma unroll
        for (int t = 0; t < 4; t++) {
            int i = tid + t*256;
            Ksps[(i >> 4)*SSTR + (i & 15)] = f2tf32(kspp[(size_t)kb*SDIM + i]);
        }
        __syncthreads();

        if (kb > q0w + 15) continue;

        float S[8][4], SP[8][4];
        #pragma unroll
        for (int nt = 0; nt < 8; nt++)
            #pragma unroll
            for (int j = 0; j < 4; j++) { S[nt][j] = 0.f; SP[nt][j] = 0.f; }

        #pragma unroll
        for (int kt = 0; kt < 8; kt++) {
            #pragma unroll
            for (int nt = 0; nt < 8; nt++) {
                unsigned b0 = Ks[(nt*8 + gid)*KSTR + kt*8 + t4];
                unsigned b1 = Ks[(nt*8 + gid)*KSTR + kt*8 + t4 + 4];
                mma_tf32(S[nt][0], S[nt][1], S[nt][2], S[nt][3],
                         qa[kt][0], qa[kt][1], qa[kt][2], qa[kt][3], b0, b1);
            }
        }
        #pragma unroll
        for (int kt = 0; kt < 2; kt++) {
            #pragma unroll
            for (int nt = 0; nt < 8; nt++) {
                unsigned b0 = Ksps[(nt*8 + gid)*SSTR + kt*8 + t4];
                unsigned b1 = Ksps[(nt*8 + gid)*SSTR + kt*8 + t4 + 4];
                mma_tf32(SP[nt][0], SP[nt][1], SP[nt][2], SP[nt][3],
                         qsa[kt][0], qsa[kt][1], qsa[kt][2], qsa[kt][3], b0, b1);
            }
        }

        #pragma unroll
        for (int nt = 0; nt < 8; nt++) {
            #pragma unroll
            for (int j = 0; j < 4; j++) {
                int key = kb + nt*8 + 2*t4 + (j & 1);
                int row = (j >= 2) ? qr1 : qr0;
                float g = 1.f / (1.f + __expf(-SP[nt][j] * 0.25f));
                float lg = S[nt][j] * 0.125f * g;
                S[nt][j] = (key > row) ? -1e30f : lg;
            }
        }

        float mx0 = -1e30f, mx1 = -1e30f;
        #pragma unroll
        for (int nt = 0; nt < 8; nt++) {
            mx0 = fmaxf(mx0, fmaxf(S[nt][0], S[nt][1]));
            mx1 = fmaxf(mx1, fmaxf(S[nt][2], S[nt][3]));
        }
        #pragma unroll
        for (int off = 1; off < 4; off <<= 1) {
            mx0 = fmaxf(mx0, __shfl_xor_sync(0xffffffffu, mx0, off));
            mx1 = fmaxf(mx1, __shfl_xor_sync(0xffffffffu, mx1, off));
        }
        float mn0 = fmaxf(m0, mx0), mn1 = fmaxf(m1, mx1);
        float sc0 = __expf(m0 - mn0), sc1 = __expf(m1 - mn1);
        float sum0 = 0.f, sum1 = 0.f;
        #pragma unroll
        for (int nt = 0; nt < 8; nt++) {
            S[nt][0] = __expf(S[nt][0] - mn0); sum0 += S[nt][0];
            S[nt][1] = __expf(S[nt][1] - mn0); sum0 += S[nt][1];
            S[nt][2] = __expf(S[nt][2] - mn1); sum1 += S[nt][2];
            S[nt][3] = __expf(S[nt][3] - mn1); sum1 += S[nt][3];
        }
        #pragma unroll
        for (int off = 1; off < 4; off <<= 1) {
            sum0 += __shfl_xor_sync(0xffffffffu, sum0, off);
            sum1 += __shfl_xor_sync(0xffffffffu, sum1, off);
        }
        l0 = l0*sc0 + sum0; l1 = l1*sc1 + sum1;
        m0 = mn0; m1 = mn1;
        #pragma unroll
        for (int dn = 0; dn < 8; dn++) {
            O[dn][0] *= sc0; O[dn][1] *= sc0;
            O[dn][2] *= sc1; O[dn][3] *= sc1;
        }

        #pragma unroll
        for (int kt = 0; kt < 8; kt++) {
            float e, o;
            e = __shfl_sync(0xffffffffu, S[kt][0], srcA);
            o = __shfl_sync(0xffffffffu, S[kt][1], srcA);
            unsigned a0 = f2tf32(odd ? o : e);
            e = __shfl_sync(0xffffffffu, S[kt][2], srcA);
            o = __shfl_sync(0xffffffffu, S[kt][3], srcA);
            unsigned a1 = f2tf32(odd ? o : e);
            e = __shfl_sync(0xffffffffu, S[kt][0], srcB);
            o = __shfl_sync(0xffffffffu, S[kt][1], srcB);
            unsigned a2 = f2tf32(odd ? o : e);
            e = __shfl_sync(0xffffffffu, S[kt][2], srcB);
            o = __shfl_sync(0xffffffffu, S[kt][3], srcB);
            unsigned a3 = f2tf32(odd ? o : e);

            #pragma unroll
            for (int dn = 0; dn < 8; dn++) {
                unsigned b0 = Vs[(kt*8 + t4    )*VSTR + dn*8 + gid];
                unsigned b1 = Vs[(kt*8 + t4 + 4)*VSTR + dn*8 + gid];
                mma_tf32(O[dn][0], O[dn][1], O[dn][2], O[dn][3],
                         a0, a1, a2, a3, b0, b1);
            }
        }
    }

    // epilogue: store tf32-rounded bits (O GEMM consumes pre-converted operand)
    float inv0 = 1.f / l0, inv1 = 1.f / l1;
    #pragma unroll
    for (int dn = 0; dn < 8; dn++) {
        int col = h*HDIM + dn*8 + 2*t4;
        float2 r0 = make_float2(__uint_as_float(f2tf32(O[dn][0]*inv0)),
                                __uint_as_float(f2tf32(O[dn][1]*inv0)));
        float2 r1 = make_float2(__uint_as_float(f2tf32(O[dn][2]*inv1)),
                                __uint_as_float(f2tf32(O[dn][3]*inv1)));
        *(float2*)&g_att[((size_t)b*SS + qr0)*DD + col] = r0;
        *(float2*)&g_att[((size_t)b*SS + qr1)*DD + col] = r1;
    }
}

// ---------------- launch ----------------
extern "C" void kernel_launch(void* const* d_in, const int* in_sizes, int n_in,
                              void* d_out, int out_size)
{
    (void)in_sizes; (void)n_in; (void)out_size;
    const float* x  = (const float*)d_in[0];
    const float* Wq = (const float*)d_in[1];
    const float* Wk = (const float*)d_in[2];
    const float* Wv = (const float*)d_in[3];
    const float* Wo = (const float*)d_in[4];
    const float* bo = (const float*)d_in[5];
    const float* Ws = (const float*)d_in[6];
    const float* bs = (const float*)d_in[7];
    float* out = (float*)d_out;

    float *qlin, *klin, *vlin, *q, *qsp, *k, *ksp, *v, *att;
    unsigned *xc, *wqc, *wkc, *wvc, *woc;
    cudaGetSymbolAddress((void**)&qlin, g_qlin);
    cudaGetSymbolAddress((void**)&klin, g_klin);
    cudaGetSymbolAddress((void**)&vlin, g_vlin);
    cudaGetSymbolAddress((void**)&q,    g_q);
    cudaGetSymbolAddress((void**)&qsp,  g_qsp);
    cudaGetSymbolAddress((void**)&k,    g_k);
    cudaGetSymbolAddress((void**)&ksp,  g_ksp);
    cudaGetSymbolAddress((void**)&v,    g_v);
    cudaGetSymbolAddress((void**)&att,  g_att);
    cudaGetSymbolAddress((void**)&xc,   g_xc);
    cudaGetSymbolAddress((void**)&wqc,  g_wqc);
    cudaGetSymbolAddress((void**)&wkc,  g_wkc);
    cudaGetSymbolAddress((void**)&wvc,  g_wvc);
    cudaGetSymbolAddress((void**)&woc,  g_woc);

    const int M = BB*SS;   // 4096

    init_rope_kernel<<<(SS*(HDIM/2) + 255)/256, 256>>>();

    cvt_tf32_kernel<<<(BB*SS*DD/4 + 255)/256, 256>>>(x,  xc,  BB*SS*DD/4);
    cvt_tf32_kernel<<<(DD*DD/4 + 255)/256, 256>>>(Wq, wqc, DD*DD/4);
    cvt_tf32_kernel<<<(HKV*HDIM*DD/4 + 255)/256, 256>>>(Wk, wkc, HKV*HDIM*DD/4);
    cvt_tf32_kernel<<<(HKV*HDIM*DD/4 + 255)/256, 256>>>(Wv, wvc, HKV*HDIM*DD/4);
    cvt_tf32_kernel<<<(DD*DD/4 + 255)/256, 256>>>(Wo, woc, DD*DD/4);

    // fused Q/K/V projections: 16 + 4 + 4 column-blocks
    gemm3<<<dim3(24, M/TBM), 256>>>(xc,
                                    wqc, qlin, 16, DD,
                                    wkc, klin, 4,  HKV*HDIM,
                                    wvc, vlin, 4,  HKV*HDIM,
                                    nullptr, DD);

    rope_sp_kernel<<<(BB*SS*HH  + 255)/256, 256>>>(qlin, nullptr, Ws, bs, q, qsp, nullptr, HH);
    rope_sp_kernel<<<(BB*SS*HKV + 255)/256, 256>>>(klin, vlin,    Ws, bs, k, ksp, v,       HKV);

    attn_mma_kernel<<<dim3(SS/AQT, HH, BB), 256>>>();

    gemm3<<<dim3(16, M/TBM), 256>>>((const unsigned*)att,
                                    woc, out, 16, DD,
                                    nullptr, nullptr, 0, 0,
                                    nullptr, nullptr, 0, 0,
                                    bo, DD);
}

// round 6
// speedup vs baseline: 6.8630x; 1.0207x over previous
#include <cuda_runtime.h>
#include <cuda_bf16.h>
#include <math.h>

#define BB 2
#define SS 2048
#define DD 1024
#define HH 16
#define HKV 4
#define HDIM 64
#define SDIM 16

// ---------------- scratch (device globals; no allocation) ----------------
__device__ float    g_qlin[BB*SS*DD];
__device__ float    g_klin[BB*SS*HKV*HDIM];
__device__ float    g_vlin[BB*SS*HKV*HDIM];
// tf32 bit-pattern buffers (written by rope_sp, consumed by attention MMAs)
__device__ unsigned g_q   [BB*HH*SS*HDIM];
__device__ unsigned g_qsp [BB*HH*SS*SDIM];
__device__ unsigned g_k   [BB*HKV*SS*HDIM];
__device__ unsigned g_ksp [BB*HKV*SS*SDIM];
__device__ unsigned g_v   [BB*HKV*SS*HDIM];
__device__ float    g_att [BB*SS*DD];          // tf32-rounded bits for O GEMM
__device__ float    g_cosT[SS*(HDIM/2)];
__device__ float    g_sinT[SS*(HDIM/2)];
// tf32-preconverted GEMM operands
__device__ unsigned g_xc  [BB*SS*DD];
__device__ unsigned g_wqc [DD*DD];
__device__ unsigned g_wkc [HKV*HDIM*DD];
__device__ unsigned g_wvc [HKV*HDIM*DD];
__device__ unsigned g_woc [DD*DD];

// ---------------- common helpers ----------------
__device__ __forceinline__ unsigned f2tf32(float f) {
    unsigned r;
    asm("cvt.rna.tf32.f32 %0, %1;" : "=r"(r) : "f"(f));
    return r;
}

__device__ __forceinline__ void mma_tf32(float& d0, float& d1, float& d2, float& d3,
                                         unsigned a0, unsigned a1, unsigned a2, unsigned a3,
                                         unsigned b0, unsigned b1) {
    asm volatile(
        "mma.sync.aligned.m16n8k8.row.col.f32.tf32.tf32.f32 "
        "{%0,%1,%2,%3},{%4,%5,%6,%7},{%8,%9},{%0,%1,%2,%3};"
        : "+f"(d0), "+f"(d1), "+f"(d2), "+f"(d3)
        : "r"(a0), "r"(a1), "r"(a2), "r"(a3), "r"(b0), "r"(b1));
}

__device__ __forceinline__ unsigned smem_u32(const void* p) {
    return (unsigned)__cvta_generic_to_shared(p);
}
__device__ __forceinline__ void cp16(unsigned dst, const void* src) {
    asm volatile("cp.async.cg.shared.global [%0], [%1], 16;" :: "r"(dst), "l"(src));
}

// ---------------- tf32 pre-conversion ----------------
__global__ void cvt_tf32_kernel(const float* __restrict__ in,
                                unsigned* __restrict__ out, int n4) {
    int i = blockIdx.x*blockDim.x + threadIdx.x;
    if (i >= n4) return;
    float4 f = ((const float4*)in)[i];
    uint4 u;
    u.x = f2tf32(f.x); u.y = f2tf32(f.y); u.z = f2tf32(f.z); u.w = f2tf32(f.w);
    ((uint4*)out)[i] = u;
}

// ---------------- RoPE table ----------------
__global__ void init_rope_kernel() {
    int idx = blockIdx.x*blockDim.x + threadIdx.x;
    if (idx >= SS*(HDIM/2)) return;
    int s = idx / (HDIM/2), i = idx % (HDIM/2);
    float thf = (float)pow(10000.0, -(double)i / (double)(HDIM/2));
    float ff  = (float)s * thf;
    g_cosT[idx] = (float)cos((double)ff);
    g_sinT[idx] = (float)sin((double)ff);
}

// ================= cp.async-pipelined TF32 GEMM =================
// C[M,N] = A[M,K] @ W[N,K]^T (+bias). block 128x128, 8 warps (2m x 4n),
// warp tile 64x32, BK=16, 3-stage cp.async pipeline. Up to 3 segments.
#define TBM 128
#define TBN 128
#define TBK 16
#define PADK 20
#define STG 3
#define GSMEM (STG*(TBM+TBN)*PADK*4)

__global__ void __launch_bounds__(256) gemm3(
    const unsigned* __restrict__ A,
    const unsigned* __restrict__ W0, float* __restrict__ C0, int nx0, int N0,
    const unsigned* __restrict__ W1, float* __restrict__ C1, int nx1, int N1,
    const unsigned* __restrict__ W2, float* __restrict__ C2, int nx2, int N2,
    const float* __restrict__ bias, int K)
{
    extern __shared__ unsigned sh[];
    unsigned* As = sh;                       // STG * TBM*PADK
    unsigned* Bs = sh + STG*TBM*PADK;        // STG * TBN*PADK

    const int tid = threadIdx.x;
    const int w = tid >> 5, lane = tid & 31;
    const int gid = lane >> 2, t4 = lane & 3;
    const int wm = w & 1, wn = w >> 1;       // 2 x 4 warp grid
    const int row0 = blockIdx.y*TBM;

    const unsigned* Wp; float* Cp; int N, cb;
    int bx = blockIdx.x;
    if (bx < nx0)            { Wp = W0; Cp = C0; N = N0; cb = bx; }
    else if (bx < nx0 + nx1) { Wp = W1; Cp = C1; N = N1; cb = bx - nx0; }
    else                     { Wp = W2; Cp = C2; N = N2; cb = bx - nx0 - nx1; }
    const int col0 = cb*TBN;

    const unsigned* Aptr = A  + (size_t)row0*K;
    const unsigned* Wptr = Wp + (size_t)col0*K;

    // cp.async chunk mapping: 128 rows x 16 cols = 512 chunks of 4; 2 per thread
    const int r0c = tid >> 2, r1c = r0c + 64;
    const int cc  = (tid & 3) << 2;

    const unsigned asA = smem_u32(As);
    const unsigned asB = smem_u32(Bs);

    #pragma unroll
    for (int s = 0; s < STG-1; s++) {
        int k0 = s*TBK;
        cp16(asA + (s*(TBM*PADK) + r0c*PADK + cc)*4, Aptr + (size_t)r0c*K + k0 + cc);
        cp16(asA + (s*(TBM*PADK) + r1c*PADK + cc)*4, Aptr + (size_t)r1c*K + k0 + cc);
        cp16(asB + (s*(TBN*PADK) + r0c*PADK + cc)*4, Wptr + (size_t)r0c*K + k0 + cc);
        cp16(asB + (s*(TBN*PADK) + r1c*PADK + cc)*4, Wptr + (size_t)r1c*K + k0 + cc);
        asm volatile("cp.async.commit_group;");
    }

    float acc[4][4][4];
    #pragma unroll
    for (int mt = 0; mt < 4; mt++)
        #pragma unroll
        for (int nt = 0; nt < 4; nt++)
            #pragma unroll
            for (int j = 0; j < 4; j++) acc[mt][nt][j] = 0.f;

    const int T = K / TBK;
    int st = 0, si = STG - 1;
    for (int t = 0; t < T; t++) {
        asm volatile("cp.async.wait_group 1;" ::: "memory");
        __syncthreads();

        if (t + STG - 1 < T) {
            int k0 = (t + STG - 1)*TBK;
            cp16(asA + (si*(TBM*PADK) + r0c*PADK + cc)*4, Aptr + (size_t)r0c*K + k0 + cc);
            cp16(asA + (si*(TBM*PADK) + r1c*PADK + cc)*4, Aptr + (size_t)r1c*K + k0 + cc);
            cp16(asB + (si*(TBN*PADK) + r0c*PADK + cc)*4, Wptr + (size_t)r0c*K + k0 + cc);
            cp16(asB + (si*(TBN*PADK) + r1c*PADK + cc)*4, Wptr + (size_t)r1c*K + k0 + cc);
        }
        asm volatile("cp.async.commit_group;");

        #pragma unroll
        for (int kk = 0; kk < TBK; kk += 8) {
            unsigned a[4][4];
            #pragma unroll
            for (int mt = 0; mt < 4; mt++) {
                int r = wm*64 + mt*16 + gid;
                a[mt][0] = As[st*(TBM*PADK) + (r    )*PADK + kk + t4];
                a[mt][1] = As[st*(TBM*PADK) + (r + 8)*PADK + kk + t4];
                a[mt][2] = As[st*(TBM*PADK) + (r    )*PADK + kk + t4 + 4];
                a[mt][3] = As[st*(TBM*PADK) + (r + 8)*PADK + kk + t4 + 4];
            }
            #pragma unroll
            for (int nt = 0; nt < 4; nt++) {
                int n0 = wn*32 + nt*8 + gid;
                unsigned b0 = Bs[st*(TBN*PADK) + n0*PADK + kk + t4];
                unsigned b1 = Bs[st*(TBN*PADK) + n0*PADK + kk + t4 + 4];
                #pragma unroll
                for (int mt = 0; mt < 4; mt++)
                    mma_tf32(acc[mt][nt][0], acc[mt][nt][1], acc[mt][nt][2], acc[mt][nt][3],
                             a[mt][0], a[mt][1], a[mt][2], a[mt][3], b0, b1);
            }
        }
        st = (st + 1 == STG) ? 0 : st + 1;
        si = (si + 1 == STG) ? 0 : si + 1;
    }

    #pragma unroll
    for (int mt = 0; mt < 4; mt++) {
        int r = row0 + wm*64 + mt*16 + gid;
        #pragma unroll
        for (int nt = 0; nt < 4; nt++) {
            int c = col0 + wn*32 + nt*8 + 2*t4;
            float bv0 = bias ? bias[c]   : 0.f;
            float bv1 = bias ? bias[c+1] : 0.f;
            *(float2*)&Cp[(size_t)r*N + c]     = make_float2(acc[mt][nt][0]+bv0, acc[mt][nt][1]+bv1);
            *(float2*)&Cp[(size_t)(r+8)*N + c] = make_float2(acc[mt][nt][2]+bv0, acc[mt][nt][3]+bv1);
        }
    }
}

// ---------------- RoPE + sparsity projection; emits tf32 BIT PATTERNS ----------------
__global__ void rope_sp_kernel(const float* __restrict__ lin,
                               const float* __restrict__ vlin,
                               const float* __restrict__ Ws,
                               const float* __restrict__ bs,
                               unsigned* __restrict__ obuf,
                               unsigned* __restrict__ spbuf,
                               unsigned* __restrict__ vbuf,
                               int NH)
{
    __shared__ float WsS[SDIM*HDIM];
    __shared__ float bsS[SDIM];
    for (int i = threadIdx.x; i < SDIM*HDIM; i += blockDim.x) WsS[i] = Ws[i];
    if (threadIdx.x < SDIM) bsS[threadIdx.x] = bs[threadIdx.x];
    __syncthreads();

    int idx = blockIdx.x*blockDim.x + threadIdx.x;
    int total = BB*SS*NH;
    if (idx >= total) return;
    int h = idx % NH;
    int s = (idx / NH) % SS;
    int b = idx / (NH*SS);

    const float4* src = (const float4*)(lin + ((size_t)(b*SS + s)*NH + h)*HDIM);
    float v[HDIM];
    #pragma unroll
    for (int t = 0; t < HDIM/4; t++) ((float4*)v)[t] = src[t];

    #pragma unroll
    for (int i = 0; i < HDIM/2; i++) {
        float c  = g_cosT[s*(HDIM/2)+i];
        float sn = g_sinT[s*(HDIM/2)+i];
        float a  = v[i], bpart = v[i+HDIM/2];
        v[i]        = a*c - bpart*sn;
        v[i+HDIM/2] = bpart*c + a*sn;
    }

    unsigned* dst = obuf + (((size_t)b*NH + h)*SS + s)*HDIM;
    #pragma unroll
    for (int d = 0; d < HDIM; d += 4) {
        uint4 u;
        u.x = f2tf32(v[d]);   u.y = f2tf32(v[d+1]);
        u.z = f2tf32(v[d+2]); u.w = f2tf32(v[d+3]);
        *(uint4*)&dst[d] = u;
    }

    unsigned* spd = spbuf + (((size_t)b*NH + h)*SS + s)*SDIM;
    #pragma unroll
    for (int j = 0; j < SDIM; j++) {
        float acc = bsS[j];
        #pragma unroll
        for (int d = 0; d < HDIM; d++) acc += WsS[j*HDIM + d] * v[d];
        spd[j] = f2tf32(acc);
    }

    if (vlin) {
        const float4* vsrc = (const float4*)(vlin + ((size_t)(b*SS + s)*NH + h)*HDIM);
        unsigned* vdst = vbuf + (((size_t)b*NH + h)*SS + s)*HDIM;
        #pragma unroll
        for (int t = 0; t < HDIM/4; t++) {
            float4 f = vsrc[t];
            uint4 u;
            u.x = f2tf32(f.x); u.y = f2tf32(f.y); u.z = f2tf32(f.z); u.w = f2tf32(f.w);
            *(uint4*)&vdst[t*4] = u;
        }
    }
}

// ================= TF32 tensor-core attention (operands pre-converted) =================
#define AQT 128
#define AKT 64
#define KSTR 68
#define VSTR 72
#define SSTR 20

__global__ void __launch_bounds__(256, 1) attn_mma_kernel()
{
    __shared__ unsigned Ks  [AKT*KSTR];
    __shared__ unsigned Vs  [AKT*VSTR];
    __shared__ unsigned Ksps[AKT*SSTR];

    const int b = blockIdx.z, h = blockIdx.y;
    const int hkv = h >> 2;
    const int q0 = (gridDim.x - 1 - blockIdx.x) * AQT;
    const int tid = threadIdx.x;
    const int w = tid >> 5, lane = tid & 31;
    const int gid = lane >> 2, t4 = lane & 3;

    const int q0w = q0 + w*16;
    const int qr0 = q0w + gid;
    const int qr1 = qr0 + 8;

    const unsigned* qbase = g_q   + ((size_t)b*HH  + h  )*SS*HDIM;
    const unsigned* qspb  = g_qsp + ((size_t)b*HH  + h  )*SS*SDIM;
    const unsigned* kptr  = g_k   + ((size_t)b*HKV + hkv)*SS*HDIM;
    const unsigned* kspp  = g_ksp + ((size_t)b*HKV + hkv)*SS*SDIM;
    const unsigned* vptr  = g_v   + ((size_t)b*HKV + hkv)*SS*HDIM;

    unsigned qa[8][4], qsa[2][4];
    #pragma unroll
    for (int kt = 0; kt < 8; kt++) {
        qa[kt][0] = qbase[(size_t)qr0*HDIM + kt*8 + t4];
        qa[kt][1] = qbase[(size_t)qr1*HDIM + kt*8 + t4];
        qa[kt][2] = qbase[(size_t)qr0*HDIM + kt*8 + t4 + 4];
        qa[kt][3] = qbase[(size_t)qr1*HDIM + kt*8 + t4 + 4];
    }
    #pragma unroll
    for (int kt = 0; kt < 2; kt++) {
        qsa[kt][0] = qspb[(size_t)qr0*SDIM + kt*8 + t4];
        qsa[kt][1] = qspb[(size_t)qr1*SDIM + kt*8 + t4];
        qsa[kt][2] = qspb[(size_t)qr0*SDIM + kt*8 + t4 + 4];
        qsa[kt][3] = qspb[(size_t)qr1*SDIM + kt*8 + t4 + 4];
    }

    float m0 = -1e30f, m1 = -1e30f, l0 = 0.f, l1 = 0.f;
    float O[8][4];
    #pragma unroll
    for (int dn = 0; dn < 8; dn++)
        #pragma unroll
        for (int j = 0; j < 4; j++) O[dn][j] = 0.f;

    const int srcA = (lane & ~3) | (t4 >> 1);
    const int srcB = srcA + 2;
    const bool odd = (t4 & 1);

    for (int kb = 0; kb < q0 + AQT; kb += AKT) {
        __syncthreads();
        #pragma unroll
        for (int t = 0; t < 16; t++) {
            int i = tid + t*256;
            int key = i >> 6, d = i & 63;
            Ks[key*KSTR + d] = kptr[(size_t)kb*HDIM + i];
            Vs[key*VSTR + d] = vptr[(size_t)kb*HDIM + i];
        }
        #pragma unroll
        for (int t = 0; t < 4; t++) {
            int i = tid + t*256;
            Ksps[(i >> 4)*SSTR + (i & 15)] = kspp[(size_t)kb*SDIM + i];
        }
        __syncthreads();

        if (kb > q0w + 15) continue;

        float S[8][4], SP[8][4];
        #pragma unroll
        for (int nt = 0; nt < 8; nt++)
            #pragma unroll
            for (int j = 0; j < 4; j++) { S[nt][j] = 0.f; SP[nt][j] = 0.f; }

        #pragma unroll
        for (int kt = 0; kt < 8; kt++) {
            #pragma unroll
            for (int nt = 0; nt < 8; nt++) {
                unsigned b0 = Ks[(nt*8 + gid)*KSTR + kt*8 + t4];
                unsigned b1 = Ks[(nt*8 + gid)*KSTR + kt*8 + t4 + 4];
                mma_tf32(S[nt][0], S[nt][1], S[nt][2], S[nt][3],
                         qa[kt][0], qa[kt][1], qa[kt][2], qa[kt][3], b0, b1);
            }
        }
        #pragma unroll
        for (int kt = 0; kt < 2; kt++) {
            #pragma unroll
            for (int nt = 0; nt < 8; nt++) {
                unsigned b0 = Ksps[(nt*8 + gid)*SSTR + kt*8 + t4];
                unsigned b1 = Ksps[(nt*8 + gid)*SSTR + kt*8 + t4 + 4];
                mma_tf32(SP[nt][0], SP[nt][1], SP[nt][2], SP[nt][3],
                         qsa[kt][0], qsa[kt][1], qsa[kt][2], qsa[kt][3], b0, b1);
            }
        }

        #pragma unroll
        for (int nt = 0; nt < 8; nt++) {
            #pragma unroll
            for (int j = 0; j < 4; j++) {
                int key = kb + nt*8 + 2*t4 + (j & 1);
                int row = (j >= 2) ? qr1 : qr0;
                float g = 1.f / (1.f + __expf(-SP[nt][j] * 0.25f));
                float lg = S[nt][j] * 0.125f * g;
                S[nt][j] = (key > row) ? -1e30f : lg;
            }
        }

        float mx0 = -1e30f, mx1 = -1e30f;
        #pragma unroll
        for (int nt = 0; nt < 8; nt++) {
            mx0 = fmaxf(mx0, fmaxf(S[nt][0], S[nt][1]));
            mx1 = fmaxf(mx1, fmaxf(S[nt][2], S[nt][3]));
        }
        #pragma unroll
        for (int off = 1; off < 4; off <<= 1) {
            mx0 = fmaxf(mx0, __shfl_xor_sync(0xffffffffu, mx0, off));
            mx1 = fmaxf(mx1, __shfl_xor_sync(0xffffffffu, mx1, off));
        }
        float mn0 = fmaxf(m0, mx0), mn1 = fmaxf(m1, mx1);
        float sc0 = __expf(m0 - mn0), sc1 = __expf(m1 - mn1);
        float sum0 = 0.f, sum1 = 0.f;
        #pragma unroll
        for (int nt = 0; nt < 8; nt++) {
            S[nt][0] = __expf(S[nt][0] - mn0); sum0 += S[nt][0];
            S[nt][1] = __expf(S[nt][1] - mn0); sum0 += S[nt][1];
            S[nt][2] = __expf(S[nt][2] - mn1); sum1 += S[nt][2];
            S[nt][3] = __expf(S[nt][3] - mn1); sum1 += S[nt][3];
        }
        #pragma unroll
        for (int off = 1; off < 4; off <<= 1) {
            sum0 += __shfl_xor_sync(0xffffffffu, sum0, off);
            sum1 += __shfl_xor_sync(0xffffffffu, sum1, off);
        }
        l0 = l0*sc0 + sum0; l1 = l1*sc1 + sum1;
        m0 = mn0; m1 = mn1;
        #pragma unroll
        for (int dn = 0; dn < 8; dn++) {
            O[dn][0] *= sc0; O[dn][1] *= sc0;
            O[dn][2] *= sc1; O[dn][3] *= sc1;
        }

        #pragma unroll
        for (int kt = 0; kt < 8; kt++) {
            float e, o;
            e = __shfl_sync(0xffffffffu, S[kt][0], srcA);
            o = __shfl_sync(0xffffffffu, S[kt][1], srcA);
            unsigned a0 = f2tf32(odd ? o : e);
            e = __shfl_sync(0xffffffffu, S[kt][2], srcA);
            o = __shfl_sync(0xffffffffu, S[kt][3], srcA);
            unsigned a1 = f2tf32(odd ? o : e);
            e = __shfl_sync(0xffffffffu, S[kt][0], srcB);
            o = __shfl_sync(0xffffffffu, S[kt][1], srcB);
            unsigned a2 = f2tf32(odd ? o : e);
            e = __shfl_sync(0xffffffffu, S[kt][2], srcB);
            o = __shfl_sync(0xffffffffu, S[kt][3], srcB);
            unsigned a3 = f2tf32(odd ? o : e);

            #pragma unroll
            for (int dn = 0; dn < 8; dn++) {
                unsigned b0 = Vs[(kt*8 + t4    )*VSTR + dn*8 + gid];
                unsigned b1 = Vs[(kt*8 + t4 + 4)*VSTR + dn*8 + gid];
                mma_tf32(O[dn][0], O[dn][1], O[dn][2], O[dn][3],
                         a0, a1, a2, a3, b0, b1);
            }
        }
    }

    float inv0 = 1.f / l0, inv1 = 1.f / l1;
    #pragma unroll
    for (int dn = 0; dn < 8; dn++) {
        int col = h*HDIM + dn*8 + 2*t4;
        float2 r0 = make_float2(__uint_as_float(f2tf32(O[dn][0]*inv0)),
                                __uint_as_float(f2tf32(O[dn][1]*inv0)));
        float2 r1 = make_float2(__uint_as_float(f2tf32(O[dn][2]*inv1)),
                                __uint_as_float(f2tf32(O[dn][3]*inv1)));
        *(float2*)&g_att[((size_t)b*SS + qr0)*DD + col] = r0;
        *(float2*)&g_att[((size_t)b*SS + qr1)*DD + col] = r1;
    }
}

// ---------------- launch ----------------
extern "C" void kernel_launch(void* const* d_in, const int* in_sizes, int n_in,
                              void* d_out, int out_size)
{
    (void)in_sizes; (void)n_in; (void)out_size;
    const float* x  = (const float*)d_in[0];
    const float* Wq = (const float*)d_in[1];
    const float* Wk = (const float*)d_in[2];
    const float* Wv = (const float*)d_in[3];
    const float* Wo = (const float*)d_in[4];
    const float* bo = (const float*)d_in[5];
    const float* Ws = (const float*)d_in[6];
    const float* bs = (const float*)d_in[7];
    float* out = (float*)d_out;

    float *qlin, *klin, *vlin, *att;
    unsigned *q, *qsp, *k, *ksp, *v;
    unsigned *xc, *wqc, *wkc, *wvc, *woc;
    cudaGetSymbolAddress((void**)&qlin, g_qlin);
    cudaGetSymbolAddress((void**)&klin, g_klin);
    cudaGetSymbolAddress((void**)&vlin, g_vlin);
    cudaGetSymbolAddress((void**)&q,    g_q);
    cudaGetSymbolAddress((void**)&qsp,  g_qsp);
    cudaGetSymbolAddress((void**)&k,    g_k);
    cudaGetSymbolAddress((void**)&ksp,  g_ksp);
    cudaGetSymbolAddress((void**)&v,    g_v);
    cudaGetSymbolAddress((void**)&att,  g_att);
    cudaGetSymbolAddress((void**)&xc,   g_xc);
    cudaGetSymbolAddress((void**)&wqc,  g_wqc);
    cudaGetSymbolAddress((void**)&wkc,  g_wkc);
    cudaGetSymbolAddress((void**)&wvc,  g_wvc);
    cudaGetSymbolAddress((void**)&woc,  g_woc);

    const int M = BB*SS;   // 4096

    static bool attr_set = false;
    if (!attr_set) {
        cudaFuncSetAttribute(gemm3, cudaFuncAttributeMaxDynamicSharedMemorySize, GSMEM);
        attr_set = true;
    }

    init_rope_kernel<<<(SS*(HDIM/2) + 255)/256, 256>>>();

    cvt_tf32_kernel<<<(BB*SS*DD/4 + 255)/256, 256>>>(x,  xc,  BB*SS*DD/4);
    cvt_tf32_kernel<<<(DD*DD/4 + 255)/256, 256>>>(Wq, wqc, DD*DD/4);
    cvt_tf32_kernel<<<(HKV*HDIM*DD/4 + 255)/256, 256>>>(Wk, wkc, HKV*HDIM*DD/4);
    cvt_tf32_kernel<<<(HKV*HDIM*DD/4 + 255)/256, 256>>>(Wv, wvc, HKV*HDIM*DD/4);
    cvt_tf32_kernel<<<(DD*DD/4 + 255)/256, 256>>>(Wo, woc, DD*DD/4);

    // fused Q/K/V projections: 8 + 2 + 2 column-blocks of 128
    gemm3<<<dim3(12, M/TBM), 256, GSMEM>>>(xc,
                                    wqc, qlin, 8, DD,
                                    wkc, klin, 2, HKV*HDIM,
                                    wvc, vlin, 2, HKV*HDIM,
                                    nullptr, DD);

    rope_sp_kernel<<<(BB*SS*HH  + 255)/256, 256>>>(qlin, nullptr, Ws, bs, q, qsp, nullptr, HH);
    rope_sp_kernel<<<(BB*SS*HKV + 255)/256, 256>>>(klin, vlin,    Ws, bs, k, ksp, v,       HKV);

    attn_mma_kernel<<<dim3(SS/AQT, HH, BB), 256>>>();

    gemm3<<<dim3(8, M/TBM), 256, GSMEM>>>((const unsigned*)att,
                                    woc, out, 8, DD,
                                    nullptr, nullptr, 0, 0,
                                    nullptr, nullptr, 0, 0,
                                    bo, DD);
}

// round 7
// speedup vs baseline: 7.2173x; 1.0516x over previous
#include <cuda_runtime.h>
#include <cuda_bf16.h>
#include <math.h>

#define BB 2
#define SS 2048
#define DD 1024
#define HH 16
#define HKV 4
#define HDIM 64
#define SDIM 16

// ---------------- scratch (device globals; no allocation) ----------------
__device__ float    g_qlin[BB*SS*DD];
__device__ float    g_klin[BB*SS*HKV*HDIM];
__device__ float    g_vlin[BB*SS*HKV*HDIM];
__device__ unsigned g_q   [BB*HH*SS*HDIM];
__device__ unsigned g_qsp [BB*HH*SS*SDIM];
__device__ unsigned g_k   [BB*HKV*SS*HDIM];
__device__ unsigned g_ksp [BB*HKV*SS*SDIM];
__device__ unsigned g_v   [BB*HKV*SS*HDIM];
__device__ float    g_att [BB*SS*DD];
__device__ float    g_cosT[SS*(HDIM/2)];
__device__ float    g_sinT[SS*(HDIM/2)];
__device__ unsigned g_xc  [BB*SS*DD];
__device__ unsigned g_wqc [DD*DD];
__device__ unsigned g_wkc [HKV*HDIM*DD];
__device__ unsigned g_wvc [HKV*HDIM*DD];
__device__ unsigned g_woc [DD*DD];

// ---------------- common helpers ----------------
__device__ __forceinline__ unsigned f2tf32(float f) {
    unsigned r;
    asm("cvt.rna.tf32.f32 %0, %1;" : "=r"(r) : "f"(f));
    return r;
}

__device__ __forceinline__ void mma_tf32(float& d0, float& d1, float& d2, float& d3,
                                         unsigned a0, unsigned a1, unsigned a2, unsigned a3,
                                         unsigned b0, unsigned b1) {
    asm volatile(
        "mma.sync.aligned.m16n8k8.row.col.f32.tf32.tf32.f32 "
        "{%0,%1,%2,%3},{%4,%5,%6,%7},{%8,%9},{%0,%1,%2,%3};"
        : "+f"(d0), "+f"(d1), "+f"(d2), "+f"(d3)
        : "r"(a0), "r"(a1), "r"(a2), "r"(a3), "r"(b0), "r"(b1));
}

__device__ __forceinline__ unsigned smem_u32(const void* p) {
    return (unsigned)__cvta_generic_to_shared(p);
}
__device__ __forceinline__ void cp16(unsigned dst, const void* src) {
    asm volatile("cp.async.cg.shared.global [%0], [%1], 16;" :: "r"(dst), "l"(src));
}
__device__ __forceinline__ uint4 ldsm4(unsigned addr) {
    uint4 r;
    asm volatile("ldmatrix.sync.aligned.m8n8.x4.shared.b16 {%0,%1,%2,%3}, [%4];"
                 : "=r"(r.x), "=r"(r.y), "=r"(r.z), "=r"(r.w) : "r"(addr));
    return r;
}

// ---------------- tf32 pre-conversion ----------------
__global__ void cvt_tf32_kernel(const float* __restrict__ in,
                                unsigned* __restrict__ out, int n4) {
    int i = blockIdx.x*blockDim.x + threadIdx.x;
    if (i >= n4) return;
    float4 f = ((const float4*)in)[i];
    uint4 u;
    u.x = f2tf32(f.x); u.y = f2tf32(f.y); u.z = f2tf32(f.z); u.w = f2tf32(f.w);
    ((uint4*)out)[i] = u;
}

// ---------------- RoPE table ----------------
__global__ void init_rope_kernel() {
    int idx = blockIdx.x*blockDim.x + threadIdx.x;
    if (idx >= SS*(HDIM/2)) return;
    int s = idx / (HDIM/2), i = idx % (HDIM/2);
    float thf = (float)pow(10000.0, -(double)i / (double)(HDIM/2));
    float ff  = (float)s * thf;
    g_cosT[idx] = (float)cos((double)ff);
    g_sinT[idx] = (float)sin((double)ff);
}

// ================= cp.async + ldmatrix TF32 GEMM =================
#define TBM 128
#define TBN 128
#define TBK 16
#define PADK 20
#define STG 3
#define GSMEM (STG*(TBM+TBN)*PADK*4)

__global__ void __launch_bounds__(256) gemm3(
    const unsigned* __restrict__ A,
    const unsigned* __restrict__ W0, float* __restrict__ C0, int nx0, int N0,
    const unsigned* __restrict__ W1, float* __restrict__ C1, int nx1, int N1,
    const unsigned* __restrict__ W2, float* __restrict__ C2, int nx2, int N2,
    const float* __restrict__ bias, int K)
{
    extern __shared__ unsigned sh[];
    unsigned* Asm = sh;
    unsigned* Bsm = sh + STG*TBM*PADK;

    const int tid = threadIdx.x;
    const int w = tid >> 5, lane = tid & 31;
    const int gid = lane >> 2, t4 = lane & 3;
    const int wm = w & 1, wn = w >> 1;
    const int row0 = blockIdx.y*TBM;

    const unsigned* Wp; float* Cp; int N, cb;
    int bx = blockIdx.x;
    if (bx < nx0)            { Wp = W0; Cp = C0; N = N0; cb = bx; }
    else if (bx < nx0 + nx1) { Wp = W1; Cp = C1; N = N1; cb = bx - nx0; }
    else                     { Wp = W2; Cp = C2; N = N2; cb = bx - nx0 - nx1; }
    const int col0 = cb*TBN;

    const unsigned* Aptr = A  + (size_t)row0*K;
    const unsigned* Wptr = Wp + (size_t)col0*K;

    const int r0c = tid >> 2, r1c = r0c + 64;
    const int cc  = (tid & 3) << 2;

    const unsigned asA = smem_u32(Asm);
    const unsigned asB = smem_u32(Bsm);

    // ldmatrix per-lane element offsets (within one stage)
    int aoff[4], boff[2];
    #pragma unroll
    for (int mt = 0; mt < 4; mt++)
        aoff[mt] = (wm*64 + mt*16 + (lane & 15))*PADK + ((lane >> 4) << 2);
    #pragma unroll
    for (int np = 0; np < 2; np++)
        boff[np] = (wn*32 + np*16 + (lane & 15))*PADK + ((lane >> 4) << 2);

    #pragma unroll
    for (int s = 0; s < STG-1; s++) {
        int k0 = s*TBK;
        cp16(asA + (s*(TBM*PADK) + r0c*PADK + cc)*4, Aptr + (size_t)r0c*K + k0 + cc);
        cp16(asA + (s*(TBM*PADK) + r1c*PADK + cc)*4, Aptr + (size_t)r1c*K + k0 + cc);
        cp16(asB + (s*(TBN*PADK) + r0c*PADK + cc)*4, Wptr + (size_t)r0c*K + k0 + cc);
        cp16(asB + (s*(TBN*PADK) + r1c*PADK + cc)*4, Wptr + (size_t)r1c*K + k0 + cc);
        asm volatile("cp.async.commit_group;");
    }

    float acc[4][4][4];
    #pragma unroll
    for (int mt = 0; mt < 4; mt++)
        #pragma unroll
        for (int nt = 0; nt < 4; nt++)
            #pragma unroll
            for (int j = 0; j < 4; j++) acc[mt][nt][j] = 0.f;

    const int T = K / TBK;
    int st = 0, si = STG - 1;
    for (int t = 0; t < T; t++) {
        asm volatile("cp.async.wait_group 1;" ::: "memory");
        __syncthreads();

        if (t + STG - 1 < T) {
            int k0 = (t + STG - 1)*TBK;
            cp16(asA + (si*(TBM*PADK) + r0c*PADK + cc)*4, Aptr + (size_t)r0c*K + k0 + cc);
            cp16(asA + (si*(TBM*PADK) + r1c*PADK + cc)*4, Aptr + (size_t)r1c*K + k0 + cc);
            cp16(asB + (si*(TBN*PADK) + r0c*PADK + cc)*4, Wptr + (size_t)r0c*K + k0 + cc);
            cp16(asB + (si*(TBN*PADK) + r1c*PADK + cc)*4, Wptr + (size_t)r1c*K + k0 + cc);
        }
        asm volatile("cp.async.commit_group;");

        const unsigned aStg = asA + (st*(TBM*PADK))*4;
        const unsigned bStg = asB + (st*(TBN*PADK))*4;
        #pragma unroll
        for (int kk = 0; kk < TBK; kk += 8) {
            uint4 av[4], bv[2];
            #pragma unroll
            for (int mt = 0; mt < 4; mt++) av[mt] = ldsm4(aStg + (aoff[mt] + kk)*4);
            #pragma unroll
            for (int np = 0; np < 2; np++) bv[np] = ldsm4(bStg + (boff[np] + kk)*4);
            #pragma unroll
            for (int np = 0; np < 2; np++) {
                #pragma unroll
                for (int mt = 0; mt < 4; mt++) {
                    mma_tf32(acc[mt][2*np  ][0], acc[mt][2*np  ][1], acc[mt][2*np  ][2], acc[mt][2*np  ][3],
                             av[mt].x, av[mt].y, av[mt].z, av[mt].w, bv[np].x, bv[np].z);
                    mma_tf32(acc[mt][2*np+1][0], acc[mt][2*np+1][1], acc[mt][2*np+1][2], acc[mt][2*np+1][3],
                             av[mt].x, av[mt].y, av[mt].z, av[mt].w, bv[np].y, bv[np].w);
                }
            }
        }
        st = (st + 1 == STG) ? 0 : st + 1;
        si = (si + 1 == STG) ? 0 : si + 1;
    }

    #pragma unroll
    for (int mt = 0; mt < 4; mt++) {
        int r = row0 + wm*64 + mt*16 + gid;
        #pragma unroll
        for (int nt = 0; nt < 4; nt++) {
            int c = col0 + wn*32 + nt*8 + 2*t4;
            float bv0 = bias ? bias[c]   : 0.f;
            float bv1 = bias ? bias[c+1] : 0.f;
            *(float2*)&Cp[(size_t)r*N + c]     = make_float2(acc[mt][nt][0]+bv0, acc[mt][nt][1]+bv1);
            *(float2*)&Cp[(size_t)(r+8)*N + c] = make_float2(acc[mt][nt][2]+bv0, acc[mt][nt][3]+bv1);
        }
    }
}

// ---------------- RoPE + sparsity projection; emits tf32 BIT PATTERNS ----------------
__global__ void rope_sp_kernel(const float* __restrict__ lin,
                               const float* __restrict__ vlin,
                               const float* __restrict__ Ws,
                               const float* __restrict__ bs,
                               unsigned* __restrict__ obuf,
                               unsigned* __restrict__ spbuf,
                               unsigned* __restrict__ vbuf,
                               int NH)
{
    __shared__ float WsS[SDIM*HDIM];
    __shared__ float bsS[SDIM];
    for (int i = threadIdx.x; i < SDIM*HDIM; i += blockDim.x) WsS[i] = Ws[i];
    if (threadIdx.x < SDIM) bsS[threadIdx.x] = bs[threadIdx.x];
    __syncthreads();

    int idx = blockIdx.x*blockDim.x + threadIdx.x;
    int total = BB*SS*NH;
    if (idx >= total) return;
    int h = idx % NH;
    int s = (idx / NH) % SS;
    int b = idx / (NH*SS);

    const float4* src = (const float4*)(lin + ((size_t)(b*SS + s)*NH + h)*HDIM);
    float v[HDIM];
    #pragma unroll
    for (int t = 0; t < HDIM/4; t++) ((float4*)v)[t] = src[t];

    #pragma unroll
    for (int i = 0; i < HDIM/2; i++) {
        float c  = g_cosT[s*(HDIM/2)+i];
        float sn = g_sinT[s*(HDIM/2)+i];
        float a  = v[i], bpart = v[i+HDIM/2];
        v[i]        = a*c - bpart*sn;
        v[i+HDIM/2] = bpart*c + a*sn;
    }

    unsigned* dst = obuf + (((size_t)b*NH + h)*SS + s)*HDIM;
    #pragma unroll
    for (int d = 0; d < HDIM; d += 4) {
        uint4 u;
        u.x = f2tf32(v[d]);   u.y = f2tf32(v[d+1]);
        u.z = f2tf32(v[d+2]); u.w = f2tf32(v[d+3]);
        *(uint4*)&dst[d] = u;
    }

    unsigned* spd = spbuf + (((size_t)b*NH + h)*SS + s)*SDIM;
    #pragma unroll
    for (int j = 0; j < SDIM; j++) {
        float acc = bsS[j];
        #pragma unroll
        for (int d = 0; d < HDIM; d++) acc += WsS[j*HDIM + d] * v[d];
        spd[j] = f2tf32(acc);
    }

    if (vlin) {
        const float4* vsrc = (const float4*)(vlin + ((size_t)(b*SS + s)*NH + h)*HDIM);
        unsigned* vdst = vbuf + (((size_t)b*NH + h)*SS + s)*HDIM;
        #pragma unroll
        for (int t = 0; t < HDIM/4; t++) {
            float4 f = vsrc[t];
            uint4 u;
            u.x = f2tf32(f.x); u.y = f2tf32(f.y); u.z = f2tf32(f.z); u.w = f2tf32(f.w);
            *(uint4*)&vdst[t*4] = u;
        }
    }
}

// ================= TF32 attention, cp.async double-buffered tiles =================
#define AQT 128
#define AKT 64
#define KSTR 68
#define VSTR 72
#define SSTR 20
#define KBUF (AKT*KSTR)
#define VBUF (AKT*VSTR)
#define SBUF (AKT*SSTR)
#define ABUF (KBUF+VBUF+SBUF)          // u32 per buffer
#define ASMEM (2*ABUF*4)               // bytes

__global__ void __launch_bounds__(256, 1) attn_mma_kernel()
{
    extern __shared__ unsigned ash[];

    const int b = blockIdx.z, h = blockIdx.y;
    const int hkv = h >> 2;
    const int q0 = (gridDim.x - 1 - blockIdx.x) * AQT;
    const int tid = threadIdx.x;
    const int w = tid >> 5, lane = tid & 31;
    const int gid = lane >> 2, t4 = lane & 3;

    const int q0w = q0 + w*16;
    const int qr0 = q0w + gid;
    const int qr1 = qr0 + 8;

    const unsigned* qbase = g_q   + ((size_t)b*HH  + h  )*SS*HDIM;
    const unsigned* qspb  = g_qsp + ((size_t)b*HH  + h  )*SS*SDIM;
    const unsigned* kptr  = g_k   + ((size_t)b*HKV + hkv)*SS*HDIM;
    const unsigned* kspp  = g_ksp + ((size_t)b*HKV + hkv)*SS*SDIM;
    const unsigned* vptr  = g_v   + ((size_t)b*HKV + hkv)*SS*HDIM;

    const unsigned shbase = smem_u32(ash);

    unsigned qa[8][4], qsa[2][4];
    #pragma unroll
    for (int kt = 0; kt < 8; kt++) {
        qa[kt][0] = qbase[(size_t)qr0*HDIM + kt*8 + t4];
        qa[kt][1] = qbase[(size_t)qr1*HDIM + kt*8 + t4];
        qa[kt][2] = qbase[(size_t)qr0*HDIM + kt*8 + t4 + 4];
        qa[kt][3] = qbase[(size_t)qr1*HDIM + kt*8 + t4 + 4];
    }
    #pragma unroll
    for (int kt = 0; kt < 2; kt++) {
        qsa[kt][0] = qspb[(size_t)qr0*SDIM + kt*8 + t4];
        qsa[kt][1] = qspb[(size_t)qr1*SDIM + kt*8 + t4];
        qsa[kt][2] = qspb[(size_t)qr0*SDIM + kt*8 + t4 + 4];
        qsa[kt][3] = qspb[(size_t)qr1*SDIM + kt*8 + t4 + 4];
    }

    float m0 = -1e30f, m1 = -1e30f, l0 = 0.f, l1 = 0.f;
    float O[8][4];
    #pragma unroll
    for (int dn = 0; dn < 8; dn++)
        #pragma unroll
        for (int j = 0; j < 4; j++) O[dn][j] = 0.f;

    const int srcA = (lane & ~3) | (t4 >> 1);
    const int srcB = srcA + 2;
    const bool odd = (t4 & 1);

    // tile-load lambda (cp.async): K 4 chunks, V 4 chunks, Ksp 1 chunk per thread
    auto issue_tile = [&](int kb, int buf) {
        unsigned base = shbase + buf*ABUF*4;
        #pragma unroll
        for (int c = 0; c < 4; c++) {
            int i = tid + c*256;                // chunk id 0..1023
            int key = i >> 4, d = (i & 15) << 2;
            cp16(base + (key*KSTR + d)*4,          kptr + (size_t)(kb+key)*HDIM + d);
            cp16(base + (KBUF + key*VSTR + d)*4,   vptr + (size_t)(kb+key)*HDIM + d);
        }
        {
            int key = tid >> 2, j = (tid & 3) << 2;   // 256 chunks
            cp16(base + (KBUF + VBUF + key*SSTR + j)*4, kspp + (size_t)(kb+key)*SDIM + j);
        }
    };

    const int nTiles = (q0 + AQT) / AKT;
    issue_tile(0, 0);
    asm volatile("cp.async.commit_group;");

    for (int t = 0; t < nTiles; t++) {
        const int kb = t*AKT;
        const int buf = t & 1;
        __syncthreads();                           // prior compute done; safe to overwrite buf^1
        if (t + 1 < nTiles) issue_tile(kb + AKT, buf ^ 1);
        asm volatile("cp.async.commit_group;");
        asm volatile("cp.async.wait_group 1;" ::: "memory");
        __syncthreads();

        if (kb > q0w + 15) continue;               // still hits top-of-loop sync next iter

        const unsigned* Ks   = ash + buf*ABUF;
        const unsigned* Vs   = Ks + KBUF;
        const unsigned* Ksps = Ks + KBUF + VBUF;

        float S[8][4], SP[8][4];
        #pragma unroll
        for (int nt = 0; nt < 8; nt++)
            #pragma unroll
            for (int j = 0; j < 4; j++) { S[nt][j] = 0.f; SP[nt][j] = 0.f; }

        #pragma unroll
        for (int kt = 0; kt < 8; kt++) {
            #pragma unroll
            for (int nt = 0; nt < 8; nt++) {
                unsigned b0 = Ks[(nt*8 + gid)*KSTR + kt*8 + t4];
                unsigned b1 = Ks[(nt*8 + gid)*KSTR + kt*8 + t4 + 4];
                mma_tf32(S[nt][0], S[nt][1], S[nt][2], S[nt][3],
                         qa[kt][0], qa[kt][1], qa[kt][2], qa[kt][3], b0, b1);
            }
        }
        #pragma unroll
        for (int kt = 0; kt < 2; kt++) {
            #pragma unroll
            for (int nt = 0; nt < 8; nt++) {
                unsigned b0 = Ksps[(nt*8 + gid)*SSTR + kt*8 + t4];
                unsigned b1 = Ksps[(nt*8 + gid)*SSTR + kt*8 + t4 + 4];
                mma_tf32(SP[nt][0], SP[nt][1], SP[nt][2], SP[nt][3],
                         qsa[kt][0], qsa[kt][1], qsa[kt][2], qsa[kt][3], b0, b1);
            }
        }

        #pragma unroll
        for (int nt = 0; nt < 8; nt++) {
            #pragma unroll
            for (int j = 0; j < 4; j++) {
                int key = kb + nt*8 + 2*t4 + (j & 1);
                int row = (j >= 2) ? qr1 : qr0;
                float g = 1.f / (1.f + __expf(-SP[nt][j] * 0.25f));
                float lg = S[nt][j] * 0.125f * g;
                S[nt][j] = (key > row) ? -1e30f : lg;
            }
        }

        float mx0 = -1e30f, mx1 = -1e30f;
        #pragma unroll
        for (int nt = 0; nt < 8; nt++) {
            mx0 = fmaxf(mx0, fmaxf(S[nt][0], S[nt][1]));
            mx1 = fmaxf(mx1, fmaxf(S[nt][2], S[nt][3]));
        }
        #pragma unroll
        for (int off = 1; off < 4; off <<= 1) {
            mx0 = fmaxf(mx0, __shfl_xor_sync(0xffffffffu, mx0, off));
            mx1 = fmaxf(mx1, __shfl_xor_sync(0xffffffffu, mx1, off));
        }
        float mn0 = fmaxf(m0, mx0), mn1 = fmaxf(m1, mx1);
        float sc0 = __expf(m0 - mn0), sc1 = __expf(m1 - mn1);
        float sum0 = 0.f, sum1 = 0.f;
        #pragma unroll
        for (int nt = 0; nt < 8; nt++) {
            S[nt][0] = __expf(S[nt][0] - mn0); sum0 += S[nt][0];
            S[nt][1] = __expf(S[nt][1] - mn0); sum0 += S[nt][1];
            S[nt][2] = __expf(S[nt][2] - mn1); sum1 += S[nt][2];
            S[nt][3] = __expf(S[nt][3] - mn1); sum1 += S[nt][3];
        }
        #pragma unroll
        for (int off = 1; off < 4; off <<= 1) {
            sum0 += __shfl_xor_sync(0xffffffffu, sum0, off);
            sum1 += __shfl_xor_sync(0xffffffffu, sum1, off);
        }
        l0 = l0*sc0 + sum0; l1 = l1*sc1 + sum1;
        m0 = mn0; m1 = mn1;
        #pragma unroll
        for (int dn = 0; dn < 8; dn++) {
            O[dn][0] *= sc0; O[dn][1] *= sc0;
            O[dn][2] *= sc1; O[dn][3] *= sc1;
        }

        #pragma unroll
        for (int kt = 0; kt < 8; kt++) {
            float e, o;
            e = __shfl_sync(0xffffffffu, S[kt][0], srcA);
            o = __shfl_sync(0xffffffffu, S[kt][1], srcA);
            unsigned a0 = f2tf32(odd ? o : e);
            e = __shfl_sync(0xffffffffu, S[kt][2], srcA);
            o = __shfl_sync(0xffffffffu, S[kt][3], srcA);
            unsigned a1 = f2tf32(odd ? o : e);
            e = __shfl_sync(0xffffffffu, S[kt][0], srcB);
            o = __shfl_sync(0xffffffffu, S[kt][1], srcB);
            unsigned a2 = f2tf32(odd ? o : e);
            e = __shfl_sync(0xffffffffu, S[kt][2], srcB);
            o = __shfl_sync(0xffffffffu, S[kt][3], srcB);
            unsigned a3 = f2tf32(odd ? o : e);

            #pragma unroll
            for (int dn = 0; dn < 8; dn++) {
                unsigned b0 = Vs[(kt*8 + t4    )*VSTR + dn*8 + gid];
                unsigned b1 = Vs[(kt*8 + t4 + 4)*VSTR + dn*8 + gid];
                mma_tf32(O[dn][0], O[dn][1], O[dn][2], O[dn][3],
                         a0, a1, a2, a3, b0, b1);
            }
        }
    }

    float inv0 = 1.f / l0, inv1 = 1.f / l1;
    #pragma unroll
    for (int dn = 0; dn < 8; dn++) {
        int col = h*HDIM + dn*8 + 2*t4;
        float2 r0 = make_float2(__uint_as_float(f2tf32(O[dn][0]*inv0)),
                                __uint_as_float(f2tf32(O[dn][1]*inv0)));
        float2 r1 = make_float2(__uint_as_float(f2tf32(O[dn][2]*inv1)),
                                __uint_as_float(f2tf32(O[dn][3]*inv1)));
        *(float2*)&g_att[((size_t)b*SS + qr0)*DD + col] = r0;
        *(float2*)&g_att[((size_t)b*SS + qr1)*DD + col] = r1;
    }
}

// ---------------- launch ----------------
extern "C" void kernel_launch(void* const* d_in, const int* in_sizes, int n_in,
                              void* d_out, int out_size)
{
    (void)in_sizes; (void)n_in; (void)out_size;
    const float* x  = (const float*)d_in[0];
    const float* Wq = (const float*)d_in[1];
    const float* Wk = (const float*)d_in[2];
    const float* Wv = (const float*)d_in[3];
    const float* Wo = (const float*)d_in[4];
    const float* bo = (const float*)d_in[5];
    const float* Ws = (const float*)d_in[6];
    const float* bs = (const float*)d_in[7];
    float* out = (float*)d_out;

    float *qlin, *klin, *vlin, *att;
    unsigned *q, *qsp, *k, *ksp, *v;
    unsigned *xc, *wqc, *wkc, *wvc, *woc;
    cudaGetSymbolAddress((void**)&qlin, g_qlin);
    cudaGetSymbolAddress((void**)&klin, g_klin);
    cudaGetSymbolAddress((void**)&vlin, g_vlin);
    cudaGetSymbolAddress((void**)&q,    g_q);
    cudaGetSymbolAddress((void**)&qsp,  g_qsp);
    cudaGetSymbolAddress((void**)&k,    g_k);
    cudaGetSymbolAddress((void**)&ksp,  g_ksp);
    cudaGetSymbolAddress((void**)&v,    g_v);
    cudaGetSymbolAddress((void**)&att,  g_att);
    cudaGetSymbolAddress((void**)&xc,   g_xc);
    cudaGetSymbolAddress((void**)&wqc,  g_wqc);
    cudaGetSymbolAddress((void**)&wkc,  g_wkc);
    cudaGetSymbolAddress((void**)&wvc,  g_wvc);
    cudaGetSymbolAddress((void**)&woc,  g_woc);

    const int M = BB*SS;   // 4096

    static bool attr_set = false;
    if (!attr_set) {
        cudaFuncSetAttribute(gemm3, cudaFuncAttributeMaxDynamicSharedMemorySize, GSMEM);
        cudaFuncSetAttribute(attn_mma_kernel, cudaFuncAttributeMaxDynamicSharedMemorySize, ASMEM);
        attr_set = true;
    }

    init_rope_kernel<<<(SS*(HDIM/2) + 255)/256, 256>>>();

    cvt_tf32_kernel<<<(BB*SS*DD/4 + 255)/256, 256>>>(x,  xc,  BB*SS*DD/4);
    cvt_tf32_kernel<<<(DD*DD/4 + 255)/256, 256>>>(Wq, wqc, DD*DD/4);
    cvt_tf32_kernel<<<(HKV*HDIM*DD/4 + 255)/256, 256>>>(Wk, wkc, HKV*HDIM*DD/4);
    cvt_tf32_kernel<<<(HKV*HDIM*DD/4 + 255)/256, 256>>>(Wv, wvc, HKV*HDIM*DD/4);
    cvt_tf32_kernel<<<(DD*DD/4 + 255)/256, 256>>>(Wo, woc, DD*DD/4);

    gemm3<<<dim3(12, M/TBM), 256, GSMEM>>>(xc,
                                    wqc, qlin, 8, DD,
                                    wkc, klin, 2, HKV*HDIM,
                                    wvc, vlin, 2, HKV*HDIM,
                                    nullptr, DD);

    rope_sp_kernel<<<(BB*SS*HH  + 255)/256, 256>>>(qlin, nullptr, Ws, bs, q, qsp, nullptr, HH);
    rope_sp_kernel<<<(BB*SS*HKV + 255)/256, 256>>>(klin, vlin,    Ws, bs, k, ksp, v,       HKV);

    attn_mma_kernel<<<dim3(SS/AQT, HH, BB), 256, ASMEM>>>();

    gemm3<<<dim3(8, M/TBM), 256, GSMEM>>>((const unsigned*)att,
                                    woc, out, 8, DD,
                                    nullptr, nullptr, 0, 0,
                                    nullptr, nullptr, 0, 0,
                                    bo, DD);
}

// round 9
// speedup vs baseline: 7.4432x; 1.0313x over previous
#include <cuda_runtime.h>
#include <cuda_bf16.h>
#include <math.h>

#define BB 2
#define SS 2048
#define DD 1024
#define HH 16
#define HKV 4
#define HDIM 64
#define SDIM 16

// ---------------- scratch (device globals; no allocation) ----------------
__device__ float    g_qlin[BB*SS*DD];
__device__ float    g_klin[BB*SS*HKV*HDIM];
__device__ float    g_vlin[BB*SS*HKV*HDIM];
__device__ unsigned g_q   [BB*HH*SS*HDIM];
__device__ unsigned g_qsp [BB*HH*SS*SDIM];
__device__ unsigned g_k   [BB*HKV*SS*HDIM];
__device__ unsigned g_ksp [BB*HKV*SS*SDIM];
__device__ unsigned g_v   [BB*HKV*SS*HDIM];
__device__ float    g_att [BB*SS*DD];
__device__ float    g_cosT[SS*(HDIM/2)];
__device__ float    g_sinT[SS*(HDIM/2)];
__device__ unsigned g_xc  [BB*SS*DD];
__device__ unsigned g_wqc [DD*DD];
__device__ unsigned g_wkc [HKV*HDIM*DD];
__device__ unsigned g_wvc [HKV*HDIM*DD];
__device__ unsigned g_woc [DD*DD];

// ---------------- common helpers ----------------
__device__ __forceinline__ unsigned f2tf32(float f) {
    unsigned r;
    asm("cvt.rna.tf32.f32 %0, %1;" : "=r"(r) : "f"(f));
    return r;
}

__device__ __forceinline__ void mma_tf32(float& d0, float& d1, float& d2, float& d3,
                                         unsigned a0, unsigned a1, unsigned a2, unsigned a3,
                                         unsigned b0, unsigned b1) {
    asm volatile(
        "mma.sync.aligned.m16n8k8.row.col.f32.tf32.tf32.f32 "
        "{%0,%1,%2,%3},{%4,%5,%6,%7},{%8,%9},{%0,%1,%2,%3};"
        : "+f"(d0), "+f"(d1), "+f"(d2), "+f"(d3)
        : "r"(a0), "r"(a1), "r"(a2), "r"(a3), "r"(b0), "r"(b1));
}

__device__ __forceinline__ unsigned smem_u32(const void* p) {
    return (unsigned)__cvta_generic_to_shared(p);
}
__device__ __forceinline__ void cp16(unsigned dst, const void* src) {
    asm volatile("cp.async.cg.shared.global [%0], [%1], 16;" :: "r"(dst), "l"(src));
}
__device__ __forceinline__ uint4 ldsm4(unsigned addr) {
    uint4 r;
    asm volatile("ldmatrix.sync.aligned.m8n8.x4.shared.b16 {%0,%1,%2,%3}, [%4];"
                 : "=r"(r.x), "=r"(r.y), "=r"(r.z), "=r"(r.w) : "r"(addr));
    return r;
}

// ---------------- fused prologue: rope table + all tf32 conversions ----------------
// segment sizes (in 256-thread blocks of float4 chunks):
//   x  : BB*SS*DD/4/256   = 4096
//   Wq : DD*DD/4/256      = 1024
//   Wk : HKV*HDIM*DD/4/256= 256
//   Wv :                  = 256
//   Wo :                  = 1024
//   rope: SS*(HDIM/2)/256 = 256
// blocks: x[0,4096) Wq[4096,5120) Wk[5120,5376) Wv[5376,5632) Wo[5632,6656) rope[6656,6912)
#define PREP_BLOCKS 6912

__device__ __forceinline__ void cvt_seg(const float* __restrict__ in,
                                        unsigned* __restrict__ out, int blk) {
    int i = blk*256 + threadIdx.x;
    float4 f = ((const float4*)in)[i];
    uint4 u;
    u.x = f2tf32(f.x); u.y = f2tf32(f.y); u.z = f2tf32(f.z); u.w = f2tf32(f.w);
    ((uint4*)out)[i] = u;
}

__global__ void prep_kernel(const float* __restrict__ x,
                            const float* __restrict__ Wq,
                            const float* __restrict__ Wk,
                            const float* __restrict__ Wv,
                            const float* __restrict__ Wo)
{
    int bx = blockIdx.x;
    if (bx < 4096)      { cvt_seg(x,  g_xc,  bx); }
    else if (bx < 5120) { cvt_seg(Wq, g_wqc, bx - 4096); }
    else if (bx < 5376) { cvt_seg(Wk, g_wkc, bx - 5120); }
    else if (bx < 5632) { cvt_seg(Wv, g_wvc, bx - 5376); }
    else if (bx < 6656) { cvt_seg(Wo, g_woc, bx - 5632); }
    else {
        int idx = (bx - 6656)*256 + threadIdx.x;   // < SS*(HDIM/2) = 65536
        int s = idx / (HDIM/2), i = idx % (HDIM/2);
        float thf = (float)pow(10000.0, -(double)i / (double)(HDIM/2));
        float ff  = (float)s * thf;
        g_cosT[idx] = (float)cos((double)ff);
        g_sinT[idx] = (float)sin((double)ff);
    }
}

// ================= cp.async + ldmatrix TF32 GEMM =================
#define TBM 128
#define TBN 128
#define TBK 16
#define PADK 20
#define STG 3
#define GSMEM (STG*(TBM+TBN)*PADK*4)

__global__ void __launch_bounds__(256) gemm3(
    const unsigned* __restrict__ A,
    const unsigned* __restrict__ W0, float* __restrict__ C0, int nx0, int N0,
    const unsigned* __restrict__ W1, float* __restrict__ C1, int nx1, int N1,
    const unsigned* __restrict__ W2, float* __restrict__ C2, int nx2, int N2,
    const float* __restrict__ bias, int K)
{
    extern __shared__ unsigned sh[];
    unsigned* Asm = sh;
    unsigned* Bsm = sh + STG*TBM*PADK;

    const int tid = threadIdx.x;
    const int w = tid >> 5, lane = tid & 31;
    const int gid = lane >> 2, t4 = lane & 3;
    const int wm = w & 1, wn = w >> 1;
    const int row0 = blockIdx.y*TBM;

    const unsigned* Wp; float* Cp; int N, cb;
    int bx = blockIdx.x;
    if (bx < nx0)            { Wp = W0; Cp = C0; N = N0; cb = bx; }
    else if (bx < nx0 + nx1) { Wp = W1; Cp = C1; N = N1; cb = bx - nx0; }
    else                     { Wp = W2; Cp = C2; N = N2; cb = bx - nx0 - nx1; }
    const int col0 = cb*TBN;

    const unsigned* Aptr = A  + (size_t)row0*K;
    const unsigned* Wptr = Wp + (size_t)col0*K;

    const int r0c = tid >> 2, r1c = r0c + 64;
    const int cc  = (tid & 3) << 2;

    const unsigned asA = smem_u32(Asm);
    const unsigned asB = smem_u32(Bsm);

    int aoff[4], boff[2];
    #pragma unroll
    for (int mt = 0; mt < 4; mt++)
        aoff[mt] = (wm*64 + mt*16 + (lane & 15))*PADK + ((lane >> 4) << 2);
    #pragma unroll
    for (int np = 0; np < 2; np++)
        boff[np] = (wn*32 + np*16 + (lane & 15))*PADK + ((lane >> 4) << 2);

    #pragma unroll
    for (int s = 0; s < STG-1; s++) {
        int k0 = s*TBK;
        cp16(asA + (s*(TBM*PADK) + r0c*PADK + cc)*4, Aptr + (size_t)r0c*K + k0 + cc);
        cp16(asA + (s*(TBM*PADK) + r1c*PADK + cc)*4, Aptr + (size_t)r1c*K + k0 + cc);
        cp16(asB + (s*(TBN*PADK) + r0c*PADK + cc)*4, Wptr + (size_t)r0c*K + k0 + cc);
        cp16(asB + (s*(TBN*PADK) + r1c*PADK + cc)*4, Wptr + (size_t)r1c*K + k0 + cc);
        asm volatile("cp.async.commit_group;");
    }

    float acc[4][4][4];
    #pragma unroll
    for (int mt = 0; mt < 4; mt++)
        #pragma unroll
        for (int nt = 0; nt < 4; nt++)
            #pragma unroll
            for (int j = 0; j < 4; j++) acc[mt][nt][j] = 0.f;

    const int T = K / TBK;
    int st = 0, si = STG - 1;
    for (int t = 0; t < T; t++) {
        asm volatile("cp.async.wait_group 1;" ::: "memory");
        __syncthreads();

        if (t + STG - 1 < T) {
            int k0 = (t + STG - 1)*TBK;
            cp16(asA + (si*(TBM*PADK) + r0c*PADK + cc)*4, Aptr + (size_t)r0c*K + k0 + cc);
            cp16(asA + (si*(TBM*PADK) + r1c*PADK + cc)*4, Aptr + (size_t)r1c*K + k0 + cc);
            cp16(asB + (si*(TBN*PADK) + r0c*PADK + cc)*4, Wptr + (size_t)r0c*K + k0 + cc);
            cp16(asB + (si*(TBN*PADK) + r1c*PADK + cc)*4, Wptr + (size_t)r1c*K + k0 + cc);
        }
        asm volatile("cp.async.commit_group;");

        const unsigned aStg = asA + (st*(TBM*PADK))*4;
        const unsigned bStg = asB + (st*(TBN*PADK))*4;
        #pragma unroll
        for (int kk = 0; kk < TBK; kk += 8) {
            uint4 av[4], bv[2];
            #pragma unroll
            for (int mt = 0; mt < 4; mt++) av[mt] = ldsm4(aStg + (aoff[mt] + kk)*4);
            #pragma unroll
            for (int np = 0; np < 2; np++) bv[np] = ldsm4(bStg + (boff[np] + kk)*4);
            #pragma unroll
            for (int np = 0; np < 2; np++) {
                #pragma unroll
                for (int mt = 0; mt < 4; mt++) {
                    mma_tf32(acc[mt][2*np  ][0], acc[mt][2*np  ][1], acc[mt][2*np  ][2], acc[mt][2*np  ][3],
                             av[mt].x, av[mt].y, av[mt].z, av[mt].w, bv[np].x, bv[np].z);
                    mma_tf32(acc[mt][2*np+1][0], acc[mt][2*np+1][1], acc[mt][2*np+1][2], acc[mt][2*np+1][3],
                             av[mt].x, av[mt].y, av[mt].z, av[mt].w, bv[np].y, bv[np].w);
                }
            }
        }
        st = (st + 1 == STG) ? 0 : st + 1;
        si = (si + 1 == STG) ? 0 : si + 1;
    }

    #pragma unroll
    for (int mt = 0; mt < 4; mt++) {
        int r = row0 + wm*64 + mt*16 + gid;
        #pragma unroll
        for (int nt = 0; nt < 4; nt++) {
            int c = col0 + wn*32 + nt*8 + 2*t4;
            float bv0 = bias ? bias[c]   : 0.f;
            float bv1 = bias ? bias[c+1] : 0.f;
            *(float2*)&Cp[(size_t)r*N + c]     = make_float2(acc[mt][nt][0]+bv0, acc[mt][nt][1]+bv1);
            *(float2*)&Cp[(size_t)(r+8)*N + c] = make_float2(acc[mt][nt][2]+bv0, acc[mt][nt][3]+bv1);
        }
    }
}

// ---------------- fused RoPE + sparsity projection (q and kv segments) ----------------
__global__ void rope_sp_all(const float* __restrict__ Ws,
                            const float* __restrict__ bs)
{
    __shared__ float WsS[SDIM*HDIM];
    __shared__ float bsS[SDIM];
    for (int i = threadIdx.x; i < SDIM*HDIM; i += blockDim.x) WsS[i] = Ws[i];
    if (threadIdx.x < SDIM) bsS[threadIdx.x] = bs[threadIdx.x];
    __syncthreads();

    const int NQ = BB*SS*HH;
    int gidx = blockIdx.x*blockDim.x + threadIdx.x;

    const float* lin; unsigned *obuf, *spbuf;
    bool doV = false;
    int idx, NH;
    if (gidx < NQ) {
        idx = gidx; NH = HH;
        lin = g_qlin; obuf = g_q; spbuf = g_qsp;
    } else {
        idx = gidx - NQ;
        if (idx >= BB*SS*HKV) return;
        NH = HKV;
        lin = g_klin; obuf = g_k; spbuf = g_ksp;
        doV = true;
    }

    int h = idx % NH;
    int s = (idx / NH) % SS;
    int b = idx / (NH*SS);

    const float4* src = (const float4*)(lin + ((size_t)(b*SS + s)*NH + h)*HDIM);
    float v[HDIM];
    #pragma unroll
    for (int t = 0; t < HDIM/4; t++) ((float4*)v)[t] = src[t];

    #pragma unroll
    for (int i = 0; i < HDIM/2; i++) {
        float c  = g_cosT[s*(HDIM/2)+i];
        float sn = g_sinT[s*(HDIM/2)+i];
        float a  = v[i], bpart = v[i+HDIM/2];
        v[i]        = a*c - bpart*sn;
        v[i+HDIM/2] = bpart*c + a*sn;
    }

    unsigned* dst = obuf + (((size_t)b*NH + h)*SS + s)*HDIM;
    #pragma unroll
    for (int d = 0; d < HDIM; d += 4) {
        uint4 u;
        u.x = f2tf32(v[d]);   u.y = f2tf32(v[d+1]);
        u.z = f2tf32(v[d+2]); u.w = f2tf32(v[d+3]);
        *(uint4*)&dst[d] = u;
    }

    unsigned* spd = spbuf + (((size_t)b*NH + h)*SS + s)*SDIM;
    #pragma unroll
    for (int j = 0; j < SDIM; j++) {
        float acc = bsS[j];
        #pragma unroll
        for (int d = 0; d < HDIM; d++) acc += WsS[j*HDIM + d] * v[d];
        spd[j] = f2tf32(acc);
    }

    if (doV) {
        const float4* vsrc = (const float4*)(g_vlin + ((size_t)(b*SS + s)*NH + h)*HDIM);
        unsigned* vdst = g_v + (((size_t)b*NH + h)*SS + s)*HDIM;
        #pragma unroll
        for (int t = 0; t < HDIM/4; t++) {
            float4 f = vsrc[t];
            uint4 u;
            u.x = f2tf32(f.x); u.y = f2tf32(f.y); u.z = f2tf32(f.z); u.w = f2tf32(f.w);
            *(uint4*)&vdst[t*4] = u;
        }
    }
}

// ================= TF32 attention, cp.async double-buffered, 2 CTAs/SM =================
#define AQT 128
#define AKT 64
#define KSTR 68
#define VSTR 72
#define SSTR 20
#define KBUF (AKT*KSTR)
#define VBUF (AKT*VSTR)
#define SBUF (AKT*SSTR)
#define ABUF (KBUF+VBUF+SBUF)
#define ASMEM (2*ABUF*4)

__global__ void __launch_bounds__(256, 2) attn_mma_kernel()
{
    extern __shared__ unsigned ash[];

    const int b = blockIdx.z, h = blockIdx.y;
    const int hkv = h >> 2;
    const int q0 = (gridDim.x - 1 - blockIdx.x) * AQT;
    const int tid = threadIdx.x;
    const int w = tid >> 5, lane = tid & 31;
    const int gid = lane >> 2, t4 = lane & 3;

    const int q0w = q0 + w*16;
    const int qr0 = q0w + gid;
    const int qr1 = qr0 + 8;

    const unsigned* qbase = g_q   + ((size_t)b*HH  + h  )*SS*HDIM;
    const unsigned* qspb  = g_qsp + ((size_t)b*HH  + h  )*SS*SDIM;
    const unsigned* kptr  = g_k   + ((size_t)b*HKV + hkv)*SS*HDIM;
    const unsigned* kspp  = g_ksp + ((size_t)b*HKV + hkv)*SS*SDIM;
    const unsigned* vptr  = g_v   + ((size_t)b*HKV + hkv)*SS*HDIM;

    const unsigned shbase = smem_u32(ash);

    unsigned qa[8][4], qsa[2][4];
    #pragma unroll
    for (int kt = 0; kt < 8; kt++) {
        qa[kt][0] = qbase[(size_t)qr0*HDIM + kt*8 + t4];
        qa[kt][1] = qbase[(size_t)qr1*HDIM + kt*8 + t4];
        qa[kt][2] = qbase[(size_t)qr0*HDIM + kt*8 + t4 + 4];
        qa[kt][3] = qbase[(size_t)qr1*HDIM + kt*8 + t4 + 4];
    }
    #pragma unroll
    for (int kt = 0; kt < 2; kt++) {
        qsa[kt][0] = qspb[(size_t)qr0*SDIM + kt*8 + t4];
        qsa[kt][1] = qspb[(size_t)qr1*SDIM + kt*8 + t4];
        qsa[kt][2] = qspb[(size_t)qr0*SDIM + kt*8 + t4 + 4];
        qsa[kt][3] = qspb[(size_t)qr1*SDIM + kt*8 + t4 + 4];
    }

    float m0 = -1e30f, m1 = -1e30f, l0 = 0.f, l1 = 0.f;
    float O[8][4];
    #pragma unroll
    for (int dn = 0; dn < 8; dn++)
        #pragma unroll
        for (int j = 0; j < 4; j++) O[dn][j] = 0.f;

    const int srcA = (lane & ~3) | (t4 >> 1);
    const int srcB = srcA + 2;
    const bool odd = (t4 & 1);

    auto issue_tile = [&](int kb, int buf) {
        unsigned base = shbase + buf*ABUF*4;
        #pragma unroll
        for (int c = 0; c < 4; c++) {
            int i = tid + c*256;
            int key = i >> 4, d = (i & 15) << 2;
            cp16(base + (key*KSTR + d)*4,          kptr + (size_t)(kb+key)*HDIM + d);
            cp16(base + (KBUF + key*VSTR + d)*4,   vptr + (size_t)(kb+key)*HDIM + d);
        }
        {
            int key = tid >> 2, j = (tid & 3) << 2;
            cp16(base + (KBUF + VBUF + key*SSTR + j)*4, kspp + (size_t)(kb+key)*SDIM + j);
        }
    };

    const int nTiles = (q0 + AQT) / AKT;
    issue_tile(0, 0);
    asm volatile("cp.async.commit_group;");

    for (int t = 0; t < nTiles; t++) {
        const int kb = t*AKT;
        const int buf = t & 1;
        __syncthreads();
        if (t + 1 < nTiles) issue_tile(kb + AKT, buf ^ 1);
        asm volatile("cp.async.commit_group;");
        asm volatile("cp.async.wait_group 1;" ::: "memory");
        __syncthreads();

        if (kb > q0w + 15) continue;

        const unsigned* Ks   = ash + buf*ABUF;
        const unsigned* Vs   = Ks + KBUF;
        const unsigned* Ksps = Ks + KBUF + VBUF;

        float S[8][4], SP[8][4];
        #pragma unroll
        for (int nt = 0; nt < 8; nt++)
            #pragma unroll
            for (int j = 0; j < 4; j++) { S[nt][j] = 0.f; SP[nt][j] = 0.f; }

        #pragma unroll
        for (int kt = 0; kt < 8; kt++) {
            #pragma unroll
            for (int nt = 0; nt < 8; nt++) {
                unsigned b0 = Ks[(nt*8 + gid)*KSTR + kt*8 + t4];
                unsigned b1 = Ks[(nt*8 + gid)*KSTR + kt*8 + t4 + 4];
                mma_tf32(S[nt][0], S[nt][1], S[nt][2], S[nt][3],
                         qa[kt][0], qa[kt][1], qa[kt][2], qa[kt][3], b0, b1);
            }
        }
        #pragma unroll
        for (int kt = 0; kt < 2; kt++) {
            #pragma unroll
            for (int nt = 0; nt < 8; nt++) {
                unsigned b0 = Ksps[(nt*8 + gid)*SSTR + kt*8 + t4];
                unsigned b1 = Ksps[(nt*8 + gid)*SSTR + kt*8 + t4 + 4];
                mma_tf32(SP[nt][0], SP[nt][1], SP[nt][2], SP[nt][3],
                         qsa[kt][0], qsa[kt][1], qsa[kt][2], qsa[kt][3], b0, b1);
            }
        }

        #pragma unroll
        for (int nt = 0; nt < 8; nt++) {
            #pragma unroll
            for (int j = 0; j < 4; j++) {
                int key = kb + nt*8 + 2*t4 + (j & 1);
                int row = (j >= 2) ? qr1 : qr0;
                float g = 1.f / (1.f + __expf(-SP[nt][j] * 0.25f));
                float lg = S[nt][j] * 0.125f * g;
                S[nt][j] = (key > row) ? -1e30f : lg;
            }
        }

        float mx0 = -1e30f, mx1 = -1e30f;
        #pragma unroll
        for (int nt = 0; nt < 8; nt++) {
            mx0 = fmaxf(mx0, fmaxf(S[nt][0], S[nt][1]));
            mx1 = fmaxf(mx1, fmaxf(S[nt][2], S[nt][3]));
        }
        #pragma unroll
        for (int off = 1; off < 4; off <<= 1) {
            mx0 = fmaxf(mx0, __shfl_xor_sync(0xffffffffu, mx0, off));
            mx1 = fmaxf(mx1, __shfl_xor_sync(0xffffffffu, mx1, off));
        }
        float mn0 = fmaxf(m0, mx0), mn1 = fmaxf(m1, mx1);
        float sc0 = __expf(m0 - mn0), sc1 = __expf(m1 - mn1);
        float sum0 = 0.f, sum1 = 0.f;
        #pragma unroll
        for (int nt = 0; nt < 8; nt++) {
            S[nt][0] = __expf(S[nt][0] - mn0); sum0 += S[nt][0];
            S[nt][1] = __expf(S[nt][1] - mn0); sum0 += S[nt][1];
            S[nt][2] = __expf(S[nt][2] - mn1); sum1 += S[nt][2];
            S[nt][3] = __expf(S[nt][3] - mn1); sum1 += S[nt][3];
        }
        #pragma unroll
        for (int off = 1; off < 4; off <<= 1) {
            sum0 += __shfl_xor_sync(0xffffffffu, sum0, off);
            sum1 += __shfl_xor_sync(0xffffffffu, sum1, off);
        }
        l0 = l0*sc0 + sum0; l1 = l1*sc1 + sum1;
        m0 = mn0; m1 = mn1;
        #pragma unroll
        for (int dn = 0; dn < 8; dn++) {
            O[dn][0] *= sc0; O[dn][1] *= sc0;
            O[dn][2] *= sc1; O[dn][3] *= sc1;
        }

        #pragma unroll
        for (int kt = 0; kt < 8; kt++) {
            float e, o;
            e = __shfl_sync(0xffffffffu, S[kt][0], srcA);
            o = __shfl_sync(0xffffffffu, S[kt][1], srcA);
            unsigned a0 = f2tf32(odd ? o : e);
            e = __shfl_sync(0xffffffffu, S[kt][2], srcA);
            o = __shfl_sync(0xffffffffu, S[kt][3], srcA);
            unsigned a1 = f2tf32(odd ? o : e);
            e = __shfl_sync(0xffffffffu, S[kt][0], srcB);
            o = __shfl_sync(0xffffffffu, S[kt][1], srcB);
            unsigned a2 = f2tf32(odd ? o : e);
            e = __shfl_sync(0xffffffffu, S[kt][2], srcB);
            o = __shfl_sync(0xffffffffu, S[kt][3], srcB);
            unsigned a3 = f2tf32(odd ? o : e);

            #pragma unroll
            for (int dn = 0; dn < 8; dn++) {
                unsigned b0 = Vs[(kt*8 + t4    )*VSTR + dn*8 + gid];
                unsigned b1 = Vs[(kt*8 + t4 + 4)*VSTR + dn*8 + gid];
                mma_tf32(O[dn][0], O[dn][1], O[dn][2], O[dn][3],
                         a0, a1, a2, a3, b0, b1);
            }
        }
    }

    float inv0 = 1.f / l0, inv1 = 1.f / l1;
    #pragma unroll
    for (int dn = 0; dn < 8; dn++) {
        int col = h*HDIM + dn*8 + 2*t4;
        float2 r0 = make_float2(__uint_as_float(f2tf32(O[dn][0]*inv0)),
                                __uint_as_float(f2tf32(O[dn][1]*inv0)));
        float2 r1 = make_float2(__uint_as_float(f2tf32(O[dn][2]*inv1)),
                                __uint_as_float(f2tf32(O[dn][3]*inv1)));
        *(float2*)&g_att[((size_t)b*SS + qr0)*DD + col] = r0;
        *(float2*)&g_att[((size_t)b*SS + qr1)*DD + col] = r1;
    }
}

// ---------------- launch ----------------
extern "C" void kernel_launch(void* const* d_in, const int* in_sizes, int n_in,
                              void* d_out, int out_size)
{
    (void)in_sizes; (void)n_in; (void)out_size;
    const float* x  = (const float*)d_in[0];
    const float* Wq = (const float*)d_in[1];
    const float* Wk = (const float*)d_in[2];
    const float* Wv = (const float*)d_in[3];
    const float* Wo = (const float*)d_in[4];
    const float* bo = (const float*)d_in[5];
    const float* Ws = (const float*)d_in[6];
    const float* bs = (const float*)d_in[7];
    float* out = (float*)d_out;

    float *qlin, *klin, *vlin, *att;
    unsigned *xc, *wqc, *wkc, *wvc, *woc;
    cudaGetSymbolAddress((void**)&qlin, g_qlin);
    cudaGetSymbolAddress((void**)&klin, g_klin);
    cudaGetSymbolAddress((void**)&vlin, g_vlin);
    cudaGetSymbolAddress((void**)&att,  g_att);
    cudaGetSymbolAddress((void**)&xc,   g_xc);
    cudaGetSymbolAddress((void**)&wqc,  g_wqc);
    cudaGetSymbolAddress((void**)&wkc,  g_wkc);
    cudaGetSymbolAddress((void**)&wvc,  g_wvc);
    cudaGetSymbolAddress((void**)&woc,  g_woc);

    const int M = BB*SS;   // 4096

    static bool attr_set = false;
    if (!attr_set) {
        cudaFuncSetAttribute(gemm3, cudaFuncAttributeMaxDynamicSharedMemorySize, GSMEM);
        cudaFuncSetAttribute(attn_mma_kernel, cudaFuncAttributeMaxDynamicSharedMemorySize, ASMEM);
        attr_set = true;
    }

    prep_kernel<<<PREP_BLOCKS, 256>>>(x, Wq, Wk, Wv, Wo);

    gemm3<<<dim3(12, M/TBM), 256, GSMEM>>>(xc,
                                    wqc, qlin, 8, DD,
                                    wkc, klin, 2, HKV*HDIM,
                                    wvc, vlin, 2, HKV*HDIM,
                                    nullptr, DD);

    rope_sp_all<<<(BB*SS*(HH+HKV) + 255)/256, 256>>>(Ws, bs);

    attn_mma_kernel<<<dim3(SS/AQT, HH, BB), 256, ASMEM>>>();

    gemm3<<<dim3(8, M/TBM), 256, GSMEM>>>((const unsigned*)att,
                                    woc, out, 8, DD,
                                    nullptr, nullptr, 0, 0,
                                    nullptr, nullptr, 0, 0,
                                    bo, DD);
}

// round 10
// speedup vs baseline: 8.2385x; 1.1068x over previous
#include <cuda_runtime.h>
#include <cuda_bf16.h>
#include <math.h>

#define BB 2
#define SS 2048
#define DD 1024
#define HH 16
#define HKV 4
#define HDIM 64
#define SDIM 16

// ---------------- scratch (device globals; no allocation) ----------------
__device__ float    g_qlin[BB*SS*DD];
__device__ float    g_klin[BB*SS*HKV*HDIM];
__device__ float    g_vlin[BB*SS*HKV*HDIM];
__device__ unsigned g_q   [BB*HH*SS*HDIM];
__device__ unsigned g_qsp [BB*HH*SS*SDIM];
__device__ unsigned g_k   [BB*HKV*SS*HDIM];
__device__ unsigned g_ksp [BB*HKV*SS*SDIM];
__device__ unsigned g_v   [BB*HKV*HDIM*SS];   // TRANSPOSED: [b,hkv,d,s]
__device__ float    g_att [BB*SS*DD];
__device__ float    g_cosT[SS*(HDIM/2)];
__device__ float    g_sinT[SS*(HDIM/2)];
__device__ unsigned g_xc  [BB*SS*DD];
__device__ unsigned g_wqc [DD*DD];
__device__ unsigned g_wkc [HKV*HDIM*DD];
__device__ unsigned g_wvc [HKV*HDIM*DD];
__device__ unsigned g_woc [DD*DD];

// ---------------- common helpers ----------------
__device__ __forceinline__ unsigned f2tf32(float f) {
    unsigned r;
    asm("cvt.rna.tf32.f32 %0, %1;" : "=r"(r) : "f"(f));
    return r;
}
__device__ __forceinline__ float ex2f(float x) {
    float r;
    asm("ex2.approx.f32 %0, %1;" : "=f"(r) : "f"(x));
    return r;
}
__device__ __forceinline__ float rcpf(float x) {
    float r;
    asm("rcp.approx.f32 %0, %1;" : "=f"(r) : "f"(x));
    return r;
}

__device__ __forceinline__ void mma_tf32(float& d0, float& d1, float& d2, float& d3,
                                         unsigned a0, unsigned a1, unsigned a2, unsigned a3,
                                         unsigned b0, unsigned b1) {
    asm volatile(
        "mma.sync.aligned.m16n8k8.row.col.f32.tf32.tf32.f32 "
        "{%0,%1,%2,%3},{%4,%5,%6,%7},{%8,%9},{%0,%1,%2,%3};"
        : "+f"(d0), "+f"(d1), "+f"(d2), "+f"(d3)
        : "r"(a0), "r"(a1), "r"(a2), "r"(a3), "r"(b0), "r"(b1));
}

__device__ __forceinline__ unsigned smem_u32(const void* p) {
    return (unsigned)__cvta_generic_to_shared(p);
}
__device__ __forceinline__ void cp16(unsigned dst, const void* src) {
    asm volatile("cp.async.cg.shared.global [%0], [%1], 16;" :: "r"(dst), "l"(src));
}
__device__ __forceinline__ uint4 ldsm4(unsigned addr) {
    uint4 r;
    asm volatile("ldmatrix.sync.aligned.m8n8.x4.shared.b16 {%0,%1,%2,%3}, [%4];"
                 : "=r"(r.x), "=r"(r.y), "=r"(r.z), "=r"(r.w) : "r"(addr));
    return r;
}

// ---------------- fused prologue: rope table + all tf32 conversions ----------------
#define PREP_BLOCKS 6912

__device__ __forceinline__ void cvt_seg(const float* __restrict__ in,
                                        unsigned* __restrict__ out, int blk) {
    int i = blk*256 + threadIdx.x;
    float4 f = ((const float4*)in)[i];
    uint4 u;
    u.x = f2tf32(f.x); u.y = f2tf32(f.y); u.z = f2tf32(f.z); u.w = f2tf32(f.w);
    ((uint4*)out)[i] = u;
}

__global__ void prep_kernel(const float* __restrict__ x,
                            const float* __restrict__ Wq,
                            const float* __restrict__ Wk,
                            const float* __restrict__ Wv,
                            const float* __restrict__ Wo)
{
    int bx = blockIdx.x;
    if (bx < 4096)      { cvt_seg(x,  g_xc,  bx); }
    else if (bx < 5120) { cvt_seg(Wq, g_wqc, bx - 4096); }
    else if (bx < 5376) { cvt_seg(Wk, g_wkc, bx - 5120); }
    else if (bx < 5632) { cvt_seg(Wv, g_wvc, bx - 5376); }
    else if (bx < 6656) { cvt_seg(Wo, g_woc, bx - 5632); }
    else {
        int idx = (bx - 6656)*256 + threadIdx.x;
        int s = idx / (HDIM/2), i = idx % (HDIM/2);
        float thf = (float)pow(10000.0, -(double)i / (double)(HDIM/2));
        float ff  = (float)s * thf;
        g_cosT[idx] = (float)cos((double)ff);
        g_sinT[idx] = (float)sin((double)ff);
    }
}

// ================= cp.async + ldmatrix TF32 GEMM =================
#define TBM 128
#define TBN 128
#define TBK 16
#define PADK 20
#define STG 3
#define GSMEM (STG*(TBM+TBN)*PADK*4)

__global__ void __launch_bounds__(256) gemm3(
    const unsigned* __restrict__ A,
    const unsigned* __restrict__ W0, float* __restrict__ C0, int nx0, int N0,
    const unsigned* __restrict__ W1, float* __restrict__ C1, int nx1, int N1,
    const unsigned* __restrict__ W2, float* __restrict__ C2, int nx2, int N2,
    const float* __restrict__ bias, int K)
{
    extern __shared__ unsigned sh[];
    unsigned* Asm = sh;
    unsigned* Bsm = sh + STG*TBM*PADK;

    const int tid = threadIdx.x;
    const int w = tid >> 5, lane = tid & 31;
    const int gid = lane >> 2, t4 = lane & 3;
    const int wm = w & 1, wn = w >> 1;
    const int row0 = blockIdx.y*TBM;

    const unsigned* Wp; float* Cp; int N, cb;
    int bx = blockIdx.x;
    if (bx < nx0)            { Wp = W0; Cp = C0; N = N0; cb = bx; }
    else if (bx < nx0 + nx1) { Wp = W1; Cp = C1; N = N1; cb = bx - nx0; }
    else                     { Wp = W2; Cp = C2; N = N2; cb = bx - nx0 - nx1; }
    const int col0 = cb*TBN;

    const unsigned* Aptr = A  + (size_t)row0*K;
    const unsigned* Wptr = Wp + (size_t)col0*K;

    const int r0c = tid >> 2, r1c = r0c + 64;
    const int cc  = (tid & 3) << 2;

    const unsigned asA = smem_u32(Asm);
    const unsigned asB = smem_u32(Bsm);

    int aoff[4], boff[2];
    #pragma unroll
    for (int mt = 0; mt < 4; mt++)
        aoff[mt] = (wm*64 + mt*16 + (lane & 15))*PADK + ((lane >> 4) << 2);
    #pragma unroll
    for (int np = 0; np < 2; np++)
        boff[np] = (wn*32 + np*16 + (lane & 15))*PADK + ((lane >> 4) << 2);

    #pragma unroll
    for (int s = 0; s < STG-1; s++) {
        int k0 = s*TBK;
        cp16(asA + (s*(TBM*PADK) + r0c*PADK + cc)*4, Aptr + (size_t)r0c*K + k0 + cc);
        cp16(asA + (s*(TBM*PADK) + r1c*PADK + cc)*4, Aptr + (size_t)r1c*K + k0 + cc);
        cp16(asB + (s*(TBN*PADK) + r0c*PADK + cc)*4, Wptr + (size_t)r0c*K + k0 + cc);
        cp16(asB + (s*(TBN*PADK) + r1c*PADK + cc)*4, Wptr + (size_t)r1c*K + k0 + cc);
        asm volatile("cp.async.commit_group;");
    }

    float acc[4][4][4];
    #pragma unroll
    for (int mt = 0; mt < 4; mt++)
        #pragma unroll
        for (int nt = 0; nt < 4; nt++)
            #pragma unroll
            for (int j = 0; j < 4; j++) acc[mt][nt][j] = 0.f;

    const int T = K / TBK;
    int st = 0, si = STG - 1;
    for (int t = 0; t < T; t++) {
        asm volatile("cp.async.wait_group 1;" ::: "memory");
        __syncthreads();

        if (t + STG - 1 < T) {
            int k0 = (t + STG - 1)*TBK;
            cp16(asA + (si*(TBM*PADK) + r0c*PADK + cc)*4, Aptr + (size_t)r0c*K + k0 + cc);
            cp16(asA + (si*(TBM*PADK) + r1c*PADK + cc)*4, Aptr + (size_t)r1c*K + k0 + cc);
            cp16(asB + (si*(TBN*PADK) + r0c*PADK + cc)*4, Wptr + (size_t)r0c*K + k0 + cc);
            cp16(asB + (si*(TBN*PADK) + r1c*PADK + cc)*4, Wptr + (size_t)r1c*K + k0 + cc);
        }
        asm volatile("cp.async.commit_group;");

        const unsigned aStg = asA + (st*(TBM*PADK))*4;
        const unsigned bStg = asB + (st*(TBN*PADK))*4;
        #pragma unroll
        for (int kk = 0; kk < TBK; kk += 8) {
            uint4 av[4], bv[2];
            #pragma unroll
            for (int mt = 0; mt < 4; mt++) av[mt] = ldsm4(aStg + (aoff[mt] + kk)*4);
            #pragma unroll
            for (int np = 0; np < 2; np++) bv[np] = ldsm4(bStg + (boff[np] + kk)*4);
            #pragma unroll
            for (int np = 0; np < 2; np++) {
                #pragma unroll
                for (int mt = 0; mt < 4; mt++) {
                    mma_tf32(acc[mt][2*np  ][0], acc[mt][2*np  ][1], acc[mt][2*np  ][2], acc[mt][2*np  ][3],
                             av[mt].x, av[mt].y, av[mt].z, av[mt].w, bv[np].x, bv[np].z);
                    mma_tf32(acc[mt][2*np+1][0], acc[mt][2*np+1][1], acc[mt][2*np+1][2], acc[mt][2*np+1][3],
                             av[mt].x, av[mt].y, av[mt].z, av[mt].w, bv[np].y, bv[np].w);
                }
            }
        }
        st = (st + 1 == STG) ? 0 : st + 1;
        si = (si + 1 == STG) ? 0 : si + 1;
    }

    #pragma unroll
    for (int mt = 0; mt < 4; mt++) {
        int r = row0 + wm*64 + mt*16 + gid;
        #pragma unroll
        for (int nt = 0; nt < 4; nt++) {
            int c = col0 + wn*32 + nt*8 + 2*t4;
            float bv0 = bias ? bias[c]   : 0.f;
            float bv1 = bias ? bias[c+1] : 0.f;
            *(float2*)&Cp[(size_t)r*N + c]     = make_float2(acc[mt][nt][0]+bv0, acc[mt][nt][1]+bv1);
            *(float2*)&Cp[(size_t)(r+8)*N + c] = make_float2(acc[mt][nt][2]+bv0, acc[mt][nt][3]+bv1);
        }
    }
}

// ---------------- fused RoPE + sparsity projection ----------------
// q segment: h-fastest indexing (reads coalesced-ish). kv segment: s-fastest
// so the transposed V writes are fully coalesced.
__global__ void rope_sp_all(const float* __restrict__ Ws,
                            const float* __restrict__ bs)
{
    __shared__ float WsS[SDIM*HDIM];
    __shared__ float bsS[SDIM];
    for (int i = threadIdx.x; i < SDIM*HDIM; i += blockDim.x) WsS[i] = Ws[i];
    if (threadIdx.x < SDIM) bsS[threadIdx.x] = bs[threadIdx.x];
    __syncthreads();

    const int NQ = BB*SS*HH;
    int gidx = blockIdx.x*blockDim.x + threadIdx.x;

    const float* lin; unsigned *obuf, *spbuf;
    bool doV = false;
    int b, s, h, NH;
    if (gidx < NQ) {
        NH = HH;
        h = gidx % NH; s = (gidx / NH) % SS; b = gidx / (NH*SS);
        lin = g_qlin; obuf = g_q; spbuf = g_qsp;
    } else {
        int idx = gidx - NQ;
        if (idx >= BB*SS*HKV) return;
        NH = HKV;
        s = idx % SS; h = (idx / SS) % HKV; b = idx / (SS*HKV);
        lin = g_klin; obuf = g_k; spbuf = g_ksp;
        doV = true;
    }

    const float4* src = (const float4*)(lin + ((size_t)(b*SS + s)*NH + h)*HDIM);
    float v[HDIM];
    #pragma unroll
    for (int t = 0; t < HDIM/4; t++) ((float4*)v)[t] = src[t];

    #pragma unroll
    for (int i = 0; i < HDIM/2; i++) {
        float c  = g_cosT[s*(HDIM/2)+i];
        float sn = g_sinT[s*(HDIM/2)+i];
        float a  = v[i], bpart = v[i+HDIM/2];
        v[i]        = a*c - bpart*sn;
        v[i+HDIM/2] = bpart*c + a*sn;
    }

    unsigned* dst = obuf + (((size_t)b*NH + h)*SS + s)*HDIM;
    #pragma unroll
    for (int d = 0; d < HDIM; d += 4) {
        uint4 u;
        u.x = f2tf32(v[d]);   u.y = f2tf32(v[d+1]);
        u.z = f2tf32(v[d+2]); u.w = f2tf32(v[d+3]);
        *(uint4*)&dst[d] = u;
    }

    unsigned* spd = spbuf + (((size_t)b*NH + h)*SS + s)*SDIM;
    #pragma unroll
    for (int j = 0; j < SDIM; j++) {
        float acc = bsS[j];
        #pragma unroll
        for (int d = 0; d < HDIM; d++) acc += WsS[j*HDIM + d] * v[d];
        spd[j] = f2tf32(acc);
    }

    if (doV) {
        const float* vsrc = g_vlin + ((size_t)(b*SS + s)*NH + h)*HDIM;
        unsigned* vbase = g_v + ((size_t)(b*HKV + h)*HDIM)*SS + s;
        #pragma unroll
        for (int d = 0; d < HDIM; d++)
            vbase[(size_t)d*SS] = f2tf32(vsrc[d]);
    }
}

// ================= TF32 attention: ldmatrix B-frags, transposed V, fast exp =================
#define AQT 128
#define AKT 64
#define KSTR 68
#define VTST 68
#define SSTR 20
#define KBUF (AKT*KSTR)
#define VBUF (AKT*VTST)
#define SBUF (AKT*SSTR)
#define ABUF (KBUF+VBUF+SBUF)
#define ASMEM (2*ABUF*4)

#define C_QK 0.1803368801f    // 0.125 * log2(e)
#define C_SP (-0.3606737602f) // -0.25 * log2(e)

__global__ void __launch_bounds__(256, 2) attn_mma_kernel()
{
    extern __shared__ unsigned ash[];

    const int b = blockIdx.z, h = blockIdx.y;
    const int hkv = h >> 2;
    const int q0 = (gridDim.x - 1 - blockIdx.x) * AQT;
    const int tid = threadIdx.x;
    const int w = tid >> 5, lane = tid & 31;
    const int gid = lane >> 2, t4 = lane & 3;

    const int q0w = q0 + w*16;
    const int qr0 = q0w + gid;
    const int qr1 = qr0 + 8;

    const unsigned* qbase = g_q   + ((size_t)b*HH  + h  )*SS*HDIM;
    const unsigned* qspb  = g_qsp + ((size_t)b*HH  + h  )*SS*SDIM;
    const unsigned* kptr  = g_k   + ((size_t)b*HKV + hkv)*SS*HDIM;
    const unsigned* kspp  = g_ksp + ((size_t)b*HKV + hkv)*SS*SDIM;
    const unsigned* vtp   = g_v   + ((size_t)b*HKV + hkv)*HDIM*SS;

    const unsigned shbase = smem_u32(ash);

    // per-lane ldmatrix row/col selectors (shared by K, Ksp, Vt)
    const int lRow = ((lane >> 4) << 3) | (lane & 7);
    const int lCol = ((lane >> 3) & 1) << 2;

    unsigned qa[8][4], qsa[2][4];
    #pragma unroll
    for (int kt = 0; kt < 8; kt++) {
        qa[kt][0] = qbase[(size_t)qr0*HDIM + kt*8 + t4];
        qa[kt][1] = qbase[(size_t)qr1*HDIM + kt*8 + t4];
        qa[kt][2] = qbase[(size_t)qr0*HDIM + kt*8 + t4 + 4];
        qa[kt][3] = qbase[(size_t)qr1*HDIM + kt*8 + t4 + 4];
    }
    #pragma unroll
    for (int kt = 0; kt < 2; kt++) {
        qsa[kt][0] = qspb[(size_t)qr0*SDIM + kt*8 + t4];
        qsa[kt][1] = qspb[(size_t)qr1*SDIM + kt*8 + t4];
        qsa[kt][2] = qspb[(size_t)qr0*SDIM + kt*8 + t4 + 4];
        qsa[kt][3] = qspb[(size_t)qr1*SDIM + kt*8 + t4 + 4];
    }

    float m0 = -1e30f, m1 = -1e30f, l0 = 0.f, l1 = 0.f;
    float O[8][4];
    #pragma unroll
    for (int dn = 0; dn < 8; dn++)
        #pragma unroll
        for (int j = 0; j < 4; j++) O[dn][j] = 0.f;

    const int srcA = (lane & ~3) | (t4 >> 1);
    const int srcB = srcA + 2;
    const bool odd = (t4 & 1);

    auto issue_tile = [&](int kb, int buf) {
        unsigned base = shbase + buf*ABUF*4;
        #pragma unroll
        for (int c = 0; c < 4; c++) {
            int i = tid + c*256;
            int r = i >> 4, q4 = (i & 15) << 2;
            cp16(base + (r*KSTR + q4)*4,          kptr + (size_t)(kb+r)*HDIM + q4);      // K [key][d]
            cp16(base + (KBUF + r*VTST + q4)*4,   vtp  + (size_t)r*SS + kb + q4);        // Vt [d][key]
        }
        {
            int key = tid >> 2, j4 = (tid & 3) << 2;
            cp16(base + (KBUF + VBUF + key*SSTR + j4)*4, kspp + (size_t)(kb+key)*SDIM + j4);
        }
    };

    const int nTiles = (q0 + AQT) / AKT;
    issue_tile(0, 0);
    asm volatile("cp.async.commit_group;");

    for (int t = 0; t < nTiles; t++) {
        const int kb = t*AKT;
        const int buf = t & 1;
        __syncthreads();
        if (t + 1 < nTiles) issue_tile(kb + AKT, buf ^ 1);
        asm volatile("cp.async.commit_group;");
        asm volatile("cp.async.wait_group 1;" ::: "memory");
        __syncthreads();

        if (kb > q0w + 15) continue;

        const unsigned kBase  = shbase + buf*ABUF*4;
        const unsigned vtBase = kBase + KBUF*4;
        const unsigned spBase = kBase + (KBUF+VBUF)*4;

        float S[8][4], SP[8][4];
        #pragma unroll
        for (int nt = 0; nt < 8; nt++)
            #pragma unroll
            for (int j = 0; j < 4; j++) { S[nt][j] = 0.f; SP[nt][j] = 0.f; }

        // ---- S = Q K^T (ldmatrix B-frags) ----
        #pragma unroll
        for (int kt = 0; kt < 8; kt++) {
            #pragma unroll
            for (int g2 = 0; g2 < 4; g2++) {
                uint4 bb = ldsm4(kBase + (((g2*16 + lRow)*KSTR) + kt*8 + lCol)*4);
                mma_tf32(S[2*g2  ][0], S[2*g2  ][1], S[2*g2  ][2], S[2*g2  ][3],
                         qa[kt][0], qa[kt][1], qa[kt][2], qa[kt][3], bb.x, bb.y);
                mma_tf32(S[2*g2+1][0], S[2*g2+1][1], S[2*g2+1][2], S[2*g2+1][3],
                         qa[kt][0], qa[kt][1], qa[kt][2], qa[kt][3], bb.z, bb.w);
            }
        }
        // ---- SP = Qsp Ksp^T ----
        #pragma unroll
        for (int kt = 0; kt < 2; kt++) {
            #pragma unroll
            for (int g2 = 0; g2 < 4; g2++) {
                uint4 bb = ldsm4(spBase + (((g2*16 + lRow)*SSTR) + kt*8 + lCol)*4);
                mma_tf32(SP[2*g2  ][0], SP[2*g2  ][1], SP[2*g2  ][2], SP[2*g2  ][3],
                         qsa[kt][0], qsa[kt][1], qsa[kt][2], qsa[kt][3], bb.x, bb.y);
                mma_tf32(SP[2*g2+1][0], SP[2*g2+1][1], SP[2*g2+1][2], SP[2*g2+1][3],
                         qsa[kt][0], qsa[kt][1], qsa[kt][2], qsa[kt][3], bb.z, bb.w);
            }
        }

        // ---- gate + causal mask (log2-domain logits) ----
        #pragma unroll
        for (int nt = 0; nt < 8; nt++) {
            #pragma unroll
            for (int j = 0; j < 4; j++) {
                int key = kb + nt*8 + 2*t4 + (j & 1);
                int row = (j >= 2) ? qr1 : qr0;
                float tt = ex2f(SP[nt][j] * C_SP);
                float gf = rcpf(1.f + tt);
                float lg = S[nt][j] * C_QK * gf;
                S[nt][j] = (key > row) ? -1e30f : lg;
            }
        }

        float mx0 = -1e30f, mx1 = -1e30f;
        #pragma unroll
        for (int nt = 0; nt < 8; nt++) {
            mx0 = fmaxf(mx0, fmaxf(S[nt][0], S[nt][1]));
            mx1 = fmaxf(mx1, fmaxf(S[nt][2], S[nt][3]));
        }
        #pragma unroll
        for (int off = 1; off < 4; off <<= 1) {
            mx0 = fmaxf(mx0, __shfl_xor_sync(0xffffffffu, mx0, off));
            mx1 = fmaxf(mx1, __shfl_xor_sync(0xffffffffu, mx1, off));
        }
        float mn0 = fmaxf(m0, mx0), mn1 = fmaxf(m1, mx1);
        float sc0 = ex2f(m0 - mn0), sc1 = ex2f(m1 - mn1);
        float sum0 = 0.f, sum1 = 0.f;
        #pragma unroll
        for (int nt = 0; nt < 8; nt++) {
            S[nt][0] = ex2f(S[nt][0] - mn0); sum0 += S[nt][0];
            S[nt][1] = ex2f(S[nt][1] - mn0); sum0 += S[nt][1];
            S[nt][2] = ex2f(S[nt][2] - mn1); sum1 += S[nt][2];
            S[nt][3] = ex2f(S[nt][3] - mn1); sum1 += S[nt][3];
        }
        #pragma unroll
        for (int off = 1; off < 4; off <<= 1) {
            sum0 += __shfl_xor_sync(0xffffffffu, sum0, off);
            sum1 += __shfl_xor_sync(0xffffffffu, sum1, off);
        }
        l0 = l0*sc0 + sum0; l1 = l1*sc1 + sum1;
        m0 = mn0; m1 = mn1;
        #pragma unroll
        for (int dn = 0; dn < 8; dn++) {
            O[dn][0] *= sc0; O[dn][1] *= sc0;
            O[dn][2] *= sc1; O[dn][3] *= sc1;
        }

        // ---- O += P V (P transposed via quad shuffles; Vt ldmatrix) ----
        #pragma unroll
        for (int kt = 0; kt < 8; kt++) {
            float e, o;
            e = __shfl_sync(0xffffffffu, S[kt][0], srcA);
            o = __shfl_sync(0xffffffffu, S[kt][1], srcA);
            unsigned a0 = f2tf32(odd ? o : e);
            e = __shfl_sync(0xffffffffu, S[kt][2], srcA);
            o = __shfl_sync(0xffffffffu, S[kt][3], srcA);
            unsigned a1 = f2tf32(odd ? o : e);
            e = __shfl_sync(0xffffffffu, S[kt][0], srcB);
            o = __shfl_sync(0xffffffffu, S[kt][1], srcB);
            unsigned a2 = f2tf32(odd ? o : e);
            e = __shfl_sync(0xffffffffu, S[kt][2], srcB);
            o = __shfl_sync(0xffffffffu, S[kt][3], srcB);
            unsigned a3 = f2tf32(odd ? o : e);

            #pragma unroll
            for (int d2 = 0; d2 < 4; d2++) {
                uint4 bb = ldsm4(vtBase + (((d2*16 + lRow)*VTST) + kt*8 + lCol)*4);
                mma_tf32(O[2*d2  ][0], O[2*d2  ][1], O[2*d2  ][2], O[2*d2  ][3],
                         a0, a1, a2, a3, bb.x, bb.y);
                mma_tf32(O[2*d2+1][0], O[2*d2+1][1], O[2*d2+1][2], O[2*d2+1][3],
                         a0, a1, a2, a3, bb.z, bb.w);
            }
        }
    }

    float inv0 = 1.f / l0, inv1 = 1.f / l1;
    #pragma unroll
    for (int dn = 0; dn < 8; dn++) {
        int col = h*HDIM + dn*8 + 2*t4;
        float2 r0 = make_float2(__uint_as_float(f2tf32(O[dn][0]*inv0)),
                                __uint_as_float(f2tf32(O[dn][1]*inv0)));
        float2 r1 = make_float2(__uint_as_float(f2tf32(O[dn][2]*inv1)),
                                __uint_as_float(f2tf32(O[dn][3]*inv1)));
        *(float2*)&g_att[((size_t)b*SS + qr0)*DD + col] = r0;
        *(float2*)&g_att[((size_t)b*SS + qr1)*DD + col] = r1;
    }
}

// ---------------- launch ----------------
extern "C" void kernel_launch(void* const* d_in, const int* in_sizes, int n_in,
                              void* d_out, int out_size)
{
    (void)in_sizes; (void)n_in; (void)out_size;
    const float* x  = (const float*)d_in[0];
    const float* Wq = (const float*)d_in[1];
    const float* Wk = (const float*)d_in[2];
    const float* Wv = (const float*)d_in[3];
    const float* Wo = (const float*)d_in[4];
    const float* bo = (const float*)d_in[5];
    const float* Ws = (const float*)d_in[6];
    const float* bs = (const float*)d_in[7];
    float* out = (float*)d_out;

    float *qlin, *klin, *vlin, *att;
    unsigned *xc, *wqc, *wkc, *wvc, *woc;
    cudaGetSymbolAddress((void**)&qlin, g_qlin);
    cudaGetSymbolAddress((void**)&klin, g_klin);
    cudaGetSymbolAddress((void**)&vlin, g_vlin);
    cudaGetSymbolAddress((void**)&att,  g_att);
    cudaGetSymbolAddress((void**)&xc,   g_xc);
    cudaGetSymbolAddress((void**)&wqc,  g_wqc);
    cudaGetSymbolAddress((void**)&wkc,  g_wkc);
    cudaGetSymbolAddress((void**)&wvc,  g_wvc);
    cudaGetSymbolAddress((void**)&woc,  g_woc);

    const int M = BB*SS;   // 4096

    static bool attr_set = false;
    if (!attr_set) {
        cudaFuncSetAttribute(gemm3, cudaFuncAttributeMaxDynamicSharedMemorySize, GSMEM);
        cudaFuncSetAttribute(attn_mma_kernel, cudaFuncAttributeMaxDynamicSharedMemorySize, ASMEM);
        attr_set = true;
    }

    prep_kernel<<<PREP_BLOCKS, 256>>>(x, Wq, Wk, Wv, Wo);

    gemm3<<<dim3(12, M/TBM), 256, GSMEM>>>(xc,
                                    wqc, qlin, 8, DD,
                                    wkc, klin, 2, HKV*HDIM,
                                    wvc, vlin, 2, HKV*HDIM,
                                    nullptr, DD);

    rope_sp_all<<<(BB*SS*(HH+HKV) + 255)/256, 256>>>(Ws, bs);

    attn_mma_kernel<<<dim3(SS/AQT, HH, BB), 256, ASMEM>>>();

    gemm3<<<dim3(8, M/TBM), 256, GSMEM>>>((const unsigned*)att,
                                    woc, out, 8, DD,
                                    nullptr, nullptr, 0, 0,
                                    nullptr, nullptr, 0, 0,
                                    bo, DD);
}

// round 11
// speedup vs baseline: 8.7485x; 1.0619x over previous
#include <cuda_runtime.h>
#include <cuda_bf16.h>
#include <math.h>

#define BB 2
#define SS 2048
#define DD 1024
#define HH 16
#define HKV 4
#define HDIM 64
#define SDIM 16

// ---------------- scratch (device globals; no allocation) ----------------
__device__ float    g_qlin[BB*SS*DD];
__device__ float    g_klin[BB*SS*HKV*HDIM];
__device__ float    g_vlin[BB*SS*HKV*HDIM];
__device__ unsigned g_q   [BB*HH*SS*HDIM];
__device__ unsigned g_qsp [BB*HH*SS*SDIM];
__device__ unsigned g_k   [BB*HKV*SS*HDIM];
__device__ unsigned g_ksp [BB*HKV*SS*SDIM];
__device__ unsigned g_v   [BB*HKV*HDIM*SS];   // TRANSPOSED: [b,hkv,d,s]
__device__ float    g_att [BB*SS*DD];
__device__ float    g_cosT[SS*(HDIM/2)];
__device__ float    g_sinT[SS*(HDIM/2)];
__device__ unsigned g_xc  [BB*SS*DD];
__device__ unsigned g_wqc [DD*DD];
__device__ unsigned g_wkc [HKV*HDIM*DD];
__device__ unsigned g_wvc [HKV*HDIM*DD];
__device__ unsigned g_woc [DD*DD];

// ---------------- common helpers ----------------
__device__ __forceinline__ unsigned f2tf32(float f) {
    unsigned r;
    asm("cvt.rna.tf32.f32 %0, %1;" : "=r"(r) : "f"(f));
    return r;
}
__device__ __forceinline__ float ex2f(float x) {
    float r;
    asm("ex2.approx.f32 %0, %1;" : "=f"(r) : "f"(x));
    return r;
}
__device__ __forceinline__ float rcpf(float x) {
    float r;
    asm("rcp.approx.f32 %0, %1;" : "=f"(r) : "f"(x));
    return r;
}
__device__ __forceinline__ float tanhf_a(float x) {
    float r;
    asm("tanh.approx.f32 %0, %1;" : "=f"(r) : "f"(x));
    return r;
}

__device__ __forceinline__ void mma_tf32(float& d0, float& d1, float& d2, float& d3,
                                         unsigned a0, unsigned a1, unsigned a2, unsigned a3,
                                         unsigned b0, unsigned b1) {
    asm volatile(
        "mma.sync.aligned.m16n8k8.row.col.f32.tf32.tf32.f32 "
        "{%0,%1,%2,%3},{%4,%5,%6,%7},{%8,%9},{%0,%1,%2,%3};"
        : "+f"(d0), "+f"(d1), "+f"(d2), "+f"(d3)
        : "r"(a0), "r"(a1), "r"(a2), "r"(a3), "r"(b0), "r"(b1));
}

__device__ __forceinline__ unsigned smem_u32(const void* p) {
    return (unsigned)__cvta_generic_to_shared(p);
}
__device__ __forceinline__ void cp16(unsigned dst, const void* src) {
    asm volatile("cp.async.cg.shared.global [%0], [%1], 16;" :: "r"(dst), "l"(src));
}
__device__ __forceinline__ uint4 ldsm4(unsigned addr) {
    uint4 r;
    asm volatile("ldmatrix.sync.aligned.m8n8.x4.shared.b16 {%0,%1,%2,%3}, [%4];"
                 : "=r"(r.x), "=r"(r.y), "=r"(r.z), "=r"(r.w) : "r"(addr));
    return r;
}

// ---------------- fused prologue: rope table + all tf32 conversions ----------------
#define PREP_BLOCKS 6912

__device__ __forceinline__ void cvt_seg(const float* __restrict__ in,
                                        unsigned* __restrict__ out, int blk) {
    int i = blk*256 + threadIdx.x;
    float4 f = ((const float4*)in)[i];
    uint4 u;
    u.x = f2tf32(f.x); u.y = f2tf32(f.y); u.z = f2tf32(f.z); u.w = f2tf32(f.w);
    ((uint4*)out)[i] = u;
}

__global__ void prep_kernel(const float* __restrict__ x,
                            const float* __restrict__ Wq,
                            const float* __restrict__ Wk,
                            const float* __restrict__ Wv,
                            const float* __restrict__ Wo)
{
    int bx = blockIdx.x;
    if (bx < 4096)      { cvt_seg(x,  g_xc,  bx); }
    else if (bx < 5120) { cvt_seg(Wq, g_wqc, bx - 4096); }
    else if (bx < 5376) { cvt_seg(Wk, g_wkc, bx - 5120); }
    else if (bx < 5632) { cvt_seg(Wv, g_wvc, bx - 5376); }
    else if (bx < 6656) { cvt_seg(Wo, g_woc, bx - 5632); }
    else {
        int idx = (bx - 6656)*256 + threadIdx.x;
        int s = idx / (HDIM/2), i = idx % (HDIM/2);
        float thf = (float)pow(10000.0, -(double)i / (double)(HDIM/2));
        float ff  = (float)s * thf;
        g_cosT[idx] = (float)cos((double)ff);
        g_sinT[idx] = (float)sin((double)ff);
    }
}

// ================= cp.async + ldmatrix TF32 GEMM =================
#define TBM 128
#define TBN 128
#define TBK 16
#define PADK 20
#define STG 3
#define GSMEM (STG*(TBM+TBN)*PADK*4)

__global__ void __launch_bounds__(256) gemm3(
    const unsigned* __restrict__ A,
    const unsigned* __restrict__ W0, float* __restrict__ C0, int nx0, int N0,
    const unsigned* __restrict__ W1, float* __restrict__ C1, int nx1, int N1,
    const unsigned* __restrict__ W2, float* __restrict__ C2, int nx2, int N2,
    const float* __restrict__ bias, int K)
{
    extern __shared__ unsigned sh[];
    unsigned* Asm = sh;
    unsigned* Bsm = sh + STG*TBM*PADK;

    const int tid = threadIdx.x;
    const int w = tid >> 5, lane = tid & 31;
    const int gid = lane >> 2, t4 = lane & 3;
    const int wm = w & 1, wn = w >> 1;
    const int row0 = blockIdx.y*TBM;

    const unsigned* Wp; float* Cp; int N, cb;
    int bx = blockIdx.x;
    if (bx < nx0)            { Wp = W0; Cp = C0; N = N0; cb = bx; }
    else if (bx < nx0 + nx1) { Wp = W1; Cp = C1; N = N1; cb = bx - nx0; }
    else                     { Wp = W2; Cp = C2; N = N2; cb = bx - nx0 - nx1; }
    const int col0 = cb*TBN;

    const unsigned* Aptr = A  + (size_t)row0*K;
    const unsigned* Wptr = Wp + (size_t)col0*K;

    const int r0c = tid >> 2, r1c = r0c + 64;
    const int cc  = (tid & 3) << 2;

    const unsigned asA = smem_u32(Asm);
    const unsigned asB = smem_u32(Bsm);

    int aoff[4], boff[2];
    #pragma unroll
    for (int mt = 0; mt < 4; mt++)
        aoff[mt] = (wm*64 + mt*16 + (lane & 15))*PADK + ((lane >> 4) << 2);
    #pragma unroll
    for (int np = 0; np < 2; np++)
        boff[np] = (wn*32 + np*16 + (lane & 15))*PADK + ((lane >> 4) << 2);

    #pragma unroll
    for (int s = 0; s < STG-1; s++) {
        int k0 = s*TBK;
        cp16(asA + (s*(TBM*PADK) + r0c*PADK + cc)*4, Aptr + (size_t)r0c*K + k0 + cc);
        cp16(asA + (s*(TBM*PADK) + r1c*PADK + cc)*4, Aptr + (size_t)r1c*K + k0 + cc);
        cp16(asB + (s*(TBN*PADK) + r0c*PADK + cc)*4, Wptr + (size_t)r0c*K + k0 + cc);
        cp16(asB + (s*(TBN*PADK) + r1c*PADK + cc)*4, Wptr + (size_t)r1c*K + k0 + cc);
        asm volatile("cp.async.commit_group;");
    }

    float acc[4][4][4];
    #pragma unroll
    for (int mt = 0; mt < 4; mt++)
        #pragma unroll
        for (int nt = 0; nt < 4; nt++)
            #pragma unroll
            for (int j = 0; j < 4; j++) acc[mt][nt][j] = 0.f;

    const int T = K / TBK;
    int st = 0, si = STG - 1;
    for (int t = 0; t < T; t++) {
        asm volatile("cp.async.wait_group 1;" ::: "memory");
        __syncthreads();

        if (t + STG - 1 < T) {
            int k0 = (t + STG - 1)*TBK;
            cp16(asA + (si*(TBM*PADK) + r0c*PADK + cc)*4, Aptr + (size_t)r0c*K + k0 + cc);
            cp16(asA + (si*(TBM*PADK) + r1c*PADK + cc)*4, Aptr + (size_t)r1c*K + k0 + cc);
            cp16(asB + (si*(TBN*PADK) + r0c*PADK + cc)*4, Wptr + (size_t)r0c*K + k0 + cc);
            cp16(asB + (si*(TBN*PADK) + r1c*PADK + cc)*4, Wptr + (size_t)r1c*K + k0 + cc);
        }
        asm volatile("cp.async.commit_group;");

        const unsigned aStg = asA + (st*(TBM*PADK))*4;
        const unsigned bStg = asB + (st*(TBN*PADK))*4;
        #pragma unroll
        for (int kk = 0; kk < TBK; kk += 8) {
            uint4 av[4], bv[2];
            #pragma unroll
            for (int mt = 0; mt < 4; mt++) av[mt] = ldsm4(aStg + (aoff[mt] + kk)*4);
            #pragma unroll
            for (int np = 0; np < 2; np++) bv[np] = ldsm4(bStg + (boff[np] + kk)*4);
            #pragma unroll
            for (int np = 0; np < 2; np++) {
                #pragma unroll
                for (int mt = 0; mt < 4; mt++) {
                    mma_tf32(acc[mt][2*np  ][0], acc[mt][2*np  ][1], acc[mt][2*np  ][2], acc[mt][2*np  ][3],
                             av[mt].x, av[mt].y, av[mt].z, av[mt].w, bv[np].x, bv[np].z);
                    mma_tf32(acc[mt][2*np+1][0], acc[mt][2*np+1][1], acc[mt][2*np+1][2], acc[mt][2*np+1][3],
                             av[mt].x, av[mt].y, av[mt].z, av[mt].w, bv[np].y, bv[np].w);
                }
            }
        }
        st = (st + 1 == STG) ? 0 : st + 1;
        si = (si + 1 == STG) ? 0 : si + 1;
    }

    #pragma unroll
    for (int mt = 0; mt < 4; mt++) {
        int r = row0 + wm*64 + mt*16 + gid;
        #pragma unroll
        for (int nt = 0; nt < 4; nt++) {
            int c = col0 + wn*32 + nt*8 + 2*t4;
            float bv0 = bias ? bias[c]   : 0.f;
            float bv1 = bias ? bias[c+1] : 0.f;
            *(float2*)&Cp[(size_t)r*N + c]     = make_float2(acc[mt][nt][0]+bv0, acc[mt][nt][1]+bv1);
            *(float2*)&Cp[(size_t)(r+8)*N + c] = make_float2(acc[mt][nt][2]+bv0, acc[mt][nt][3]+bv1);
        }
    }
}

// ---------------- fused RoPE + sparsity projection ----------------
__global__ void rope_sp_all(const float* __restrict__ Ws,
                            const float* __restrict__ bs)
{
    __shared__ float WsS[SDIM*HDIM];
    __shared__ float bsS[SDIM];
    for (int i = threadIdx.x; i < SDIM*HDIM; i += blockDim.x) WsS[i] = Ws[i];
    if (threadIdx.x < SDIM) bsS[threadIdx.x] = bs[threadIdx.x];
    __syncthreads();

    const int NQ = BB*SS*HH;
    int gidx = blockIdx.x*blockDim.x + threadIdx.x;

    const float* lin; unsigned *obuf, *spbuf;
    bool doV = false;
    int b, s, h, NH;
    if (gidx < NQ) {
        NH = HH;
        h = gidx % NH; s = (gidx / NH) % SS; b = gidx / (NH*SS);
        lin = g_qlin; obuf = g_q; spbuf = g_qsp;
    } else {
        int idx = gidx - NQ;
        if (idx >= BB*SS*HKV) return;
        NH = HKV;
        s = idx % SS; h = (idx / SS) % HKV; b = idx / (SS*HKV);
        lin = g_klin; obuf = g_k; spbuf = g_ksp;
        doV = true;
    }

    const float4* src = (const float4*)(lin + ((size_t)(b*SS + s)*NH + h)*HDIM);
    float v[HDIM];
    #pragma unroll
    for (int t = 0; t < HDIM/4; t++) ((float4*)v)[t] = src[t];

    #pragma unroll
    for (int i = 0; i < HDIM/2; i++) {
        float c  = g_cosT[s*(HDIM/2)+i];
        float sn = g_sinT[s*(HDIM/2)+i];
        float a  = v[i], bpart = v[i+HDIM/2];
        v[i]        = a*c - bpart*sn;
        v[i+HDIM/2] = bpart*c + a*sn;
    }

    unsigned* dst = obuf + (((size_t)b*NH + h)*SS + s)*HDIM;
    #pragma unroll
    for (int d = 0; d < HDIM; d += 4) {
        uint4 u;
        u.x = f2tf32(v[d]);   u.y = f2tf32(v[d+1]);
        u.z = f2tf32(v[d+2]); u.w = f2tf32(v[d+3]);
        *(uint4*)&dst[d] = u;
    }

    unsigned* spd = spbuf + (((size_t)b*NH + h)*SS + s)*SDIM;
    #pragma unroll
    for (int j = 0; j < SDIM; j++) {
        float acc = bsS[j];
        #pragma unroll
        for (int d = 0; d < HDIM; d++) acc += WsS[j*HDIM + d] * v[d];
        spd[j] = f2tf32(acc);
    }

    if (doV) {
        const float* vsrc = g_vlin + ((size_t)(b*SS + s)*NH + h)*HDIM;
        unsigned* vbase = g_v + ((size_t)(b*HKV + h)*HDIM)*SS + s;
        #pragma unroll
        for (int d = 0; d < HDIM; d++)
            vbase[(size_t)d*SS] = f2tf32(vsrc[d]);
    }
}

// ================= TF32 attention: tanh gate, low-reg SP, ldmatrix everywhere =================
#define AQT 128
#define AKT 64
#define KSTR 68
#define VTST 68
#define SSTR 20
#define KBUF (AKT*KSTR)
#define VBUF (AKT*VTST)
#define SBUF (AKT*SSTR)
#define ABUF (KBUF+VBUF+SBUF)
#define ASMEM (2*ABUF*4)

#define C_QK 0.1803368801f    // 0.125 * log2(e)

__global__ void __launch_bounds__(256, 2) attn_mma_kernel()
{
    extern __shared__ unsigned ash[];

    const int b = blockIdx.z, h = blockIdx.y;
    const int hkv = h >> 2;
    const int q0 = (gridDim.x - 1 - blockIdx.x) * AQT;
    const int tid = threadIdx.x;
    const int w = tid >> 5, lane = tid & 31;
    const int gid = lane >> 2, t4 = lane & 3;

    const int q0w = q0 + w*16;
    const int qr0 = q0w + gid;
    const int qr1 = qr0 + 8;

    const unsigned* qbase = g_q   + ((size_t)b*HH  + h  )*SS*HDIM;
    const unsigned* qspb  = g_qsp + ((size_t)b*HH  + h  )*SS*SDIM;
    const unsigned* kptr  = g_k   + ((size_t)b*HKV + hkv)*SS*HDIM;
    const unsigned* kspp  = g_ksp + ((size_t)b*HKV + hkv)*SS*SDIM;
    const unsigned* vtp   = g_v   + ((size_t)b*HKV + hkv)*HDIM*SS;

    const unsigned shbase = smem_u32(ash);

    const int lRow = ((lane >> 4) << 3) | (lane & 7);
    const int lCol = ((lane >> 3) & 1) << 2;

    unsigned qa[8][4], qsa[2][4];
    #pragma unroll
    for (int kt = 0; kt < 8; kt++) {
        qa[kt][0] = qbase[(size_t)qr0*HDIM + kt*8 + t4];
        qa[kt][1] = qbase[(size_t)qr1*HDIM + kt*8 + t4];
        qa[kt][2] = qbase[(size_t)qr0*HDIM + kt*8 + t4 + 4];
        qa[kt][3] = qbase[(size_t)qr1*HDIM + kt*8 + t4 + 4];
    }
    #pragma unroll
    for (int kt = 0; kt < 2; kt++) {
        qsa[kt][0] = qspb[(size_t)qr0*SDIM + kt*8 + t4];
        qsa[kt][1] = qspb[(size_t)qr1*SDIM + kt*8 + t4];
        qsa[kt][2] = qspb[(size_t)qr0*SDIM + kt*8 + t4 + 4];
        qsa[kt][3] = qspb[(size_t)qr1*SDIM + kt*8 + t4 + 4];
    }

    float m0 = -1e30f, m1 = -1e30f, l0 = 0.f, l1 = 0.f;
    float O[8][4];
    #pragma unroll
    for (int dn = 0; dn < 8; dn++)
        #pragma unroll
        for (int j = 0; j < 4; j++) O[dn][j] = 0.f;

    const int srcA = (lane & ~3) | (t4 >> 1);
    const int srcB = srcA + 2;
    const bool odd = (t4 & 1);

    auto issue_tile = [&](int kb, int buf) {
        unsigned base = shbase + buf*ABUF*4;
        #pragma unroll
        for (int c = 0; c < 4; c++) {
            int i = tid + c*256;
            int r = i >> 4, q4 = (i & 15) << 2;
            cp16(base + (r*KSTR + q4)*4,          kptr + (size_t)(kb+r)*HDIM + q4);
            cp16(base + (KBUF + r*VTST + q4)*4,   vtp  + (size_t)r*SS + kb + q4);
        }
        {
            int key = tid >> 2, j4 = (tid & 3) << 2;
            cp16(base + (KBUF + VBUF + key*SSTR + j4)*4, kspp + (size_t)(kb+key)*SDIM + j4);
        }
    };

    const int nTiles = (q0 + AQT) / AKT;
    issue_tile(0, 0);
    asm volatile("cp.async.commit_group;");

    for (int t = 0; t < nTiles; t++) {
        const int kb = t*AKT;
        const int buf = t & 1;
        __syncthreads();
        if (t + 1 < nTiles) issue_tile(kb + AKT, buf ^ 1);
        asm volatile("cp.async.commit_group;");
        asm volatile("cp.async.wait_group 1;" ::: "memory");
        __syncthreads();

        if (kb > q0w + 15) continue;

        const unsigned kBase  = shbase + buf*ABUF*4;
        const unsigned vtBase = kBase + KBUF*4;
        const unsigned spBase = kBase + (KBUF+VBUF)*4;

        float S[8][4];
        #pragma unroll
        for (int nt = 0; nt < 8; nt++)
            #pragma unroll
            for (int j = 0; j < 4; j++) S[nt][j] = 0.f;

        // ---- S = Q K^T ----
        #pragma unroll
        for (int kt = 0; kt < 8; kt++) {
            #pragma unroll
            for (int g2 = 0; g2 < 4; g2++) {
                uint4 bb = ldsm4(kBase + (((g2*16 + lRow)*KSTR) + kt*8 + lCol)*4);
                mma_tf32(S[2*g2  ][0], S[2*g2  ][1], S[2*g2  ][2], S[2*g2  ][3],
                         qa[kt][0], qa[kt][1], qa[kt][2], qa[kt][3], bb.x, bb.y);
                mma_tf32(S[2*g2+1][0], S[2*g2+1][1], S[2*g2+1][2], S[2*g2+1][3],
                         qa[kt][0], qa[kt][1], qa[kt][2], qa[kt][3], bb.z, bb.w);
            }
        }

        // ---- gate (tanh) + causal mask, SP computed per 16-key group ----
        #pragma unroll
        for (int g2 = 0; g2 < 4; g2++) {
            float sp0[4] = {0.f,0.f,0.f,0.f}, sp1[4] = {0.f,0.f,0.f,0.f};
            uint4 b0 = ldsm4(spBase + (((g2*16 + lRow)*SSTR) + 0 + lCol)*4);
            uint4 b1 = ldsm4(spBase + (((g2*16 + lRow)*SSTR) + 8 + lCol)*4);
            mma_tf32(sp0[0], sp0[1], sp0[2], sp0[3],
                     qsa[0][0], qsa[0][1], qsa[0][2], qsa[0][3], b0.x, b0.y);
            mma_tf32(sp0[0], sp0[1], sp0[2], sp0[3],
                     qsa[1][0], qsa[1][1], qsa[1][2], qsa[1][3], b1.x, b1.y);
            mma_tf32(sp1[0], sp1[1], sp1[2], sp1[3],
                     qsa[0][0], qsa[0][1], qsa[0][2], qsa[0][3], b0.z, b0.w);
            mma_tf32(sp1[0], sp1[1], sp1[2], sp1[3],
                     qsa[1][0], qsa[1][1], qsa[1][2], qsa[1][3], b1.z, b1.w);

            #pragma unroll
            for (int j = 0; j < 4; j++) {
                // nt = 2*g2 (sp0)
                {
                    int key = kb + (2*g2)*8 + 2*t4 + (j & 1);
                    int row = (j >= 2) ? qr1 : qr0;
                    float gf = fmaf(0.5f, tanhf_a(sp0[j] * 0.125f), 0.5f); // sigmoid(sp/4)
                    float lg = S[2*g2][j] * C_QK * gf;
                    S[2*g2][j] = (key > row) ? -1e30f : lg;
                }
                // nt = 2*g2+1 (sp1)
                {
                    int key = kb + (2*g2+1)*8 + 2*t4 + (j & 1);
                    int row = (j >= 2) ? qr1 : qr0;
                    float gf = fmaf(0.5f, tanhf_a(sp1[j] * 0.125f), 0.5f);
                    float lg = S[2*g2+1][j] * C_QK * gf;
                    S[2*g2+1][j] = (key > row) ? -1e30f : lg;
                }
            }
        }

        // ---- online softmax (log2 domain) ----
        float mx0 = -1e30f, mx1 = -1e30f;
        #pragma unroll
        for (int nt = 0; nt < 8; nt++) {
            mx0 = fmaxf(mx0, fmaxf(S[nt][0], S[nt][1]));
            mx1 = fmaxf(mx1, fmaxf(S[nt][2], S[nt][3]));
        }
        #pragma unroll
        for (int off = 1; off < 4; off <<= 1) {
            mx0 = fmaxf(mx0, __shfl_xor_sync(0xffffffffu, mx0, off));
            mx1 = fmaxf(mx1, __shfl_xor_sync(0xffffffffu, mx1, off));
        }
        float mn0 = fmaxf(m0, mx0), mn1 = fmaxf(m1, mx1);
        float sc0 = ex2f(m0 - mn0), sc1 = ex2f(m1 - mn1);
        float sum0 = 0.f, sum1 = 0.f;
        #pragma unroll
        for (int nt = 0; nt < 8; nt++) {
            S[nt][0] = ex2f(S[nt][0] - mn0); sum0 += S[nt][0];
            S[nt][1] = ex2f(S[nt][1] - mn0); sum0 += S[nt][1];
            S[nt][2] = ex2f(S[nt][2] - mn1); sum1 += S[nt][2];
            S[nt][3] = ex2f(S[nt][3] - mn1); sum1 += S[nt][3];
        }
        #pragma unroll
        for (int off = 1; off < 4; off <<= 1) {
            sum0 += __shfl_xor_sync(0xffffffffu, sum0, off);
            sum1 += __shfl_xor_sync(0xffffffffu, sum1, off);
        }
        l0 = l0*sc0 + sum0; l1 = l1*sc1 + sum1;
        m0 = mn0; m1 = mn1;
        #pragma unroll
        for (int dn = 0; dn < 8; dn++) {
            O[dn][0] *= sc0; O[dn][1] *= sc0;
            O[dn][2] *= sc1; O[dn][3] *= sc1;
        }

        // ---- O += P V ----
        #pragma unroll
        for (int kt = 0; kt < 8; kt++) {
            float e, o;
            e = __shfl_sync(0xffffffffu, S[kt][0], srcA);
            o = __shfl_sync(0xffffffffu, S[kt][1], srcA);
            unsigned a0 = f2tf32(odd ? o : e);
            e = __shfl_sync(0xffffffffu, S[kt][2], srcA);
            o = __shfl_sync(0xffffffffu, S[kt][3], srcA);
            unsigned a1 = f2tf32(odd ? o : e);
            e = __shfl_sync(0xffffffffu, S[kt][0], srcB);
            o = __shfl_sync(0xffffffffu, S[kt][1], srcB);
            unsigned a2 = f2tf32(odd ? o : e);
            e = __shfl_sync(0xffffffffu, S[kt][2], srcB);
            o = __shfl_sync(0xffffffffu, S[kt][3], srcB);
            unsigned a3 = f2tf32(odd ? o : e);

            #pragma unroll
            for (int d2 = 0; d2 < 4; d2++) {
                uint4 bb = ldsm4(vtBase + (((d2*16 + lRow)*VTST) + kt*8 + lCol)*4);
                mma_tf32(O[2*d2  ][0], O[2*d2  ][1], O[2*d2  ][2], O[2*d2  ][3],
                         a0, a1, a2, a3, bb.x, bb.y);
                mma_tf32(O[2*d2+1][0], O[2*d2+1][1], O[2*d2+1][2], O[2*d2+1][3],
                         a0, a1, a2, a3, bb.z, bb.w);
            }
        }
    }

    float inv0 = rcpf(l0), inv1 = rcpf(l1);
    #pragma unroll
    for (int dn = 0; dn < 8; dn++) {
        int col = h*HDIM + dn*8 + 2*t4;
        float2 r0 = make_float2(__uint_as_float(f2tf32(O[dn][0]*inv0)),
                                __uint_as_float(f2tf32(O[dn][1]*inv0)));
        float2 r1 = make_float2(__uint_as_float(f2tf32(O[dn][2]*inv1)),
                                __uint_as_float(f2tf32(O[dn][3]*inv1)));
        *(float2*)&g_att[((size_t)b*SS + qr0)*DD + col] = r0;
        *(float2*)&g_att[((size_t)b*SS + qr1)*DD + col] = r1;
    }
}

// ---------------- launch ----------------
extern "C" void kernel_launch(void* const* d_in, const int* in_sizes, int n_in,
                              void* d_out, int out_size)
{
    (void)in_sizes; (void)n_in; (void)out_size;
    const float* x  = (const float*)d_in[0];
    const float* Wq = (const float*)d_in[1];
    const float* Wk = (const float*)d_in[2];
    const float* Wv = (const float*)d_in[3];
    const float* Wo = (const float*)d_in[4];
    const float* bo = (const float*)d_in[5];
    const float* Ws = (const float*)d_in[6];
    const float* bs = (const float*)d_in[7];
    float* out = (float*)d_out;

    float *qlin, *klin, *vlin, *att;
    unsigned *xc, *wqc, *wkc, *wvc, *woc;
    cudaGetSymbolAddress((void**)&qlin, g_qlin);
    cudaGetSymbolAddress((void**)&klin, g_klin);
    cudaGetSymbolAddress((void**)&vlin, g_vlin);
    cudaGetSymbolAddress((void**)&att,  g_att);
    cudaGetSymbolAddress((void**)&xc,   g_xc);
    cudaGetSymbolAddress((void**)&wqc,  g_wqc);
    cudaGetSymbolAddress((void**)&wkc,  g_wkc);
    cudaGetSymbolAddress((void**)&wvc,  g_wvc);
    cudaGetSymbolAddress((void**)&woc,  g_woc);

    const int M = BB*SS;   // 4096

    static bool attr_set = false;
    if (!attr_set) {
        cudaFuncSetAttribute(gemm3, cudaFuncAttributeMaxDynamicSharedMemorySize, GSMEM);
        cudaFuncSetAttribute(attn_mma_kernel, cudaFuncAttributeMaxDynamicSharedMemorySize, ASMEM);
        attr_set = true;
    }

    prep_kernel<<<PREP_BLOCKS, 256>>>(x, Wq, Wk, Wv, Wo);

    gemm3<<<dim3(12, M/TBM), 256, GSMEM>>>(xc,
                                    wqc, qlin, 8, DD,
                                    wkc, klin, 2, HKV*HDIM,
                                    wvc, vlin, 2, HKV*HDIM,
                                    nullptr, DD);

    rope_sp_all<<<(BB*SS*(HH+HKV) + 255)/256, 256>>>(Ws, bs);

    attn_mma_kernel<<<dim3(SS/AQT, HH, BB), 256, ASMEM>>>();

    gemm3<<<dim3(8, M/TBM), 256, GSMEM>>>((const unsigned*)att,
                                    woc, out, 8, DD,
                                    nullptr, nullptr, 0, 0,
                                    nullptr, nullptr, 0, 0,
                                    bo, DD);
}